// round 3
// baseline (speedup 1.0000x reference)
#include <cuda_runtime.h>
#include <math.h>

#define DIMM 4096
#define HEADD 128
#define NHQ 32
#define NHKV 8
#define HIDDEN 11008
#define BATCH 32
#define MAXSEQ 2048
#define STARTPOS 1024
#define SEQL (STARTPOS + 1)
#define EPS 1e-5f
#define KT 128

typedef unsigned long long u64;

__device__ __forceinline__ u64 fma2(u64 a, u64 b, u64 c) {
    u64 d;
    asm("fma.rn.f32x2 %0, %1, %2, %3;" : "=l"(d) : "l"(a), "l"(b), "l"(c));
    return d;
}
__device__ __forceinline__ u64 bcast2(float x) {
    u64 r;
    asm("mov.b64 %0, {%1, %1};" : "=l"(r) : "f"(x));
    return r;
}
__device__ __forceinline__ float2 unpk(u64 a) {
    float2 f;
    asm("mov.b64 {%0, %1}, %2;" : "=f"(f.x), "=f"(f.y) : "l"(a));
    return f;
}

// ---------- scratch ----------
__device__ __align__(16) float g_hT[DIMM * BATCH];
__device__ __align__(16) float g_q[BATCH * NHQ * HEADD];
__device__ __align__(16) float g_knew[BATCH * NHKV * HEADD];
__device__ __align__(16) float g_vnew[BATCH * NHKV * HEADD];
__device__ __align__(16) float g_attnT[DIMM * BATCH];
__device__ __align__(16) float g_res2[BATCH * DIMM];
__device__ __align__(16) float g_h2T[DIMM * BATCH];
__device__ __align__(16) float g_gateT[HIDDEN * BATCH];
__device__ __align__(16) float g_P1[32 * 6144 * 32];     // 25.2 MB partials
__device__ __align__(16) float g_P2[16 * 11008 * 32];    // 22.5 MB partials
__device__ __align__(16) float g_apart[NHKV * BATCH * 4 * 520]; // attn partials

// ---------- rmsnorm: x b-major -> yT[k][b] ----------
__global__ void __launch_bounds__(256) rmsnorm_kernel(
    const float* __restrict__ x, const float* __restrict__ w, float* __restrict__ yT)
{
    int b = blockIdx.x;
    const float* xr = x + (size_t)b * DIMM;
    __shared__ float red[32];
    float ss = 0.f;
    for (int i = threadIdx.x; i < DIMM; i += 256) { float v = xr[i]; ss += v * v; }
    #pragma unroll
    for (int o = 16; o; o >>= 1) ss += __shfl_xor_sync(0xffffffffu, ss, o);
    if ((threadIdx.x & 31) == 0) red[threadIdx.x >> 5] = ss;
    __syncthreads();
    if (threadIdx.x < 32) {
        float v = (threadIdx.x < 8) ? red[threadIdx.x] : 0.f;
        #pragma unroll
        for (int o = 16; o; o >>= 1) v += __shfl_xor_sync(0xffffffffu, v, o);
        if (threadIdx.x == 0) red[0] = v;
    }
    __syncthreads();
    float inv = 1.0f / (sqrtf(red[0] * (1.0f / DIMM)) + EPS);
    for (int i = threadIdx.x; i < DIMM; i += 256)
        yT[(size_t)i * BATCH + b] = w[i] * xr[i] * inv;
}

// ---------- GEMV core: thread = 4 consecutive cols x 16 batches ----------
// XT layout: [k][32 batches]. W row-major [K][ldW]. Pout points at
// P[(kz*NP + col)*32 + h*16]; col stride in P is 32 floats.
__device__ __forceinline__ void gemv4(
    const float* __restrict__ XT, const float* __restrict__ W, int ldW,
    int col, int k0, int k1, int h, float* __restrict__ Pout)
{
    __shared__ __align__(16) float sh[KT * 32];
    u64 acc[4][8];
    #pragma unroll
    for (int c = 0; c < 4; c++)
        #pragma unroll
        for (int j = 0; j < 8; j++) acc[c][j] = 0ull;

    for (int kt = k0; kt < k1; kt += KT) {
        const float4* src = (const float4*)(XT + (size_t)kt * 32);
        float4* dst = (float4*)sh;
        #pragma unroll
        for (int i = 0; i < 4; i++) dst[threadIdx.x + i * 256] = src[threadIdx.x + i * 256];
        __syncthreads();
        const float* wp = W + (size_t)kt * ldW + col;
        #pragma unroll 4
        for (int k = 0; k < KT; k++) {
            float4 w = *(const float4*)(wp + (size_t)k * ldW);
            u64 w0 = bcast2(w.x), w1 = bcast2(w.y), w2 = bcast2(w.z), w3 = bcast2(w.w);
            const u64* hb = (const u64*)(sh + k * 32 + h * 16);
            #pragma unroll
            for (int j = 0; j < 8; j++) {
                u64 hv = hb[j];
                acc[0][j] = fma2(hv, w0, acc[0][j]);
                acc[1][j] = fma2(hv, w1, acc[1][j]);
                acc[2][j] = fma2(hv, w2, acc[2][j]);
                acc[3][j] = fma2(hv, w3, acc[3][j]);
            }
        }
        __syncthreads();
    }
    #pragma unroll
    for (int c = 0; c < 4; c++) {
        #pragma unroll
        for (int j = 0; j < 4; j++) {
            float2 lo = unpk(acc[c][2 * j]), hi = unpk(acc[c][2 * j + 1]);
            *(float4*)(Pout + (size_t)c * 32 + 4 * j) = make_float4(lo.x, lo.y, hi.x, hi.y);
        }
    }
}

// fused qkv: global cols 0..4095 wq, 4096..5119 wk, 5120..6143 wv
__global__ void __launch_bounds__(256) gemv_qkv_kernel(
    const float* __restrict__ XT, const float* __restrict__ wq,
    const float* __restrict__ wk, const float* __restrict__ wv,
    float* __restrict__ P)
{
    int c = threadIdx.x & 127, h = threadIdx.x >> 7;
    int nbase = blockIdx.x * 512;
    const float* W; int ld, nloc;
    if (nbase < 4096)      { W = wq; ld = 4096; nloc = nbase; }
    else if (nbase < 5120) { W = wk; ld = 1024; nloc = nbase - 4096; }
    else                   { W = wv; ld = 1024; nloc = nbase - 5120; }
    int k0 = blockIdx.y * KT;
    gemv4(XT, W, ld, nloc + 4 * c, k0, k0 + KT, h,
          P + ((size_t)blockIdx.y * 6144 + nbase + 4 * c) * 32 + h * 16);
}

__global__ void __launch_bounds__(256) gemv_single_kernel(
    const float* __restrict__ XT, const float* __restrict__ W,
    float* __restrict__ P, int K, int N, int kchunk)
{
    int c = threadIdx.x & 127, h = threadIdx.x >> 7;
    int nbase = blockIdx.x * 512;
    int k0 = blockIdx.y * kchunk;
    int k1 = min(k0 + kchunk, K);
    gemv4(XT, W, N, nbase + 4 * c, k0, k1, h,
          P + ((size_t)blockIdx.y * N + nbase + 4 * c) * 32 + h * 16);
}

// gate: thread = 2 cols x 2 matrices x 16 batches
__global__ void __launch_bounds__(256) gemv_gate_kernel(
    const float* __restrict__ XT, const float* __restrict__ W1, const float* __restrict__ W3,
    float* __restrict__ P1, float* __restrict__ P2, int kchunk)
{
    __shared__ __align__(16) float sh[KT * 32];
    int c = threadIdx.x & 127, h = threadIdx.x >> 7;
    int n = blockIdx.x * 256 + 2 * c;
    u64 a1[2][8], a3[2][8];
    #pragma unroll
    for (int cc = 0; cc < 2; cc++)
        #pragma unroll
        for (int j = 0; j < 8; j++) { a1[cc][j] = 0ull; a3[cc][j] = 0ull; }
    int k0 = blockIdx.y * kchunk, k1 = k0 + kchunk;
    for (int kt = k0; kt < k1; kt += KT) {
        const float4* src = (const float4*)(XT + (size_t)kt * 32);
        float4* dst = (float4*)sh;
        #pragma unroll
        for (int i = 0; i < 4; i++) dst[threadIdx.x + i * 256] = src[threadIdx.x + i * 256];
        __syncthreads();
        const float* p1 = W1 + (size_t)kt * HIDDEN + n;
        const float* p3 = W3 + (size_t)kt * HIDDEN + n;
        #pragma unroll 4
        for (int k = 0; k < KT; k++) {
            float2 wa = *(const float2*)(p1 + (size_t)k * HIDDEN);
            float2 wb = *(const float2*)(p3 + (size_t)k * HIDDEN);
            u64 wa0 = bcast2(wa.x), wa1 = bcast2(wa.y);
            u64 wb0 = bcast2(wb.x), wb1 = bcast2(wb.y);
            const u64* hb = (const u64*)(sh + k * 32 + h * 16);
            #pragma unroll
            for (int j = 0; j < 8; j++) {
                u64 hv = hb[j];
                a1[0][j] = fma2(hv, wa0, a1[0][j]);
                a1[1][j] = fma2(hv, wa1, a1[1][j]);
                a3[0][j] = fma2(hv, wb0, a3[0][j]);
                a3[1][j] = fma2(hv, wb1, a3[1][j]);
            }
        }
        __syncthreads();
    }
    size_t off = ((size_t)blockIdx.y * HIDDEN + n) * 32 + h * 16;
    #pragma unroll
    for (int cc = 0; cc < 2; cc++) {
        #pragma unroll
        for (int j = 0; j < 4; j++) {
            float2 lo = unpk(a1[cc][2 * j]), hi = unpk(a1[cc][2 * j + 1]);
            *(float4*)(P1 + off + (size_t)cc * 32 + 4 * j) = make_float4(lo.x, lo.y, hi.x, hi.y);
            float2 lo3 = unpk(a3[cc][2 * j]), hi3 = unpk(a3[cc][2 * j + 1]);
            *(float4*)(P2 + off + (size_t)cc * 32 + 4 * j) = make_float4(lo3.x, lo3.y, hi3.x, hi3.y);
        }
    }
}

// ---------- reduces ----------
// qkv reduce + RoPE. Thread = 4 consecutive cols (2 rope pairs) x 16 batches.
__global__ void __launch_bounds__(256) reduce_qkv_rope_kernel(
    const float* __restrict__ P, const float* __restrict__ fcos, const float* __restrict__ fsin,
    float* __restrict__ q, float* __restrict__ knew, float* __restrict__ vnew)
{
    int c = threadIdx.x & 127, h = threadIdx.x >> 7;
    int colg = blockIdx.x * 512 + 4 * c;
    float4 a[4][4];
    #pragma unroll
    for (int cc = 0; cc < 4; cc++)
        #pragma unroll
        for (int j = 0; j < 4; j++) a[cc][j] = make_float4(0.f, 0.f, 0.f, 0.f);
    for (int kz = 0; kz < 32; kz++) {
        const float* p = P + ((size_t)kz * 6144 + colg) * 32 + h * 16;
        #pragma unroll
        for (int cc = 0; cc < 4; cc++)
            #pragma unroll
            for (int j = 0; j < 4; j++) {
                float4 u = *(const float4*)(p + (size_t)cc * 32 + 4 * j);
                a[cc][j].x += u.x; a[cc][j].y += u.y; a[cc][j].z += u.z; a[cc][j].w += u.w;
            }
    }
    int d0 = colg & 127;
    if (colg < 5120) {
        int i0 = d0 >> 1;
        float c0 = fcos[i0], s0 = fsin[i0];
        float c1 = fcos[i0 + 1], s1 = fsin[i0 + 1];
        float* dst; int head, H;
        if (colg < 4096) { head = colg >> 7; dst = q; H = NHQ; }
        else { head = (colg - 4096) >> 7; dst = knew; H = NHKV; }
        #pragma unroll
        for (int j = 0; j < 4; j++) {
            #pragma unroll
            for (int e = 0; e < 4; e++) {
                int b = h * 16 + 4 * j + e;
                float x0 = (e == 0 ? a[0][j].x : e == 1 ? a[0][j].y : e == 2 ? a[0][j].z : a[0][j].w);
                float x1 = (e == 0 ? a[1][j].x : e == 1 ? a[1][j].y : e == 2 ? a[1][j].z : a[1][j].w);
                float x2 = (e == 0 ? a[2][j].x : e == 1 ? a[2][j].y : e == 2 ? a[2][j].z : a[2][j].w);
                float x3 = (e == 0 ? a[3][j].x : e == 1 ? a[3][j].y : e == 2 ? a[3][j].z : a[3][j].w);
                float* o = dst + ((size_t)b * H + head) * HEADD + d0;
                o[0] = x0 * c0 - x1 * s0;
                o[1] = x0 * s0 + x1 * c0;
                o[2] = x2 * c1 - x3 * s1;
                o[3] = x2 * s1 + x3 * c1;
            }
        }
    } else {
        int g = (colg - 5120) >> 7;
        #pragma unroll
        for (int j = 0; j < 4; j++) {
            #pragma unroll
            for (int e = 0; e < 4; e++) {
                int b = h * 16 + 4 * j + e;
                float x0 = (e == 0 ? a[0][j].x : e == 1 ? a[0][j].y : e == 2 ? a[0][j].z : a[0][j].w);
                float x1 = (e == 0 ? a[1][j].x : e == 1 ? a[1][j].y : e == 2 ? a[1][j].z : a[1][j].w);
                float x2 = (e == 0 ? a[2][j].x : e == 1 ? a[2][j].y : e == 2 ? a[2][j].z : a[2][j].w);
                float x3 = (e == 0 ? a[3][j].x : e == 1 ? a[3][j].y : e == 2 ? a[3][j].z : a[3][j].w);
                float* o = vnew + ((size_t)b * NHKV + g) * HEADD + d0;
                o[0] = x0; o[1] = x1; o[2] = x2; o[3] = x3;
            }
        }
    }
}

// sum partials + residual (both b-major [b][N])
__global__ void __launch_bounds__(256) reduce_addres_kernel(
    const float* __restrict__ P, const float* __restrict__ res, float* __restrict__ out,
    int N, int SK)
{
    int c = threadIdx.x & 127, h = threadIdx.x >> 7;
    int n = blockIdx.x * 128 + c;
    float4 a[4];
    #pragma unroll
    for (int j = 0; j < 4; j++) a[j] = make_float4(0.f, 0.f, 0.f, 0.f);
    for (int kz = 0; kz < SK; kz++) {
        const float* p = P + ((size_t)kz * N + n) * 32 + h * 16;
        #pragma unroll
        for (int j = 0; j < 4; j++) {
            float4 u = *(const float4*)(p + 4 * j);
            a[j].x += u.x; a[j].y += u.y; a[j].z += u.z; a[j].w += u.w;
        }
    }
    #pragma unroll
    for (int j = 0; j < 4; j++) {
        int b = h * 16 + 4 * j;
        out[(size_t)(b + 0) * N + n] = a[j].x + res[(size_t)(b + 0) * N + n];
        out[(size_t)(b + 1) * N + n] = a[j].y + res[(size_t)(b + 1) * N + n];
        out[(size_t)(b + 2) * N + n] = a[j].z + res[(size_t)(b + 2) * N + n];
        out[(size_t)(b + 3) * N + n] = a[j].w + res[(size_t)(b + 3) * N + n];
    }
}

// gate reduce -> silu(a1)*a3, written transposed gT[n][b]
__global__ void __launch_bounds__(256) reduce_gate_kernel(
    const float* __restrict__ P1, const float* __restrict__ P2, float* __restrict__ gT)
{
    int c = threadIdx.x & 127, h = threadIdx.x >> 7;
    int n = blockIdx.x * 128 + c;
    float4 a[4], g3[4];
    #pragma unroll
    for (int j = 0; j < 4; j++) { a[j] = make_float4(0.f, 0.f, 0.f, 0.f); g3[j] = a[j]; }
    for (int kz = 0; kz < 16; kz++) {
        const float* p1 = P1 + ((size_t)kz * HIDDEN + n) * 32 + h * 16;
        const float* p3 = P2 + ((size_t)kz * HIDDEN + n) * 32 + h * 16;
        #pragma unroll
        for (int j = 0; j < 4; j++) {
            float4 u = *(const float4*)(p1 + 4 * j);
            a[j].x += u.x; a[j].y += u.y; a[j].z += u.z; a[j].w += u.w;
            float4 w = *(const float4*)(p3 + 4 * j);
            g3[j].x += w.x; g3[j].y += w.y; g3[j].z += w.z; g3[j].w += w.w;
        }
    }
    float* dst = gT + (size_t)n * 32 + h * 16;
    #pragma unroll
    for (int j = 0; j < 4; j++) {
        float4 o;
        o.x = (a[j].x / (1.f + expf(-a[j].x))) * g3[j].x;
        o.y = (a[j].y / (1.f + expf(-a[j].y))) * g3[j].y;
        o.z = (a[j].z / (1.f + expf(-a[j].z))) * g3[j].z;
        o.w = (a[j].w / (1.f + expf(-a[j].w))) * g3[j].w;
        *(float4*)(dst + 4 * j) = o;
    }
}

// ---------- attention, split-L into 4 chunks ----------
// apart layout per (g,b,ch): [m0..m3][s0..s3][pv[4][128]] = 520 floats
__global__ void __launch_bounds__(256) attn_part_kernel(
    const float* __restrict__ cache_k, const float* __restrict__ cache_v,
    const float* __restrict__ q, const float* __restrict__ knew, const float* __restrict__ vnew,
    float* __restrict__ apart)
{
    int g = blockIdx.x, b = blockIdx.y, ch = blockIdx.z;
    int lbase = ch * 256;
    int cs = (ch == 3) ? 257 : 256;
    __shared__ __align__(16) float sc[4][272];
    __shared__ __align__(16) float qs[4][HEADD];
    __shared__ float red[8];
    __shared__ float accb[4][HEADD];
    int tid = threadIdx.x, warp = tid >> 5, lane = tid & 31;
    float* ap = apart + (size_t)((g * 32 + b) * 4 + ch) * 520;

    for (int i = tid; i < 4 * HEADD; i += 256) {
        int r = i >> 7, d = i & 127;
        qs[r][d] = q[((size_t)b * NHQ + (g * 4 + r)) * HEADD + d];
    }
    __syncthreads();
    float ql[4][4];
    #pragma unroll
    for (int r = 0; r < 4; r++) {
        float4 t = *(const float4*)&qs[r][lane * 4];
        ql[r][0] = t.x; ql[r][1] = t.y; ql[r][2] = t.z; ql[r][3] = t.w;
    }
    const float scale = 0.08838834764831845f;

    #pragma unroll 4
    for (int i = 0; i < 32; i++) {
        int l = lbase + warp + i * 8;
        const float* kp = cache_k + (((size_t)b * MAXSEQ + l) * NHKV + g) * HEADD;
        float4 kv = *(const float4*)(kp + lane * 4);
        float p0 = kv.x * ql[0][0] + kv.y * ql[0][1] + kv.z * ql[0][2] + kv.w * ql[0][3];
        float p1 = kv.x * ql[1][0] + kv.y * ql[1][1] + kv.z * ql[1][2] + kv.w * ql[1][3];
        float p2 = kv.x * ql[2][0] + kv.y * ql[2][1] + kv.z * ql[2][2] + kv.w * ql[2][3];
        float p3 = kv.x * ql[3][0] + kv.y * ql[3][1] + kv.z * ql[3][2] + kv.w * ql[3][3];
        #pragma unroll
        for (int o = 16; o; o >>= 1) {
            p0 += __shfl_xor_sync(0xffffffffu, p0, o);
            p1 += __shfl_xor_sync(0xffffffffu, p1, o);
            p2 += __shfl_xor_sync(0xffffffffu, p2, o);
            p3 += __shfl_xor_sync(0xffffffffu, p3, o);
        }
        if (lane == 0) {
            int li = warp + i * 8;
            sc[0][li] = p0 * scale; sc[1][li] = p1 * scale;
            sc[2][li] = p2 * scale; sc[3][li] = p3 * scale;
        }
    }
    if (ch == 3 && warp == 0) {
        const float* kp = knew + ((size_t)b * NHKV + g) * HEADD;
        float4 kv = *(const float4*)(kp + lane * 4);
        float p0 = kv.x * ql[0][0] + kv.y * ql[0][1] + kv.z * ql[0][2] + kv.w * ql[0][3];
        float p1 = kv.x * ql[1][0] + kv.y * ql[1][1] + kv.z * ql[1][2] + kv.w * ql[1][3];
        float p2 = kv.x * ql[2][0] + kv.y * ql[2][1] + kv.z * ql[2][2] + kv.w * ql[2][3];
        float p3 = kv.x * ql[3][0] + kv.y * ql[3][1] + kv.z * ql[3][2] + kv.w * ql[3][3];
        #pragma unroll
        for (int o = 16; o; o >>= 1) {
            p0 += __shfl_xor_sync(0xffffffffu, p0, o);
            p1 += __shfl_xor_sync(0xffffffffu, p1, o);
            p2 += __shfl_xor_sync(0xffffffffu, p2, o);
            p3 += __shfl_xor_sync(0xffffffffu, p3, o);
        }
        if (lane == 0) {
            sc[0][256] = p0 * scale; sc[1][256] = p1 * scale;
            sc[2][256] = p2 * scale; sc[3][256] = p3 * scale;
        }
    }
    __syncthreads();

    // partial softmax per head (64 threads each)
    {
        int r = tid >> 6, t = tid & 63;
        float m = -1e30f;
        for (int li = t; li < cs; li += 64) m = fmaxf(m, sc[r][li]);
        #pragma unroll
        for (int o = 16; o; o >>= 1) m = fmaxf(m, __shfl_xor_sync(0xffffffffu, m, o));
        if (lane == 0) red[warp] = m;
        __syncthreads();
        m = fmaxf(red[2 * r], red[2 * r + 1]);
        float s = 0.f;
        for (int li = t; li < cs; li += 64) {
            float e = expf(sc[r][li] - m);
            sc[r][li] = e; s += e;
        }
        #pragma unroll
        for (int o = 16; o; o >>= 1) s += __shfl_xor_sync(0xffffffffu, s, o);
        __syncthreads();
        if (lane == 0) red[warp] = s;
        __syncthreads();
        s = red[2 * r] + red[2 * r + 1];
        if (t == 0) { ap[r] = m; ap[4 + r] = s; }
    }
    __syncthreads();

    // partial weighted V
    int d = tid & 127, half = tid >> 7;
    float a0 = 0, a1 = 0, a2 = 0, a3 = 0;
    #pragma unroll 4
    for (int li = half; li < cs; li += 2) {
        int l = lbase + li;
        const float* vp = (l < STARTPOS)
            ? cache_v + (((size_t)b * MAXSEQ + l) * NHKV + g) * HEADD
            : vnew + ((size_t)b * NHKV + g) * HEADD;
        float v = vp[d];
        a0 += sc[0][li] * v; a1 += sc[1][li] * v; a2 += sc[2][li] * v; a3 += sc[3][li] * v;
    }
    if (half == 1) { accb[0][d] = a0; accb[1][d] = a1; accb[2][d] = a2; accb[3][d] = a3; }
    __syncthreads();
    if (half == 0) {
        a0 += accb[0][d]; a1 += accb[1][d]; a2 += accb[2][d]; a3 += accb[3][d];
        ap[8 + 0 * 128 + d] = a0;
        ap[8 + 1 * 128 + d] = a1;
        ap[8 + 2 * 128 + d] = a2;
        ap[8 + 3 * 128 + d] = a3;
    }
}

__global__ void __launch_bounds__(128) attn_combine_kernel(
    const float* __restrict__ apart, float* __restrict__ attnT)
{
    int g = blockIdx.x, b = blockIdx.y, d = threadIdx.x;
    const float* base = apart + (size_t)((g * 32 + b) * 4) * 520;
    #pragma unroll
    for (int r = 0; r < 4; r++) {
        float m0 = base[0 * 520 + r], m1 = base[1 * 520 + r];
        float m2 = base[2 * 520 + r], m3 = base[3 * 520 + r];
        float M = fmaxf(fmaxf(m0, m1), fmaxf(m2, m3));
        float w0 = expf(m0 - M), w1 = expf(m1 - M), w2 = expf(m2 - M), w3 = expf(m3 - M);
        float denom = base[0 * 520 + 4 + r] * w0 + base[1 * 520 + 4 + r] * w1
                    + base[2 * 520 + 4 + r] * w2 + base[3 * 520 + 4 + r] * w3;
        float o = base[0 * 520 + 8 + r * 128 + d] * w0 + base[1 * 520 + 8 + r * 128 + d] * w1
                + base[2 * 520 + 8 + r * 128 + d] * w2 + base[3 * 520 + 8 + r * 128 + d] * w3;
        attnT[(size_t)((g * 4 + r) * 128 + d) * 32 + b] = o / denom;
    }
}

// ---------- launch ----------
extern "C" void kernel_launch(void* const* d_in, const int* in_sizes, int n_in,
                              void* d_out, int out_size)
{
    const float* x     = (const float*)d_in[0];
    const float* fcos  = (const float*)d_in[2];
    const float* fsin  = (const float*)d_in[3];
    const float* cachek = (const float*)d_in[4];
    const float* cachev = (const float*)d_in[5];
    const float* wq = (const float*)d_in[6];
    const float* wk = (const float*)d_in[7];
    const float* wv = (const float*)d_in[8];
    const float* wo = (const float*)d_in[9];
    const float* w1 = (const float*)d_in[10];
    const float* w2 = (const float*)d_in[11];
    const float* w3 = (const float*)d_in[12];
    const float* anw = (const float*)d_in[13];
    const float* fnw = (const float*)d_in[14];
    float* out = (float*)d_out;

    float *p_hT, *p_q, *p_knew, *p_vnew, *p_attnT, *p_res2, *p_h2T, *p_gateT, *p_P1, *p_P2, *p_apart;
    cudaGetSymbolAddress((void**)&p_hT, g_hT);
    cudaGetSymbolAddress((void**)&p_q, g_q);
    cudaGetSymbolAddress((void**)&p_knew, g_knew);
    cudaGetSymbolAddress((void**)&p_vnew, g_vnew);
    cudaGetSymbolAddress((void**)&p_attnT, g_attnT);
    cudaGetSymbolAddress((void**)&p_res2, g_res2);
    cudaGetSymbolAddress((void**)&p_h2T, g_h2T);
    cudaGetSymbolAddress((void**)&p_gateT, g_gateT);
    cudaGetSymbolAddress((void**)&p_P1, g_P1);
    cudaGetSymbolAddress((void**)&p_P2, g_P2);
    cudaGetSymbolAddress((void**)&p_apart, g_apart);

    rmsnorm_kernel<<<32, 256>>>(x, anw, p_hT);
    gemv_qkv_kernel<<<dim3(12, 32), 256>>>(p_hT, wq, wk, wv, p_P1);
    reduce_qkv_rope_kernel<<<12, 256>>>(p_P1, fcos, fsin, p_q, p_knew, p_vnew);
    attn_part_kernel<<<dim3(8, 32, 4), 256>>>(cachek, cachev, p_q, p_knew, p_vnew, p_apart);
    attn_combine_kernel<<<dim3(8, 32), 128>>>(p_apart, p_attnT);
    gemv_single_kernel<<<dim3(8, 32), 256>>>(p_attnT, wo, p_P1, 4096, 4096, 128);
    reduce_addres_kernel<<<32, 256>>>(p_P1, x, p_res2, 4096, 32);
    rmsnorm_kernel<<<32, 256>>>(p_res2, fnw, p_h2T);
    gemv_gate_kernel<<<dim3(43, 16), 256>>>(p_h2T, w1, w3, p_P1, p_P2, 256);
    reduce_gate_kernel<<<86, 256>>>(p_P1, p_P2, p_gateT);
    gemv_single_kernel<<<dim3(8, 43), 256>>>(p_gateT, w2, p_P1, 11008, 4096, 256);
    reduce_addres_kernel<<<32, 256>>>(p_P1, p_res2, out, 4096, 43);
}

// round 5
// speedup vs baseline: 2.2270x; 2.2270x over previous
#include <cuda_runtime.h>
#include <cuda_bf16.h>
#include <math.h>
#include <stdint.h>

#define DIMM 4096
#define HEADD 128
#define NHQ 32
#define NHKV 8
#define HIDDEN 11008
#define BATCH 32
#define MAXSEQ 2048
#define STARTPOS 1024
#define SEQL (STARTPOS + 1)
#define EPS 1e-5f

// ---------------- PTX helpers (all baseline PTX, no arch-variant features) ----------------
__device__ __forceinline__ uint32_t s2u(const void* p) {
    uint32_t a;
    asm("{ .reg .u64 t; cvta.to.shared.u64 t, %1; cvt.u32.u64 %0, t; }" : "=r"(a) : "l"(p));
    return a;
}
__device__ __forceinline__ void ldm_x4(uint32_t* r, uint32_t a) {
    asm volatile("ldmatrix.sync.aligned.m8n8.x4.shared.b16 {%0,%1,%2,%3}, [%4];"
                 : "=r"(r[0]), "=r"(r[1]), "=r"(r[2]), "=r"(r[3]) : "r"(a));
}
__device__ __forceinline__ void ldm_x4t(uint32_t* r, uint32_t a) {
    asm volatile("ldmatrix.sync.aligned.m8n8.x4.trans.shared.b16 {%0,%1,%2,%3}, [%4];"
                 : "=r"(r[0]), "=r"(r[1]), "=r"(r[2]), "=r"(r[3]) : "r"(a));
}
__device__ __forceinline__ void mmab(float* c, const uint32_t* a, const uint32_t* b) {
    asm volatile(
        "mma.sync.aligned.m16n8k16.row.col.f32.bf16.bf16.f32 "
        "{%0,%1,%2,%3}, {%4,%5,%6,%7}, {%8,%9}, {%0,%1,%2,%3};"
        : "+f"(c[0]), "+f"(c[1]), "+f"(c[2]), "+f"(c[3])
        : "r"(a[0]), "r"(a[1]), "r"(a[2]), "r"(a[3]), "r"(b[0]), "r"(b[1]));
}

// ---------------- scratch ----------------
__device__ __align__(16) __nv_bfloat16 g_xh[BATCH * DIMM];
__device__ __align__(16) __nv_bfloat16 g_xl[BATCH * DIMM];
__device__ __align__(16) __nv_bfloat16 g_aoh[BATCH * DIMM];
__device__ __align__(16) __nv_bfloat16 g_aol[BATCH * DIMM];
__device__ __align__(16) __nv_bfloat16 g_h2h[BATCH * DIMM];
__device__ __align__(16) __nv_bfloat16 g_h2l[BATCH * DIMM];
__device__ __align__(16) __nv_bfloat16 g_gh[BATCH * HIDDEN];
__device__ __align__(16) __nv_bfloat16 g_gl[BATCH * HIDDEN];
__device__ __align__(16) float g_q[BATCH * NHQ * HEADD];
__device__ __align__(16) float g_knew[BATCH * NHKV * HEADD];
__device__ __align__(16) float g_vnew[BATCH * NHKV * HEADD];
__device__ __align__(16) float g_res2[BATCH * DIMM];
__device__ __align__(16) float g_P1[1179648];   // up to 9 x 4096 x 32 / 6 x 6144 x 32
__device__ __align__(16) float g_P2[704512];    // 2 x 11008 x 32
__device__ __align__(16) float g_apart[NHKV * BATCH * 4 * 520];

// ---------------- HMMA GEMM core ----------------
// Y[b,n] = sum_k X[b,k]*W[k,n].  A = X bf16 hi/lo (b-major), B = W fp32 converted
// in-kernel to bf16 hi/lo.  CTA tile: M=32 x N=128, K chunks of 64, double buffered.
// smem layout (bytes):
//   A: buf*9216 : AH 32x(72 bf16,144B pitch)=4608, AL at +4608   (2 bufs = 18432)
//   B: 18432 + buf*34816 : BH 64x(136 bf16,272B pitch)=17408, BL at +17408
#define GSMEM 88064

__device__ __forceinline__ void gemm_core(
    const __nv_bfloat16* __restrict__ XH, const __nv_bfloat16* __restrict__ XL,
    int Ktot, const float* __restrict__ W, int ldW,
    float* __restrict__ Pout, int s, int nsplit, char* smem, uint32_t sb)
{
    int tid = threadIdx.x, wid = tid >> 5, lane = tid & 31;
    int chunks = Ktot >> 6;
    int c0 = (chunks * s) / nsplit, c1 = (chunks * (s + 1)) / nsplit;
    int nch = c1 - c0;

    float acc[2][2][4];
    #pragma unroll
    for (int t = 0; t < 2; t++)
        #pragma unroll
        for (int u = 0; u < 2; u++)
            #pragma unroll
            for (int i = 0; i < 4; i++) acc[t][u][i] = 0.f;

    int arow = tid >> 3, aseg = tid & 7;            // A: 32 rows x 8 segs of 16B
    int bn = (tid & 15) * 8, bk0 = tid >> 4;        // B: 16 k-rows per pass x 128 n

    uint4 AHr, ALr;
    float4 Br[8];

    auto GLOAD = [&](int c) {
        int kg = (c0 + c) << 6;
        AHr = *(const uint4*)(XH + (size_t)arow * Ktot + kg + aseg * 8);
        ALr = *(const uint4*)(XL + (size_t)arow * Ktot + kg + aseg * 8);
        #pragma unroll
        for (int p = 0; p < 4; p++) {
            const float* wp = W + (size_t)(kg + p * 16 + bk0) * ldW + bn;
            Br[2 * p]     = *(const float4*)wp;
            Br[2 * p + 1] = *(const float4*)(wp + 4);
        }
    };
    auto GSTORE = [&](int buf) {
        *(uint4*)(smem + buf * 9216 + arow * 144 + aseg * 16) = AHr;
        *(uint4*)(smem + buf * 9216 + 4608 + arow * 144 + aseg * 16) = ALr;
        #pragma unroll
        for (int p = 0; p < 4; p++) {
            float v[8] = {Br[2 * p].x, Br[2 * p].y, Br[2 * p].z, Br[2 * p].w,
                          Br[2 * p + 1].x, Br[2 * p + 1].y, Br[2 * p + 1].z, Br[2 * p + 1].w};
            uint32_t H[4], L[4];
            #pragma unroll
            for (int e = 0; e < 4; e++) {
                __nv_bfloat16 h0 = __float2bfloat16(v[2 * e]);
                __nv_bfloat16 h1 = __float2bfloat16(v[2 * e + 1]);
                __nv_bfloat16 l0 = __float2bfloat16(v[2 * e] - __bfloat162float(h0));
                __nv_bfloat16 l1 = __float2bfloat16(v[2 * e + 1] - __bfloat162float(h1));
                H[e] = (uint32_t)__bfloat16_as_ushort(h0) | ((uint32_t)__bfloat16_as_ushort(h1) << 16);
                L[e] = (uint32_t)__bfloat16_as_ushort(l0) | ((uint32_t)__bfloat16_as_ushort(l1) << 16);
            }
            int k = p * 16 + bk0;
            char* bp = smem + 18432 + buf * 34816 + k * 272 + bn * 2;
            *(uint4*)bp = make_uint4(H[0], H[1], H[2], H[3]);
            *(uint4*)(bp + 17408) = make_uint4(L[0], L[1], L[2], L[3]);
        }
    };

    GLOAD(0);
    GSTORE(0);
    __syncthreads();

    for (int c = 0; c < nch; c++) {
        int buf = c & 1;
        if (c + 1 < nch) GLOAD(c + 1);

        uint32_t abase = sb + buf * 9216;
        uint32_t bbase = sb + 18432 + buf * 34816 + wid * 32;  // n0 = wid*16 cols * 2B
        // lane-invariant pieces of ldmatrix addressing
        uint32_t a_row = ((lane >> 3) & 1) * 8 + (lane & 7);
        uint32_t a_kk8 = (lane >> 4) * 8;
        uint32_t b_kk  = ((lane >> 3) & 1) * 8 + (lane & 7);
        uint32_t b_nn  = (lane >> 4) * 8;

        #pragma unroll
        for (int ks = 0; ks < 4; ks++) {
            uint32_t ah[2][4], al[2][4], bh[4], bl[4];
            #pragma unroll
            for (int t = 0; t < 2; t++) {
                uint32_t ad = abase + (t * 16 + a_row) * 144 + (ks * 16 + a_kk8) * 2;
                ldm_x4(ah[t], ad);
                ldm_x4(al[t], ad + 4608);
            }
            {
                uint32_t bd = bbase + (ks * 16 + b_kk) * 272 + b_nn * 2;
                ldm_x4t(bh, bd);
                ldm_x4t(bl, bd + 17408);
            }
            #pragma unroll
            for (int t = 0; t < 2; t++)
                #pragma unroll
                for (int u = 0; u < 2; u++) {
                    mmab(acc[t][u], ah[t], bh + 2 * u);
                    mmab(acc[t][u], al[t], bh + 2 * u);
                    mmab(acc[t][u], ah[t], bl + 2 * u);
                }
        }
        if (c + 1 < nch) GSTORE((c + 1) & 1);
        __syncthreads();
    }

    int g = lane >> 2, tg = lane & 3;
    #pragma unroll
    for (int t = 0; t < 2; t++)
        #pragma unroll
        for (int u = 0; u < 2; u++) {
            int n = wid * 16 + u * 8 + tg * 2;
            int r0 = t * 16 + g;
            Pout[(size_t)n * 32 + r0]           = acc[t][u][0];
            Pout[(size_t)(n + 1) * 32 + r0]     = acc[t][u][1];
            Pout[(size_t)n * 32 + r0 + 8]       = acc[t][u][2];
            Pout[(size_t)(n + 1) * 32 + r0 + 8] = acc[t][u][3];
        }
}

// fused qkv: cols 0..4095 wq, 4096..5119 wk, 5120..6143 wv
__global__ void __launch_bounds__(256, 2) gemm_qkv_kernel(
    const __nv_bfloat16* __restrict__ XH, const __nv_bfloat16* __restrict__ XL,
    const float* __restrict__ wq, const float* __restrict__ wk, const float* __restrict__ wv,
    float* __restrict__ P)
{
    extern __shared__ char smem[];
    uint32_t sb = s2u(smem);
    int nbase = blockIdx.x * 128, s = blockIdx.y;
    const float* W; int ld, nloc;
    if (nbase < 4096)      { W = wq; ld = 4096; nloc = nbase; }
    else if (nbase < 5120) { W = wk; ld = 1024; nloc = nbase - 4096; }
    else                   { W = wv; ld = 1024; nloc = nbase - 5120; }
    gemm_core(XH, XL, 4096, W + nloc, ld,
              P + ((size_t)s * 6144 + nbase) * 32, s, 6, smem, sb);
}

__global__ void __launch_bounds__(256, 2) gemm_single_kernel(
    const __nv_bfloat16* __restrict__ XH, const __nv_bfloat16* __restrict__ XL,
    int Ktot, const float* __restrict__ W, int ldW,
    float* __restrict__ P, int PN, int nsplit)
{
    extern __shared__ char smem[];
    uint32_t sb = s2u(smem);
    int nbase = blockIdx.x * 128, s = blockIdx.y;
    gemm_core(XH, XL, Ktot, W + nbase, ldW,
              P + ((size_t)s * PN + nbase) * 32, s, nsplit, smem, sb);
}

// fused gate: tiles 0..85 -> w1/P1, 86..171 -> w3/P2
__global__ void __launch_bounds__(256, 2) gemm_gate_kernel(
    const __nv_bfloat16* __restrict__ XH, const __nv_bfloat16* __restrict__ XL,
    const float* __restrict__ w1, const float* __restrict__ w3,
    float* __restrict__ P1, float* __restrict__ P2)
{
    extern __shared__ char smem[];
    uint32_t sb = s2u(smem);
    int t = blockIdx.x, s = blockIdx.y;
    if (t < 86) {
        int nbase = t * 128;
        gemm_core(XH, XL, 4096, w1 + nbase, HIDDEN,
                  P1 + ((size_t)s * HIDDEN + nbase) * 32, s, 2, smem, sb);
    } else {
        int nbase = (t - 86) * 128;
        gemm_core(XH, XL, 4096, w3 + nbase, HIDDEN,
                  P2 + ((size_t)s * HIDDEN + nbase) * 32, s, 2, smem, sb);
    }
}

// ---------------- rmsnorm + bf16 hi/lo split (b-major out) ----------------
__global__ void __launch_bounds__(256) rmsnorm_split_kernel(
    const float* __restrict__ x, const float* __restrict__ w,
    __nv_bfloat16* __restrict__ yh, __nv_bfloat16* __restrict__ yl)
{
    int b = blockIdx.x;
    const float* xr = x + (size_t)b * DIMM;
    __shared__ float red[32];
    float ss = 0.f;
    for (int i = threadIdx.x; i < DIMM; i += 256) { float v = xr[i]; ss += v * v; }
    #pragma unroll
    for (int o = 16; o; o >>= 1) ss += __shfl_xor_sync(0xffffffffu, ss, o);
    if ((threadIdx.x & 31) == 0) red[threadIdx.x >> 5] = ss;
    __syncthreads();
    if (threadIdx.x < 32) {
        float v = (threadIdx.x < 8) ? red[threadIdx.x] : 0.f;
        #pragma unroll
        for (int o = 16; o; o >>= 1) v += __shfl_xor_sync(0xffffffffu, v, o);
        if (threadIdx.x == 0) red[0] = v;
    }
    __syncthreads();
    float inv = 1.0f / (sqrtf(red[0] * (1.0f / DIMM)) + EPS);
    for (int i = threadIdx.x; i < DIMM; i += 256) {
        float v = w[i] * xr[i] * inv;
        __nv_bfloat16 h = __float2bfloat16(v);
        yh[(size_t)b * DIMM + i] = h;
        yl[(size_t)b * DIMM + i] = __float2bfloat16(v - __bfloat162float(h));
    }
}

// ---------------- reduces ----------------
__global__ void __launch_bounds__(256) reduce_qkv_rope_kernel(
    const float* __restrict__ P, const float* __restrict__ fcos, const float* __restrict__ fsin,
    float* __restrict__ q, float* __restrict__ knew, float* __restrict__ vnew, int SK)
{
    int c = threadIdx.x & 127, h = threadIdx.x >> 7;
    int colg = blockIdx.x * 512 + 4 * c;
    float4 a[4][4];
    #pragma unroll
    for (int cc = 0; cc < 4; cc++)
        #pragma unroll
        for (int j = 0; j < 4; j++) a[cc][j] = make_float4(0.f, 0.f, 0.f, 0.f);
    for (int kz = 0; kz < SK; kz++) {
        const float* p = P + ((size_t)kz * 6144 + colg) * 32 + h * 16;
        #pragma unroll
        for (int cc = 0; cc < 4; cc++)
            #pragma unroll
            for (int j = 0; j < 4; j++) {
                float4 u = *(const float4*)(p + (size_t)cc * 32 + 4 * j);
                a[cc][j].x += u.x; a[cc][j].y += u.y; a[cc][j].z += u.z; a[cc][j].w += u.w;
            }
    }
    int d0 = colg & 127;
    if (colg < 5120) {
        int i0 = d0 >> 1;
        float c0 = fcos[i0], s0 = fsin[i0];
        float c1 = fcos[i0 + 1], s1 = fsin[i0 + 1];
        float* dst; int head, H;
        if (colg < 4096) { head = colg >> 7; dst = q; H = NHQ; }
        else { head = (colg - 4096) >> 7; dst = knew; H = NHKV; }
        #pragma unroll
        for (int j = 0; j < 4; j++) {
            #pragma unroll
            for (int e = 0; e < 4; e++) {
                int b = h * 16 + 4 * j + e;
                float x0 = (e == 0 ? a[0][j].x : e == 1 ? a[0][j].y : e == 2 ? a[0][j].z : a[0][j].w);
                float x1 = (e == 0 ? a[1][j].x : e == 1 ? a[1][j].y : e == 2 ? a[1][j].z : a[1][j].w);
                float x2 = (e == 0 ? a[2][j].x : e == 1 ? a[2][j].y : e == 2 ? a[2][j].z : a[2][j].w);
                float x3 = (e == 0 ? a[3][j].x : e == 1 ? a[3][j].y : e == 2 ? a[3][j].z : a[3][j].w);
                float* o = dst + ((size_t)b * H + head) * HEADD + d0;
                o[0] = x0 * c0 - x1 * s0;
                o[1] = x0 * s0 + x1 * c0;
                o[2] = x2 * c1 - x3 * s1;
                o[3] = x2 * s1 + x3 * c1;
            }
        }
    } else {
        int g = (colg - 5120) >> 7;
        #pragma unroll
        for (int j = 0; j < 4; j++) {
            #pragma unroll
            for (int e = 0; e < 4; e++) {
                int b = h * 16 + 4 * j + e;
                float x0 = (e == 0 ? a[0][j].x : e == 1 ? a[0][j].y : e == 2 ? a[0][j].z : a[0][j].w);
                float x1 = (e == 0 ? a[1][j].x : e == 1 ? a[1][j].y : e == 2 ? a[1][j].z : a[1][j].w);
                float x2 = (e == 0 ? a[2][j].x : e == 1 ? a[2][j].y : e == 2 ? a[2][j].z : a[2][j].w);
                float x3 = (e == 0 ? a[3][j].x : e == 1 ? a[3][j].y : e == 2 ? a[3][j].z : a[3][j].w);
                float* o = vnew + ((size_t)b * NHKV + g) * HEADD + d0;
                o[0] = x0; o[1] = x1; o[2] = x2; o[3] = x3;
            }
        }
    }
}

__global__ void __launch_bounds__(256) reduce_addres_kernel(
    const float* __restrict__ P, const float* __restrict__ res, float* __restrict__ out,
    int N, int SK)
{
    int c = threadIdx.x & 127, h = threadIdx.x >> 7;
    int n = blockIdx.x * 128 + c;
    float4 a[4];
    #pragma unroll
    for (int j = 0; j < 4; j++) a[j] = make_float4(0.f, 0.f, 0.f, 0.f);
    for (int kz = 0; kz < SK; kz++) {
        const float* p = P + ((size_t)kz * N + n) * 32 + h * 16;
        #pragma unroll
        for (int j = 0; j < 4; j++) {
            float4 u = *(const float4*)(p + 4 * j);
            a[j].x += u.x; a[j].y += u.y; a[j].z += u.z; a[j].w += u.w;
        }
    }
    #pragma unroll
    for (int j = 0; j < 4; j++) {
        int b = h * 16 + 4 * j;
        out[(size_t)(b + 0) * N + n] = a[j].x + res[(size_t)(b + 0) * N + n];
        out[(size_t)(b + 1) * N + n] = a[j].y + res[(size_t)(b + 1) * N + n];
        out[(size_t)(b + 2) * N + n] = a[j].z + res[(size_t)(b + 2) * N + n];
        out[(size_t)(b + 3) * N + n] = a[j].w + res[(size_t)(b + 3) * N + n];
    }
}

__global__ void __launch_bounds__(256) reduce_gate_kernel(
    const float* __restrict__ P1, const float* __restrict__ P2,
    __nv_bfloat16* __restrict__ gh, __nv_bfloat16* __restrict__ gl, int SK)
{
    int c = threadIdx.x & 127, h = threadIdx.x >> 7;
    int n = blockIdx.x * 128 + c;
    float4 a[4], g3[4];
    #pragma unroll
    for (int j = 0; j < 4; j++) { a[j] = make_float4(0.f, 0.f, 0.f, 0.f); g3[j] = a[j]; }
    for (int kz = 0; kz < SK; kz++) {
        const float* p1 = P1 + ((size_t)kz * HIDDEN + n) * 32 + h * 16;
        const float* p3 = P2 + ((size_t)kz * HIDDEN + n) * 32 + h * 16;
        #pragma unroll
        for (int j = 0; j < 4; j++) {
            float4 u = *(const float4*)(p1 + 4 * j);
            a[j].x += u.x; a[j].y += u.y; a[j].z += u.z; a[j].w += u.w;
            float4 w = *(const float4*)(p3 + 4 * j);
            g3[j].x += w.x; g3[j].y += w.y; g3[j].z += w.z; g3[j].w += w.w;
        }
    }
    #pragma unroll
    for (int j = 0; j < 4; j++) {
        float vs[4] = {a[j].x, a[j].y, a[j].z, a[j].w};
        float ws[4] = {g3[j].x, g3[j].y, g3[j].z, g3[j].w};
        #pragma unroll
        for (int e = 0; e < 4; e++) {
            int b = h * 16 + 4 * j + e;
            float v = (vs[e] / (1.f + expf(-vs[e]))) * ws[e];
            __nv_bfloat16 hh = __float2bfloat16(v);
            gh[(size_t)b * HIDDEN + n] = hh;
            gl[(size_t)b * HIDDEN + n] = __float2bfloat16(v - __bfloat162float(hh));
        }
    }
}

// ---------------- attention (split-L SIMT) ----------------
__global__ void __launch_bounds__(256) attn_part_kernel(
    const float* __restrict__ cache_k, const float* __restrict__ cache_v,
    const float* __restrict__ q, const float* __restrict__ knew, const float* __restrict__ vnew,
    float* __restrict__ apart)
{
    int g = blockIdx.x, b = blockIdx.y, ch = blockIdx.z;
    int lbase = ch * 256;
    int cs = (ch == 3) ? 257 : 256;
    __shared__ __align__(16) float sc[4][272];
    __shared__ __align__(16) float qs[4][HEADD];
    __shared__ float red[8];
    __shared__ float accb[4][HEADD];
    int tid = threadIdx.x, warp = tid >> 5, lane = tid & 31;
    float* ap = apart + (size_t)((g * 32 + b) * 4 + ch) * 520;

    for (int i = tid; i < 4 * HEADD; i += 256) {
        int r = i >> 7, d = i & 127;
        qs[r][d] = q[((size_t)b * NHQ + (g * 4 + r)) * HEADD + d];
    }
    __syncthreads();
    float ql[4][4];
    #pragma unroll
    for (int r = 0; r < 4; r++) {
        float4 t = *(const float4*)&qs[r][lane * 4];
        ql[r][0] = t.x; ql[r][1] = t.y; ql[r][2] = t.z; ql[r][3] = t.w;
    }
    const float scale = 0.08838834764831845f;

    #pragma unroll 4
    for (int i = 0; i < 32; i++) {
        int l = lbase + warp + i * 8;
        const float* kp = cache_k + (((size_t)b * MAXSEQ + l) * NHKV + g) * HEADD;
        float4 kv = *(const float4*)(kp + lane * 4);
        float p0 = kv.x * ql[0][0] + kv.y * ql[0][1] + kv.z * ql[0][2] + kv.w * ql[0][3];
        float p1 = kv.x * ql[1][0] + kv.y * ql[1][1] + kv.z * ql[1][2] + kv.w * ql[1][3];
        float p2 = kv.x * ql[2][0] + kv.y * ql[2][1] + kv.z * ql[2][2] + kv.w * ql[2][3];
        float p3 = kv.x * ql[3][0] + kv.y * ql[3][1] + kv.z * ql[3][2] + kv.w * ql[3][3];
        #pragma unroll
        for (int o = 16; o; o >>= 1) {
            p0 += __shfl_xor_sync(0xffffffffu, p0, o);
            p1 += __shfl_xor_sync(0xffffffffu, p1, o);
            p2 += __shfl_xor_sync(0xffffffffu, p2, o);
            p3 += __shfl_xor_sync(0xffffffffu, p3, o);
        }
        if (lane == 0) {
            int li = warp + i * 8;
            sc[0][li] = p0 * scale; sc[1][li] = p1 * scale;
            sc[2][li] = p2 * scale; sc[3][li] = p3 * scale;
        }
    }
    if (ch == 3 && warp == 0) {
        const float* kp = knew + ((size_t)b * NHKV + g) * HEADD;
        float4 kv = *(const float4*)(kp + lane * 4);
        float p0 = kv.x * ql[0][0] + kv.y * ql[0][1] + kv.z * ql[0][2] + kv.w * ql[0][3];
        float p1 = kv.x * ql[1][0] + kv.y * ql[1][1] + kv.z * ql[1][2] + kv.w * ql[1][3];
        float p2 = kv.x * ql[2][0] + kv.y * ql[2][1] + kv.z * ql[2][2] + kv.w * ql[2][3];
        float p3 = kv.x * ql[3][0] + kv.y * ql[3][1] + kv.z * ql[3][2] + kv.w * ql[3][3];
        #pragma unroll
        for (int o = 16; o; o >>= 1) {
            p0 += __shfl_xor_sync(0xffffffffu, p0, o);
            p1 += __shfl_xor_sync(0xffffffffu, p1, o);
            p2 += __shfl_xor_sync(0xffffffffu, p2, o);
            p3 += __shfl_xor_sync(0xffffffffu, p3, o);
        }
        if (lane == 0) {
            sc[0][256] = p0 * scale; sc[1][256] = p1 * scale;
            sc[2][256] = p2 * scale; sc[3][256] = p3 * scale;
        }
    }
    __syncthreads();
    {
        int r = tid >> 6, t = tid & 63;
        float m = -1e30f;
        for (int li = t; li < cs; li += 64) m = fmaxf(m, sc[r][li]);
        #pragma unroll
        for (int o = 16; o; o >>= 1) m = fmaxf(m, __shfl_xor_sync(0xffffffffu, m, o));
        if (lane == 0) red[warp] = m;
        __syncthreads();
        m = fmaxf(red[2 * r], red[2 * r + 1]);
        float s = 0.f;
        for (int li = t; li < cs; li += 64) {
            float e = expf(sc[r][li] - m);
            sc[r][li] = e; s += e;
        }
        #pragma unroll
        for (int o = 16; o; o >>= 1) s += __shfl_xor_sync(0xffffffffu, s, o);
        __syncthreads();
        if (lane == 0) red[warp] = s;
        __syncthreads();
        s = red[2 * r] + red[2 * r + 1];
        if (t == 0) { ap[r] = m; ap[4 + r] = s; }
    }
    __syncthreads();
    int d = tid & 127, half = tid >> 7;
    float a0 = 0, a1 = 0, a2 = 0, a3 = 0;
    #pragma unroll 4
    for (int li = half; li < cs; li += 2) {
        int l = lbase + li;
        const float* vp = (l < STARTPOS)
            ? cache_v + (((size_t)b * MAXSEQ + l) * NHKV + g) * HEADD
            : vnew + ((size_t)b * NHKV + g) * HEADD;
        float v = vp[d];
        a0 += sc[0][li] * v; a1 += sc[1][li] * v; a2 += sc[2][li] * v; a3 += sc[3][li] * v;
    }
    if (half == 1) { accb[0][d] = a0; accb[1][d] = a1; accb[2][d] = a2; accb[3][d] = a3; }
    __syncthreads();
    if (half == 0) {
        a0 += accb[0][d]; a1 += accb[1][d]; a2 += accb[2][d]; a3 += accb[3][d];
        ap[8 + 0 * 128 + d] = a0;
        ap[8 + 1 * 128 + d] = a1;
        ap[8 + 2 * 128 + d] = a2;
        ap[8 + 3 * 128 + d] = a3;
    }
}

__global__ void __launch_bounds__(128) attn_combine_kernel(
    const float* __restrict__ apart,
    __nv_bfloat16* __restrict__ aoh, __nv_bfloat16* __restrict__ aol)
{
    int g = blockIdx.x, b = blockIdx.y, d = threadIdx.x;
    const float* base = apart + (size_t)((g * 32 + b) * 4) * 520;
    #pragma unroll
    for (int r = 0; r < 4; r++) {
        float m0 = base[0 * 520 + r], m1 = base[1 * 520 + r];
        float m2 = base[2 * 520 + r], m3 = base[3 * 520 + r];
        float M = fmaxf(fmaxf(m0, m1), fmaxf(m2, m3));
        float w0 = expf(m0 - M), w1 = expf(m1 - M), w2 = expf(m2 - M), w3 = expf(m3 - M);
        float denom = base[0 * 520 + 4 + r] * w0 + base[1 * 520 + 4 + r] * w1
                    + base[2 * 520 + 4 + r] * w2 + base[3 * 520 + 4 + r] * w3;
        float o = base[0 * 520 + 8 + r * 128 + d] * w0 + base[1 * 520 + 8 + r * 128 + d] * w1
                + base[2 * 520 + 8 + r * 128 + d] * w2 + base[3 * 520 + 8 + r * 128 + d] * w3;
        float v = o / denom;
        __nv_bfloat16 hh = __float2bfloat16(v);
        size_t idx = (size_t)b * DIMM + (g * 4 + r) * 128 + d;
        aoh[idx] = hh;
        aol[idx] = __float2bfloat16(v - __bfloat162float(hh));
    }
}

// ---------------- launch ----------------
extern "C" void kernel_launch(void* const* d_in, const int* in_sizes, int n_in,
                              void* d_out, int out_size)
{
    const float* x     = (const float*)d_in[0];
    const float* fcos  = (const float*)d_in[2];
    const float* fsin  = (const float*)d_in[3];
    const float* cachek = (const float*)d_in[4];
    const float* cachev = (const float*)d_in[5];
    const float* wq = (const float*)d_in[6];
    const float* wk = (const float*)d_in[7];
    const float* wv = (const float*)d_in[8];
    const float* wo = (const float*)d_in[9];
    const float* w1 = (const float*)d_in[10];
    const float* w2 = (const float*)d_in[11];
    const float* w3 = (const float*)d_in[12];
    const float* anw = (const float*)d_in[13];
    const float* fnw = (const float*)d_in[14];
    float* out = (float*)d_out;

    __nv_bfloat16 *p_xh, *p_xl, *p_aoh, *p_aol, *p_h2h, *p_h2l, *p_gh, *p_gl;
    float *p_q, *p_knew, *p_vnew, *p_res2, *p_P1, *p_P2, *p_apart;
    cudaGetSymbolAddress((void**)&p_xh, g_xh);
    cudaGetSymbolAddress((void**)&p_xl, g_xl);
    cudaGetSymbolAddress((void**)&p_aoh, g_aoh);
    cudaGetSymbolAddress((void**)&p_aol, g_aol);
    cudaGetSymbolAddress((void**)&p_h2h, g_h2h);
    cudaGetSymbolAddress((void**)&p_h2l, g_h2l);
    cudaGetSymbolAddress((void**)&p_gh, g_gh);
    cudaGetSymbolAddress((void**)&p_gl, g_gl);
    cudaGetSymbolAddress((void**)&p_q, g_q);
    cudaGetSymbolAddress((void**)&p_knew, g_knew);
    cudaGetSymbolAddress((void**)&p_vnew, g_vnew);
    cudaGetSymbolAddress((void**)&p_res2, g_res2);
    cudaGetSymbolAddress((void**)&p_P1, g_P1);
    cudaGetSymbolAddress((void**)&p_P2, g_P2);
    cudaGetSymbolAddress((void**)&p_apart, g_apart);

    cudaFuncSetAttribute(gemm_qkv_kernel, cudaFuncAttributeMaxDynamicSharedMemorySize, GSMEM);
    cudaFuncSetAttribute(gemm_single_kernel, cudaFuncAttributeMaxDynamicSharedMemorySize, GSMEM);
    cudaFuncSetAttribute(gemm_gate_kernel, cudaFuncAttributeMaxDynamicSharedMemorySize, GSMEM);

    // 1. rmsnorm + split
    rmsnorm_split_kernel<<<32, 256>>>(x, anw, p_xh, p_xl);
    // 2. fused QKV gemm (48 n-tiles x split-K 6 = 288 CTAs)
    gemm_qkv_kernel<<<dim3(48, 6), 256, GSMEM>>>(p_xh, p_xl, wq, wk, wv, p_P1);
    // 3. reduce + RoPE
    reduce_qkv_rope_kernel<<<12, 256>>>(p_P1, fcos, fsin, p_q, p_knew, p_vnew, 6);
    // 4. attention
    attn_part_kernel<<<dim3(8, 32, 4), 256>>>(cachek, cachev, p_q, p_knew, p_vnew, p_apart);
    attn_combine_kernel<<<dim3(8, 32), 128>>>(p_apart, p_aoh, p_aol);
    // 5. wo gemm (32 x 9 = 288 CTAs) + residual
    gemm_single_kernel<<<dim3(32, 9), 256, GSMEM>>>(p_aoh, p_aol, 4096, wo, 4096, p_P1, 4096, 9);
    reduce_addres_kernel<<<32, 256>>>(p_P1, x, p_res2, 4096, 9);
    // 6. ffn norm + split
    rmsnorm_split_kernel<<<32, 256>>>(p_res2, fnw, p_h2h, p_h2l);
    // 7. fused gate gemm (172 x 2 = 344 CTAs)
    gemm_gate_kernel<<<dim3(172, 2), 256, GSMEM>>>(p_h2h, p_h2l, w1, w3, p_P1, p_P2);
    reduce_gate_kernel<<<86, 256>>>(p_P1, p_P2, p_gh, p_gl, 2);
    // 8. down gemm (32 x 9 = 288 CTAs) + residual -> out
    gemm_single_kernel<<<dim3(32, 9), 256, GSMEM>>>(p_gh, p_gl, 11008, w2, 4096, p_P1, 4096, 9);
    reduce_addres_kernel<<<32, 256>>>(p_P1, p_res2, out, 4096, 9);
}

// round 6
// speedup vs baseline: 2.4370x; 1.0943x over previous
#include <cuda_runtime.h>
#include <cuda_bf16.h>
#include <math.h>
#include <stdint.h>

#define DIMM 4096
#define HEADD 128
#define NHQ 32
#define NHKV 8
#define HIDDEN 11008
#define BATCH 32
#define MAXSEQ 2048
#define STARTPOS 1024
#define SEQL (STARTPOS + 1)
#define EPS 1e-5f
#define NCH 8
#define CHL 128

// ---------------- PTX helpers (baseline PTX only) ----------------
__device__ __forceinline__ uint32_t s2u(const void* p) {
    uint32_t a;
    asm("{ .reg .u64 t; cvta.to.shared.u64 t, %1; cvt.u32.u64 %0, t; }" : "=r"(a) : "l"(p));
    return a;
}
__device__ __forceinline__ void ldm_x4(uint32_t* r, uint32_t a) {
    asm volatile("ldmatrix.sync.aligned.m8n8.x4.shared.b16 {%0,%1,%2,%3}, [%4];"
                 : "=r"(r[0]), "=r"(r[1]), "=r"(r[2]), "=r"(r[3]) : "r"(a));
}
__device__ __forceinline__ void ldm_x4t(uint32_t* r, uint32_t a) {
    asm volatile("ldmatrix.sync.aligned.m8n8.x4.trans.shared.b16 {%0,%1,%2,%3}, [%4];"
                 : "=r"(r[0]), "=r"(r[1]), "=r"(r[2]), "=r"(r[3]) : "r"(a));
}
__device__ __forceinline__ void mmab(float* c, const uint32_t* a, const uint32_t* b) {
    asm volatile(
        "mma.sync.aligned.m16n8k16.row.col.f32.bf16.bf16.f32 "
        "{%0,%1,%2,%3}, {%4,%5,%6,%7}, {%8,%9}, {%0,%1,%2,%3};"
        : "+f"(c[0]), "+f"(c[1]), "+f"(c[2]), "+f"(c[3])
        : "r"(a[0]), "r"(a[1]), "r"(a[2]), "r"(a[3]), "r"(b[0]), "r"(b[1]));
}

// ---------------- scratch ----------------
__device__ __align__(16) __nv_bfloat16 g_xh[BATCH * DIMM];
__device__ __align__(16) __nv_bfloat16 g_xl[BATCH * DIMM];
__device__ __align__(16) __nv_bfloat16 g_aoh[BATCH * DIMM];
__device__ __align__(16) __nv_bfloat16 g_aol[BATCH * DIMM];
__device__ __align__(16) __nv_bfloat16 g_h2h[BATCH * DIMM];
__device__ __align__(16) __nv_bfloat16 g_h2l[BATCH * DIMM];
__device__ __align__(16) __nv_bfloat16 g_gh[BATCH * HIDDEN];
__device__ __align__(16) __nv_bfloat16 g_gl[BATCH * HIDDEN];
__device__ __align__(16) float g_q[BATCH * NHQ * HEADD];
__device__ __align__(16) float g_knew[BATCH * NHKV * HEADD];
__device__ __align__(16) float g_vnew[BATCH * NHKV * HEADD];
__device__ __align__(16) float g_res2[BATCH * DIMM];
__device__ __align__(16) float g_P1[1179648];
__device__ __align__(16) float g_P2[704512];
__device__ __align__(16) float g_apart[NHKV * BATCH * NCH * 520];

// ---------------- HMMA GEMM core (unchanged, proven) ----------------
#define GSMEM 88064

__device__ __forceinline__ void gemm_core(
    const __nv_bfloat16* __restrict__ XH, const __nv_bfloat16* __restrict__ XL,
    int Ktot, const float* __restrict__ W, int ldW,
    float* __restrict__ Pout, int s, int nsplit, char* smem, uint32_t sb)
{
    int tid = threadIdx.x, wid = tid >> 5, lane = tid & 31;
    int chunks = Ktot >> 6;
    int c0 = (chunks * s) / nsplit, c1 = (chunks * (s + 1)) / nsplit;
    int nch = c1 - c0;

    float acc[2][2][4];
    #pragma unroll
    for (int t = 0; t < 2; t++)
        #pragma unroll
        for (int u = 0; u < 2; u++)
            #pragma unroll
            for (int i = 0; i < 4; i++) acc[t][u][i] = 0.f;

    int arow = tid >> 3, aseg = tid & 7;
    int bn = (tid & 15) * 8, bk0 = tid >> 4;

    uint4 AHr, ALr;
    float4 Br[8];

    auto GLOAD = [&](int c) {
        int kg = (c0 + c) << 6;
        AHr = *(const uint4*)(XH + (size_t)arow * Ktot + kg + aseg * 8);
        ALr = *(const uint4*)(XL + (size_t)arow * Ktot + kg + aseg * 8);
        #pragma unroll
        for (int p = 0; p < 4; p++) {
            const float* wp = W + (size_t)(kg + p * 16 + bk0) * ldW + bn;
            Br[2 * p]     = *(const float4*)wp;
            Br[2 * p + 1] = *(const float4*)(wp + 4);
        }
    };
    auto GSTORE = [&](int buf) {
        *(uint4*)(smem + buf * 9216 + arow * 144 + aseg * 16) = AHr;
        *(uint4*)(smem + buf * 9216 + 4608 + arow * 144 + aseg * 16) = ALr;
        #pragma unroll
        for (int p = 0; p < 4; p++) {
            float v[8] = {Br[2 * p].x, Br[2 * p].y, Br[2 * p].z, Br[2 * p].w,
                          Br[2 * p + 1].x, Br[2 * p + 1].y, Br[2 * p + 1].z, Br[2 * p + 1].w};
            uint32_t H[4], L[4];
            #pragma unroll
            for (int e = 0; e < 4; e++) {
                __nv_bfloat16 h0 = __float2bfloat16(v[2 * e]);
                __nv_bfloat16 h1 = __float2bfloat16(v[2 * e + 1]);
                __nv_bfloat16 l0 = __float2bfloat16(v[2 * e] - __bfloat162float(h0));
                __nv_bfloat16 l1 = __float2bfloat16(v[2 * e + 1] - __bfloat162float(h1));
                H[e] = (uint32_t)__bfloat16_as_ushort(h0) | ((uint32_t)__bfloat16_as_ushort(h1) << 16);
                L[e] = (uint32_t)__bfloat16_as_ushort(l0) | ((uint32_t)__bfloat16_as_ushort(l1) << 16);
            }
            int k = p * 16 + bk0;
            char* bp = smem + 18432 + buf * 34816 + k * 272 + bn * 2;
            *(uint4*)bp = make_uint4(H[0], H[1], H[2], H[3]);
            *(uint4*)(bp + 17408) = make_uint4(L[0], L[1], L[2], L[3]);
        }
    };

    GLOAD(0);
    GSTORE(0);
    __syncthreads();

    for (int c = 0; c < nch; c++) {
        int buf = c & 1;
        if (c + 1 < nch) GLOAD(c + 1);

        uint32_t abase = sb + buf * 9216;
        uint32_t bbase = sb + 18432 + buf * 34816 + wid * 32;
        uint32_t a_row = ((lane >> 3) & 1) * 8 + (lane & 7);
        uint32_t a_kk8 = (lane >> 4) * 8;
        uint32_t b_kk  = ((lane >> 3) & 1) * 8 + (lane & 7);
        uint32_t b_nn  = (lane >> 4) * 8;

        #pragma unroll
        for (int ks = 0; ks < 4; ks++) {
            uint32_t ah[2][4], al[2][4], bh[4], bl[4];
            #pragma unroll
            for (int t = 0; t < 2; t++) {
                uint32_t ad = abase + (t * 16 + a_row) * 144 + (ks * 16 + a_kk8) * 2;
                ldm_x4(ah[t], ad);
                ldm_x4(al[t], ad + 4608);
            }
            {
                uint32_t bd = bbase + (ks * 16 + b_kk) * 272 + b_nn * 2;
                ldm_x4t(bh, bd);
                ldm_x4t(bl, bd + 17408);
            }
            #pragma unroll
            for (int t = 0; t < 2; t++)
                #pragma unroll
                for (int u = 0; u < 2; u++) {
                    mmab(acc[t][u], ah[t], bh + 2 * u);
                    mmab(acc[t][u], al[t], bh + 2 * u);
                    mmab(acc[t][u], ah[t], bl + 2 * u);
                }
        }
        if (c + 1 < nch) GSTORE((c + 1) & 1);
        __syncthreads();
    }

    int g = lane >> 2, tg = lane & 3;
    #pragma unroll
    for (int t = 0; t < 2; t++)
        #pragma unroll
        for (int u = 0; u < 2; u++) {
            int n = wid * 16 + u * 8 + tg * 2;
            int r0 = t * 16 + g;
            Pout[(size_t)n * 32 + r0]           = acc[t][u][0];
            Pout[(size_t)(n + 1) * 32 + r0]     = acc[t][u][1];
            Pout[(size_t)n * 32 + r0 + 8]       = acc[t][u][2];
            Pout[(size_t)(n + 1) * 32 + r0 + 8] = acc[t][u][3];
        }
}

__global__ void __launch_bounds__(256, 2) gemm_qkv_kernel(
    const __nv_bfloat16* __restrict__ XH, const __nv_bfloat16* __restrict__ XL,
    const float* __restrict__ wq, const float* __restrict__ wk, const float* __restrict__ wv,
    float* __restrict__ P)
{
    extern __shared__ char smem[];
    uint32_t sb = s2u(smem);
    int nbase = blockIdx.x * 128, s = blockIdx.y;
    const float* W; int ld, nloc;
    if (nbase < 4096)      { W = wq; ld = 4096; nloc = nbase; }
    else if (nbase < 5120) { W = wk; ld = 1024; nloc = nbase - 4096; }
    else                   { W = wv; ld = 1024; nloc = nbase - 5120; }
    gemm_core(XH, XL, 4096, W + nloc, ld,
              P + ((size_t)s * 6144 + nbase) * 32, s, 6, smem, sb);
}

__global__ void __launch_bounds__(256, 2) gemm_single_kernel(
    const __nv_bfloat16* __restrict__ XH, const __nv_bfloat16* __restrict__ XL,
    int Ktot, const float* __restrict__ W, int ldW,
    float* __restrict__ P, int PN, int nsplit)
{
    extern __shared__ char smem[];
    uint32_t sb = s2u(smem);
    int nbase = blockIdx.x * 128, s = blockIdx.y;
    gemm_core(XH, XL, Ktot, W + nbase, ldW,
              P + ((size_t)s * PN + nbase) * 32, s, nsplit, smem, sb);
}

__global__ void __launch_bounds__(256, 2) gemm_gate_kernel(
    const __nv_bfloat16* __restrict__ XH, const __nv_bfloat16* __restrict__ XL,
    const float* __restrict__ w1, const float* __restrict__ w3,
    float* __restrict__ P1, float* __restrict__ P2)
{
    extern __shared__ char smem[];
    uint32_t sb = s2u(smem);
    int t = blockIdx.x, s = blockIdx.y;
    if (t < 86) {
        int nbase = t * 128;
        gemm_core(XH, XL, 4096, w1 + nbase, HIDDEN,
                  P1 + ((size_t)s * HIDDEN + nbase) * 32, s, 2, smem, sb);
    } else {
        int nbase = (t - 86) * 128;
        gemm_core(XH, XL, 4096, w3 + nbase, HIDDEN,
                  P2 + ((size_t)s * HIDDEN + nbase) * 32, s, 2, smem, sb);
    }
}

// ---------------- rmsnorm + bf16 hi/lo split ----------------
__global__ void __launch_bounds__(256) rmsnorm_split_kernel(
    const float* __restrict__ x, const float* __restrict__ w,
    __nv_bfloat16* __restrict__ yh, __nv_bfloat16* __restrict__ yl)
{
    int b = blockIdx.x;
    const float* xr = x + (size_t)b * DIMM;
    __shared__ float red[32];
    float ss = 0.f;
    for (int i = threadIdx.x; i < DIMM; i += 256) { float v = xr[i]; ss += v * v; }
    #pragma unroll
    for (int o = 16; o; o >>= 1) ss += __shfl_xor_sync(0xffffffffu, ss, o);
    if ((threadIdx.x & 31) == 0) red[threadIdx.x >> 5] = ss;
    __syncthreads();
    if (threadIdx.x < 32) {
        float v = (threadIdx.x < 8) ? red[threadIdx.x] : 0.f;
        #pragma unroll
        for (int o = 16; o; o >>= 1) v += __shfl_xor_sync(0xffffffffu, v, o);
        if (threadIdx.x == 0) red[0] = v;
    }
    __syncthreads();
    float inv = 1.0f / (sqrtf(red[0] * (1.0f / DIMM)) + EPS);
    for (int i = threadIdx.x; i < DIMM; i += 256) {
        float v = w[i] * xr[i] * inv;
        __nv_bfloat16 h = __float2bfloat16(v);
        yh[(size_t)b * DIMM + i] = h;
        yl[(size_t)b * DIMM + i] = __float2bfloat16(v - __bfloat162float(h));
    }
}

// ---------------- reduces (unchanged) ----------------
__global__ void __launch_bounds__(256) reduce_qkv_rope_kernel(
    const float* __restrict__ P, const float* __restrict__ fcos, const float* __restrict__ fsin,
    float* __restrict__ q, float* __restrict__ knew, float* __restrict__ vnew, int SK)
{
    int c = threadIdx.x & 127, h = threadIdx.x >> 7;
    int colg = blockIdx.x * 512 + 4 * c;
    float4 a[4][4];
    #pragma unroll
    for (int cc = 0; cc < 4; cc++)
        #pragma unroll
        for (int j = 0; j < 4; j++) a[cc][j] = make_float4(0.f, 0.f, 0.f, 0.f);
    for (int kz = 0; kz < SK; kz++) {
        const float* p = P + ((size_t)kz * 6144 + colg) * 32 + h * 16;
        #pragma unroll
        for (int cc = 0; cc < 4; cc++)
            #pragma unroll
            for (int j = 0; j < 4; j++) {
                float4 u = *(const float4*)(p + (size_t)cc * 32 + 4 * j);
                a[cc][j].x += u.x; a[cc][j].y += u.y; a[cc][j].z += u.z; a[cc][j].w += u.w;
            }
    }
    int d0 = colg & 127;
    if (colg < 5120) {
        int i0 = d0 >> 1;
        float c0 = fcos[i0], s0 = fsin[i0];
        float c1 = fcos[i0 + 1], s1 = fsin[i0 + 1];
        float* dst; int head, H;
        if (colg < 4096) { head = colg >> 7; dst = q; H = NHQ; }
        else { head = (colg - 4096) >> 7; dst = knew; H = NHKV; }
        #pragma unroll
        for (int j = 0; j < 4; j++) {
            #pragma unroll
            for (int e = 0; e < 4; e++) {
                int b = h * 16 + 4 * j + e;
                float x0 = (e == 0 ? a[0][j].x : e == 1 ? a[0][j].y : e == 2 ? a[0][j].z : a[0][j].w);
                float x1 = (e == 0 ? a[1][j].x : e == 1 ? a[1][j].y : e == 2 ? a[1][j].z : a[1][j].w);
                float x2 = (e == 0 ? a[2][j].x : e == 1 ? a[2][j].y : e == 2 ? a[2][j].z : a[2][j].w);
                float x3 = (e == 0 ? a[3][j].x : e == 1 ? a[3][j].y : e == 2 ? a[3][j].z : a[3][j].w);
                float* o = dst + ((size_t)b * H + head) * HEADD + d0;
                o[0] = x0 * c0 - x1 * s0;
                o[1] = x0 * s0 + x1 * c0;
                o[2] = x2 * c1 - x3 * s1;
                o[3] = x2 * s1 + x3 * c1;
            }
        }
    } else {
        int g = (colg - 5120) >> 7;
        #pragma unroll
        for (int j = 0; j < 4; j++) {
            #pragma unroll
            for (int e = 0; e < 4; e++) {
                int b = h * 16 + 4 * j + e;
                float x0 = (e == 0 ? a[0][j].x : e == 1 ? a[0][j].y : e == 2 ? a[0][j].z : a[0][j].w);
                float x1 = (e == 0 ? a[1][j].x : e == 1 ? a[1][j].y : e == 2 ? a[1][j].z : a[1][j].w);
                float x2 = (e == 0 ? a[2][j].x : e == 1 ? a[2][j].y : e == 2 ? a[2][j].z : a[2][j].w);
                float x3 = (e == 0 ? a[3][j].x : e == 1 ? a[3][j].y : e == 2 ? a[3][j].z : a[3][j].w);
                float* o = vnew + ((size_t)b * NHKV + g) * HEADD + d0;
                o[0] = x0; o[1] = x1; o[2] = x2; o[3] = x3;
            }
        }
    }
}

__global__ void __launch_bounds__(256) reduce_addres_kernel(
    const float* __restrict__ P, const float* __restrict__ res, float* __restrict__ out,
    int N, int SK)
{
    int c = threadIdx.x & 127, h = threadIdx.x >> 7;
    int n = blockIdx.x * 128 + c;
    float4 a[4];
    #pragma unroll
    for (int j = 0; j < 4; j++) a[j] = make_float4(0.f, 0.f, 0.f, 0.f);
    for (int kz = 0; kz < SK; kz++) {
        const float* p = P + ((size_t)kz * N + n) * 32 + h * 16;
        #pragma unroll
        for (int j = 0; j < 4; j++) {
            float4 u = *(const float4*)(p + 4 * j);
            a[j].x += u.x; a[j].y += u.y; a[j].z += u.z; a[j].w += u.w;
        }
    }
    #pragma unroll
    for (int j = 0; j < 4; j++) {
        int b = h * 16 + 4 * j;
        out[(size_t)(b + 0) * N + n] = a[j].x + res[(size_t)(b + 0) * N + n];
        out[(size_t)(b + 1) * N + n] = a[j].y + res[(size_t)(b + 1) * N + n];
        out[(size_t)(b + 2) * N + n] = a[j].z + res[(size_t)(b + 2) * N + n];
        out[(size_t)(b + 3) * N + n] = a[j].w + res[(size_t)(b + 3) * N + n];
    }
}

__global__ void __launch_bounds__(256) reduce_gate_kernel(
    const float* __restrict__ P1, const float* __restrict__ P2,
    __nv_bfloat16* __restrict__ gh, __nv_bfloat16* __restrict__ gl, int SK)
{
    int c = threadIdx.x & 127, h = threadIdx.x >> 7;
    int n = blockIdx.x * 128 + c;
    float4 a[4], g3[4];
    #pragma unroll
    for (int j = 0; j < 4; j++) { a[j] = make_float4(0.f, 0.f, 0.f, 0.f); g3[j] = a[j]; }
    for (int kz = 0; kz < SK; kz++) {
        const float* p1 = P1 + ((size_t)kz * HIDDEN + n) * 32 + h * 16;
        const float* p3 = P2 + ((size_t)kz * HIDDEN + n) * 32 + h * 16;
        #pragma unroll
        for (int j = 0; j < 4; j++) {
            float4 u = *(const float4*)(p1 + 4 * j);
            a[j].x += u.x; a[j].y += u.y; a[j].z += u.z; a[j].w += u.w;
            float4 w = *(const float4*)(p3 + 4 * j);
            g3[j].x += w.x; g3[j].y += w.y; g3[j].z += w.z; g3[j].w += w.w;
        }
    }
    #pragma unroll
    for (int j = 0; j < 4; j++) {
        float vs[4] = {a[j].x, a[j].y, a[j].z, a[j].w};
        float ws[4] = {g3[j].x, g3[j].y, g3[j].z, g3[j].w};
        #pragma unroll
        for (int e = 0; e < 4; e++) {
            int b = h * 16 + 4 * j + e;
            float v = (vs[e] / (1.f + expf(-vs[e]))) * ws[e];
            __nv_bfloat16 hh = __float2bfloat16(v);
            gh[(size_t)b * HIDDEN + n] = hh;
            gl[(size_t)b * HIDDEN + n] = __float2bfloat16(v - __bfloat162float(hh));
        }
    }
}

// ---------------- attention: split-L x8, merged-shfl scores, float4 V ----------------
// apart per (g,b,ch): [m0..3][s0..3][pv[4][128]] = 520 floats
__global__ void __launch_bounds__(256) attn_part_kernel(
    const float* __restrict__ cache_k, const float* __restrict__ cache_v,
    const float* __restrict__ q, const float* __restrict__ knew, const float* __restrict__ vnew,
    float* __restrict__ apart)
{
    int g = blockIdx.x, b = blockIdx.y, ch = blockIdx.z;
    int lbase = ch * CHL;
    int cs = (ch == NCH - 1) ? CHL + 1 : CHL;
    __shared__ __align__(16) float sc[4][136];
    __shared__ __align__(16) float qs[4][HEADD];
    __shared__ float red[8];
    __shared__ __align__(16) float vred[8][4][32][4];  // 16KB
    int tid = threadIdx.x, warp = tid >> 5, lane = tid & 31;
    float* ap = apart + (size_t)((g * 32 + b) * NCH + ch) * 520;

    for (int i = tid; i < 4 * HEADD; i += 256) {
        int r = i >> 7, d = i & 127;
        qs[r][d] = q[((size_t)b * NHQ + (g * 4 + r)) * HEADD + d];
    }
    __syncthreads();
    float ql[4][4];
    #pragma unroll
    for (int r = 0; r < 4; r++) {
        float4 t = *(const float4*)&qs[r][lane * 4];
        ql[r][0] = t.x; ql[r][1] = t.y; ql[r][2] = t.z; ql[r][3] = t.w;
    }
    const float scale = 0.08838834764831845f;
    bool odd1 = (lane & 1), odd2 = (lane & 2);

    #pragma unroll 2
    for (int i = 0; i < CHL / 8; i++) {
        int li = warp + i * 8;
        int l = lbase + li;
        const float* kp = cache_k + (((size_t)b * MAXSEQ + l) * NHKV + g) * HEADD;
        float4 kv = *(const float4*)(kp + lane * 4);
        float p0 = kv.x * ql[0][0] + kv.y * ql[0][1] + kv.z * ql[0][2] + kv.w * ql[0][3];
        float p1 = kv.x * ql[1][0] + kv.y * ql[1][1] + kv.z * ql[1][2] + kv.w * ql[1][3];
        float p2 = kv.x * ql[2][0] + kv.y * ql[2][1] + kv.z * ql[2][2] + kv.w * ql[2][3];
        float p3 = kv.x * ql[3][0] + kv.y * ql[3][1] + kv.z * ql[3][2] + kv.w * ql[3][3];
        // merged 4-head reduce: 6 shfls
        float a01 = (odd1 ? p1 : p0) + __shfl_xor_sync(0xffffffffu, odd1 ? p0 : p1, 1);
        float a23 = (odd1 ? p3 : p2) + __shfl_xor_sync(0xffffffffu, odd1 ? p2 : p3, 1);
        float v4 = (odd2 ? a23 : a01) + __shfl_xor_sync(0xffffffffu, odd2 ? a01 : a23, 2);
        v4 += __shfl_xor_sync(0xffffffffu, v4, 4);
        v4 += __shfl_xor_sync(0xffffffffu, v4, 8);
        v4 += __shfl_xor_sync(0xffffffffu, v4, 16);
        if (lane < 4) sc[lane][li] = v4 * scale;
    }
    if (ch == NCH - 1 && warp == 0) {
        const float* kp = knew + ((size_t)b * NHKV + g) * HEADD;
        float4 kv = *(const float4*)(kp + lane * 4);
        float p0 = kv.x * ql[0][0] + kv.y * ql[0][1] + kv.z * ql[0][2] + kv.w * ql[0][3];
        float p1 = kv.x * ql[1][0] + kv.y * ql[1][1] + kv.z * ql[1][2] + kv.w * ql[1][3];
        float p2 = kv.x * ql[2][0] + kv.y * ql[2][1] + kv.z * ql[2][2] + kv.w * ql[2][3];
        float p3 = kv.x * ql[3][0] + kv.y * ql[3][1] + kv.z * ql[3][2] + kv.w * ql[3][3];
        float a01 = (odd1 ? p1 : p0) + __shfl_xor_sync(0xffffffffu, odd1 ? p0 : p1, 1);
        float a23 = (odd1 ? p3 : p2) + __shfl_xor_sync(0xffffffffu, odd1 ? p2 : p3, 1);
        float v4 = (odd2 ? a23 : a01) + __shfl_xor_sync(0xffffffffu, odd2 ? a01 : a23, 2);
        v4 += __shfl_xor_sync(0xffffffffu, v4, 4);
        v4 += __shfl_xor_sync(0xffffffffu, v4, 8);
        v4 += __shfl_xor_sync(0xffffffffu, v4, 16);
        if (lane < 4) sc[lane][CHL] = v4 * scale;
    }
    __syncthreads();

    // partial softmax per head (64 threads each)
    {
        int r = tid >> 6, t = tid & 63;
        float m = -1e30f;
        for (int li = t; li < cs; li += 64) m = fmaxf(m, sc[r][li]);
        #pragma unroll
        for (int o = 16; o; o >>= 1) m = fmaxf(m, __shfl_xor_sync(0xffffffffu, m, o));
        if (lane == 0) red[warp] = m;
        __syncthreads();
        m = fmaxf(red[2 * r], red[2 * r + 1]);
        float s = 0.f;
        for (int li = t; li < cs; li += 64) {
            float e = expf(sc[r][li] - m);
            sc[r][li] = e; s += e;
        }
        #pragma unroll
        for (int o = 16; o; o >>= 1) s += __shfl_xor_sync(0xffffffffu, s, o);
        __syncthreads();
        if (lane == 0) red[warp] = s;
        __syncthreads();
        s = red[2 * r] + red[2 * r + 1];
        if (t == 0) { ap[r] = m; ap[4 + r] = s; }
    }
    __syncthreads();

    // weighted V: thread = (quad of 4 dims, slice of 8 l's), float4 loads
    {
        int quad = tid & 31, sl = tid >> 5;
        float4 a0 = make_float4(0, 0, 0, 0), a1 = a0, a2 = a0, a3 = a0;
        #pragma unroll 4
        for (int li = sl; li < cs; li += 8) {
            int l = lbase + li;
            const float* vp = (l < STARTPOS)
                ? cache_v + (((size_t)b * MAXSEQ + l) * NHKV + g) * HEADD
                : vnew + ((size_t)b * NHKV + g) * HEADD;
            float4 v = *(const float4*)(vp + quad * 4);
            float s0 = sc[0][li], s1 = sc[1][li], s2 = sc[2][li], s3 = sc[3][li];
            a0.x += s0 * v.x; a0.y += s0 * v.y; a0.z += s0 * v.z; a0.w += s0 * v.w;
            a1.x += s1 * v.x; a1.y += s1 * v.y; a1.z += s1 * v.z; a1.w += s1 * v.w;
            a2.x += s2 * v.x; a2.y += s2 * v.y; a2.z += s2 * v.z; a2.w += s2 * v.w;
            a3.x += s3 * v.x; a3.y += s3 * v.y; a3.z += s3 * v.z; a3.w += s3 * v.w;
        }
        *(float4*)&vred[sl][0][quad][0] = a0;
        *(float4*)&vred[sl][1][quad][0] = a1;
        *(float4*)&vred[sl][2][quad][0] = a2;
        *(float4*)&vred[sl][3][quad][0] = a3;
    }
    __syncthreads();
    if (tid < 128) {
        int head = tid >> 5, quad = tid & 31;
        float4 s = make_float4(0, 0, 0, 0);
        #pragma unroll
        for (int sl = 0; sl < 8; sl++) {
            float4 u = *(const float4*)&vred[sl][head][quad][0];
            s.x += u.x; s.y += u.y; s.z += u.z; s.w += u.w;
        }
        *(float4*)(ap + 8 + head * 128 + quad * 4) = s;
    }
}

// combine NCH partials -> bf16 hi/lo b-major
__global__ void __launch_bounds__(128) attn_combine_kernel(
    const float* __restrict__ apart,
    __nv_bfloat16* __restrict__ aoh, __nv_bfloat16* __restrict__ aol)
{
    int g = blockIdx.x, b = blockIdx.y, d = threadIdx.x;
    const float* base = apart + (size_t)((g * 32 + b) * NCH) * 520;
    #pragma unroll
    for (int r = 0; r < 4; r++) {
        float M = -1e30f;
        #pragma unroll
        for (int c = 0; c < NCH; c++) M = fmaxf(M, base[c * 520 + r]);
        float denom = 0.f, o = 0.f;
        #pragma unroll
        for (int c = 0; c < NCH; c++) {
            float w = expf(base[c * 520 + r] - M);
            denom += base[c * 520 + 4 + r] * w;
            o += base[c * 520 + 8 + r * 128 + d] * w;
        }
        float v = o / denom;
        __nv_bfloat16 hh = __float2bfloat16(v);
        size_t idx = (size_t)b * DIMM + (g * 4 + r) * 128 + d;
        aoh[idx] = hh;
        aol[idx] = __float2bfloat16(v - __bfloat162float(hh));
    }
}

// ---------------- launch ----------------
extern "C" void kernel_launch(void* const* d_in, const int* in_sizes, int n_in,
                              void* d_out, int out_size)
{
    const float* x     = (const float*)d_in[0];
    const float* fcos  = (const float*)d_in[2];
    const float* fsin  = (const float*)d_in[3];
    const float* cachek = (const float*)d_in[4];
    const float* cachev = (const float*)d_in[5];
    const float* wq = (const float*)d_in[6];
    const float* wk = (const float*)d_in[7];
    const float* wv = (const float*)d_in[8];
    const float* wo = (const float*)d_in[9];
    const float* w1 = (const float*)d_in[10];
    const float* w2 = (const float*)d_in[11];
    const float* w3 = (const float*)d_in[12];
    const float* anw = (const float*)d_in[13];
    const float* fnw = (const float*)d_in[14];
    float* out = (float*)d_out;

    __nv_bfloat16 *p_xh, *p_xl, *p_aoh, *p_aol, *p_h2h, *p_h2l, *p_gh, *p_gl;
    float *p_q, *p_knew, *p_vnew, *p_res2, *p_P1, *p_P2, *p_apart;
    cudaGetSymbolAddress((void**)&p_xh, g_xh);
    cudaGetSymbolAddress((void**)&p_xl, g_xl);
    cudaGetSymbolAddress((void**)&p_aoh, g_aoh);
    cudaGetSymbolAddress((void**)&p_aol, g_aol);
    cudaGetSymbolAddress((void**)&p_h2h, g_h2h);
    cudaGetSymbolAddress((void**)&p_h2l, g_h2l);
    cudaGetSymbolAddress((void**)&p_gh, g_gh);
    cudaGetSymbolAddress((void**)&p_gl, g_gl);
    cudaGetSymbolAddress((void**)&p_q, g_q);
    cudaGetSymbolAddress((void**)&p_knew, g_knew);
    cudaGetSymbolAddress((void**)&p_vnew, g_vnew);
    cudaGetSymbolAddress((void**)&p_res2, g_res2);
    cudaGetSymbolAddress((void**)&p_P1, g_P1);
    cudaGetSymbolAddress((void**)&p_P2, g_P2);
    cudaGetSymbolAddress((void**)&p_apart, g_apart);

    cudaFuncSetAttribute(gemm_qkv_kernel, cudaFuncAttributeMaxDynamicSharedMemorySize, GSMEM);
    cudaFuncSetAttribute(gemm_single_kernel, cudaFuncAttributeMaxDynamicSharedMemorySize, GSMEM);
    cudaFuncSetAttribute(gemm_gate_kernel, cudaFuncAttributeMaxDynamicSharedMemorySize, GSMEM);

    rmsnorm_split_kernel<<<32, 256>>>(x, anw, p_xh, p_xl);
    gemm_qkv_kernel<<<dim3(48, 6), 256, GSMEM>>>(p_xh, p_xl, wq, wk, wv, p_P1);
    reduce_qkv_rope_kernel<<<12, 256>>>(p_P1, fcos, fsin, p_q, p_knew, p_vnew, 6);
    attn_part_kernel<<<dim3(8, 32, NCH), 256>>>(cachek, cachev, p_q, p_knew, p_vnew, p_apart);
    attn_combine_kernel<<<dim3(8, 32), 128>>>(p_apart, p_aoh, p_aol);
    gemm_single_kernel<<<dim3(32, 9), 256, GSMEM>>>(p_aoh, p_aol, 4096, wo, 4096, p_P1, 4096, 9);
    reduce_addres_kernel<<<32, 256>>>(p_P1, x, p_res2, 4096, 9);
    rmsnorm_split_kernel<<<32, 256>>>(p_res2, fnw, p_h2h, p_h2l);
    gemm_gate_kernel<<<dim3(172, 2), 256, GSMEM>>>(p_h2h, p_h2l, w1, w3, p_P1, p_P2);
    reduce_gate_kernel<<<86, 256>>>(p_P1, p_P2, p_gh, p_gl, 2);
    gemm_single_kernel<<<dim3(32, 9), 256, GSMEM>>>(p_gh, p_gl, 11008, w2, 4096, p_P1, 4096, 9);
    reduce_addres_kernel<<<32, 256>>>(p_P1, p_res2, out, 4096, 9);
}

// round 7
// speedup vs baseline: 2.7441x; 1.1260x over previous
#include <cuda_runtime.h>
#include <cuda_bf16.h>
#include <math.h>
#include <stdint.h>

#define DIMM 4096
#define HEADD 128
#define NHQ 32
#define NHKV 8
#define HIDDEN 11008
#define BATCH 32
#define MAXSEQ 2048
#define STARTPOS 1024
#define SEQL (STARTPOS + 1)
#define EPS 1e-5f
#define NCH 8
#define CHL 128

// ---------------- PTX helpers (baseline PTX only) ----------------
__device__ __forceinline__ uint32_t s2u(const void* p) {
    uint32_t a;
    asm("{ .reg .u64 t; cvta.to.shared.u64 t, %1; cvt.u32.u64 %0, t; }" : "=r"(a) : "l"(p));
    return a;
}
__device__ __forceinline__ void ldm_x4(uint32_t* r, uint32_t a) {
    asm volatile("ldmatrix.sync.aligned.m8n8.x4.shared.b16 {%0,%1,%2,%3}, [%4];"
                 : "=r"(r[0]), "=r"(r[1]), "=r"(r[2]), "=r"(r[3]) : "r"(a));
}
__device__ __forceinline__ void ldm_x4t(uint32_t* r, uint32_t a) {
    asm volatile("ldmatrix.sync.aligned.m8n8.x4.trans.shared.b16 {%0,%1,%2,%3}, [%4];"
                 : "=r"(r[0]), "=r"(r[1]), "=r"(r[2]), "=r"(r[3]) : "r"(a));
}
__device__ __forceinline__ void mmab(float* c, const uint32_t* a, const uint32_t* b) {
    asm volatile(
        "mma.sync.aligned.m16n8k16.row.col.f32.bf16.bf16.f32 "
        "{%0,%1,%2,%3}, {%4,%5,%6,%7}, {%8,%9}, {%0,%1,%2,%3};"
        : "+f"(c[0]), "+f"(c[1]), "+f"(c[2]), "+f"(c[3])
        : "r"(a[0]), "r"(a[1]), "r"(a[2]), "r"(a[3]), "r"(b[0]), "r"(b[1]));
}
// pack two fp32 -> bf16x2 (lo half = v0, hi half = v1), and return hi/lo split
__device__ __forceinline__ void bf16_hilo2(float v0, float v1, uint32_t& H, uint32_t& L) {
    uint32_t hp;
    asm("cvt.rn.bf16x2.f32 %0, %1, %2;" : "=r"(hp) : "f"(v1), "f"(v0));
    float f0 = __uint_as_float(hp << 16);
    float f1 = __uint_as_float(hp & 0xFFFF0000u);
    float l0 = v0 - f0, l1 = v1 - f1;
    uint32_t lp;
    asm("cvt.rn.bf16x2.f32 %0, %1, %2;" : "=r"(lp) : "f"(l1), "f"(l0));
    H = hp; L = lp;
}

// ---------------- scratch ----------------
__device__ __align__(16) __nv_bfloat16 g_xh[BATCH * DIMM];
__device__ __align__(16) __nv_bfloat16 g_xl[BATCH * DIMM];
__device__ __align__(16) __nv_bfloat16 g_aoh[BATCH * DIMM];
__device__ __align__(16) __nv_bfloat16 g_aol[BATCH * DIMM];
__device__ __align__(16) __nv_bfloat16 g_h2h[BATCH * DIMM];
__device__ __align__(16) __nv_bfloat16 g_h2l[BATCH * DIMM];
__device__ __align__(16) __nv_bfloat16 g_gh[BATCH * HIDDEN];
__device__ __align__(16) __nv_bfloat16 g_gl[BATCH * HIDDEN];
__device__ __align__(16) float g_q[BATCH * NHQ * HEADD];
__device__ __align__(16) float g_knew[BATCH * NHKV * HEADD];
__device__ __align__(16) float g_vnew[BATCH * NHKV * HEADD];
__device__ __align__(16) float g_res2[BATCH * DIMM];
__device__ __align__(16) float g_P1[1441792];   // 4 x 11008 x 32 max
__device__ __align__(16) float g_P2[1441792];
__device__ __align__(16) float g_apart[NHKV * BATCH * NCH * 520];

// ---------------- HMMA GEMM core ----------------
#define GSMEM 88064

__device__ __forceinline__ void gemm_core(
    const __nv_bfloat16* __restrict__ XH, const __nv_bfloat16* __restrict__ XL,
    int Ktot, const float* __restrict__ W, int ldW,
    float* __restrict__ Pout, int s, int nsplit, char* smem, uint32_t sb)
{
    int tid = threadIdx.x, wid = tid >> 5, lane = tid & 31;
    int chunks = Ktot >> 6;
    int c0 = (chunks * s) / nsplit, c1 = (chunks * (s + 1)) / nsplit;
    int nch = c1 - c0;

    float acc[2][2][4];
    #pragma unroll
    for (int t = 0; t < 2; t++)
        #pragma unroll
        for (int u = 0; u < 2; u++)
            #pragma unroll
            for (int i = 0; i < 4; i++) acc[t][u][i] = 0.f;

    int arow = tid >> 3, aseg = tid & 7;
    int bn = (tid & 15) * 8, bk0 = tid >> 4;

    uint4 AHr, ALr;
    float4 Br[8];

    auto GLOAD = [&](int c) {
        int kg = (c0 + c) << 6;
        AHr = *(const uint4*)(XH + (size_t)arow * Ktot + kg + aseg * 8);
        ALr = *(const uint4*)(XL + (size_t)arow * Ktot + kg + aseg * 8);
        #pragma unroll
        for (int p = 0; p < 4; p++) {
            const float* wp = W + (size_t)(kg + p * 16 + bk0) * ldW + bn;
            Br[2 * p]     = *(const float4*)wp;
            Br[2 * p + 1] = *(const float4*)(wp + 4);
        }
    };
    auto GSTORE = [&](int buf) {
        *(uint4*)(smem + buf * 9216 + arow * 144 + aseg * 16) = AHr;
        *(uint4*)(smem + buf * 9216 + 4608 + arow * 144 + aseg * 16) = ALr;
        #pragma unroll
        for (int p = 0; p < 4; p++) {
            uint32_t H[4], L[4];
            bf16_hilo2(Br[2 * p].x, Br[2 * p].y, H[0], L[0]);
            bf16_hilo2(Br[2 * p].z, Br[2 * p].w, H[1], L[1]);
            bf16_hilo2(Br[2 * p + 1].x, Br[2 * p + 1].y, H[2], L[2]);
            bf16_hilo2(Br[2 * p + 1].z, Br[2 * p + 1].w, H[3], L[3]);
            int k = p * 16 + bk0;
            char* bp = smem + 18432 + buf * 34816 + k * 272 + bn * 2;
            *(uint4*)bp = make_uint4(H[0], H[1], H[2], H[3]);
            *(uint4*)(bp + 17408) = make_uint4(L[0], L[1], L[2], L[3]);
        }
    };

    GLOAD(0);
    GSTORE(0);
    __syncthreads();

    for (int c = 0; c < nch; c++) {
        int buf = c & 1;
        if (c + 1 < nch) GLOAD(c + 1);

        uint32_t abase = sb + buf * 9216;
        uint32_t bbase = sb + 18432 + buf * 34816 + wid * 32;
        uint32_t a_row = ((lane >> 3) & 1) * 8 + (lane & 7);
        uint32_t a_kk8 = (lane >> 4) * 8;
        uint32_t b_kk  = ((lane >> 3) & 1) * 8 + (lane & 7);
        uint32_t b_nn  = (lane >> 4) * 8;

        #pragma unroll
        for (int ks = 0; ks < 4; ks++) {
            uint32_t ah[2][4], al[2][4], bh[4], bl[4];
            #pragma unroll
            for (int t = 0; t < 2; t++) {
                uint32_t ad = abase + (t * 16 + a_row) * 144 + (ks * 16 + a_kk8) * 2;
                ldm_x4(ah[t], ad);
                ldm_x4(al[t], ad + 4608);
            }
            {
                uint32_t bd = bbase + (ks * 16 + b_kk) * 272 + b_nn * 2;
                ldm_x4t(bh, bd);
                ldm_x4t(bl, bd + 17408);
            }
            #pragma unroll
            for (int t = 0; t < 2; t++)
                #pragma unroll
                for (int u = 0; u < 2; u++) {
                    mmab(acc[t][u], ah[t], bh + 2 * u);
                    mmab(acc[t][u], al[t], bh + 2 * u);
                    mmab(acc[t][u], ah[t], bl + 2 * u);
                }
        }
        if (c + 1 < nch) GSTORE((c + 1) & 1);
        __syncthreads();
    }

    int g = lane >> 2, tg = lane & 3;
    #pragma unroll
    for (int t = 0; t < 2; t++)
        #pragma unroll
        for (int u = 0; u < 2; u++) {
            int n = wid * 16 + u * 8 + tg * 2;
            int r0 = t * 16 + g;
            Pout[(size_t)n * 32 + r0]           = acc[t][u][0];
            Pout[(size_t)(n + 1) * 32 + r0]     = acc[t][u][1];
            Pout[(size_t)n * 32 + r0 + 8]       = acc[t][u][2];
            Pout[(size_t)(n + 1) * 32 + r0 + 8] = acc[t][u][3];
        }
}

__global__ void __launch_bounds__(256, 2) gemm_qkv_kernel(
    const __nv_bfloat16* __restrict__ XH, const __nv_bfloat16* __restrict__ XL,
    const float* __restrict__ wq, const float* __restrict__ wk, const float* __restrict__ wv,
    float* __restrict__ P)
{
    extern __shared__ char smem[];
    uint32_t sb = s2u(smem);
    int nbase = blockIdx.x * 128, s = blockIdx.y;
    const float* W; int ld, nloc;
    if (nbase < 4096)      { W = wq; ld = 4096; nloc = nbase; }
    else if (nbase < 5120) { W = wk; ld = 1024; nloc = nbase - 4096; }
    else                   { W = wv; ld = 1024; nloc = nbase - 5120; }
    gemm_core(XH, XL, 4096, W + nloc, ld,
              P + ((size_t)s * 6144 + nbase) * 32, s, 6, smem, sb);
}

__global__ void __launch_bounds__(256, 2) gemm_single_kernel(
    const __nv_bfloat16* __restrict__ XH, const __nv_bfloat16* __restrict__ XL,
    int Ktot, const float* __restrict__ W, int ldW,
    float* __restrict__ P, int PN, int nsplit)
{
    extern __shared__ char smem[];
    uint32_t sb = s2u(smem);
    int nbase = blockIdx.x * 128, s = blockIdx.y;
    gemm_core(XH, XL, Ktot, W + nbase, ldW,
              P + ((size_t)s * PN + nbase) * 32, s, nsplit, smem, sb);
}

__global__ void __launch_bounds__(256, 2) gemm_gate_kernel(
    const __nv_bfloat16* __restrict__ XH, const __nv_bfloat16* __restrict__ XL,
    const float* __restrict__ w1, const float* __restrict__ w3,
    float* __restrict__ P1, float* __restrict__ P2)
{
    extern __shared__ char smem[];
    uint32_t sb = s2u(smem);
    int t = blockIdx.x, s = blockIdx.y;
    if (t < 86) {
        int nbase = t * 128;
        gemm_core(XH, XL, 4096, w1 + nbase, HIDDEN,
                  P1 + ((size_t)s * HIDDEN + nbase) * 32, s, 4, smem, sb);
    } else {
        int nbase = (t - 86) * 128;
        gemm_core(XH, XL, 4096, w3 + nbase, HIDDEN,
                  P2 + ((size_t)s * HIDDEN + nbase) * 32, s, 4, smem, sb);
    }
}

// ---------------- rmsnorm + bf16 hi/lo split ----------------
__global__ void __launch_bounds__(256) rmsnorm_split_kernel(
    const float* __restrict__ x, const float* __restrict__ w,
    __nv_bfloat16* __restrict__ yh, __nv_bfloat16* __restrict__ yl)
{
    int b = blockIdx.x;
    const float* xr = x + (size_t)b * DIMM;
    __shared__ float red[32];
    float ss = 0.f;
    for (int i = threadIdx.x; i < DIMM; i += 256) { float v = xr[i]; ss += v * v; }
    #pragma unroll
    for (int o = 16; o; o >>= 1) ss += __shfl_xor_sync(0xffffffffu, ss, o);
    if ((threadIdx.x & 31) == 0) red[threadIdx.x >> 5] = ss;
    __syncthreads();
    if (threadIdx.x < 32) {
        float v = (threadIdx.x < 8) ? red[threadIdx.x] : 0.f;
        #pragma unroll
        for (int o = 16; o; o >>= 1) v += __shfl_xor_sync(0xffffffffu, v, o);
        if (threadIdx.x == 0) red[0] = v;
    }
    __syncthreads();
    float inv = 1.0f / (sqrtf(red[0] * (1.0f / DIMM)) + EPS);
    for (int i = threadIdx.x; i < DIMM; i += 256) {
        float v = w[i] * xr[i] * inv;
        __nv_bfloat16 h = __float2bfloat16(v);
        yh[(size_t)b * DIMM + i] = h;
        yl[(size_t)b * DIMM + i] = __float2bfloat16(v - __bfloat162float(h));
    }
}

// ---------------- reduces ----------------
__global__ void __launch_bounds__(256) reduce_qkv_rope_kernel(
    const float* __restrict__ P, const float* __restrict__ fcos, const float* __restrict__ fsin,
    float* __restrict__ q, float* __restrict__ knew, float* __restrict__ vnew, int SK)
{
    int c = threadIdx.x & 127, h = threadIdx.x >> 7;
    int colg = blockIdx.x * 512 + 4 * c;
    float4 a[4][4];
    #pragma unroll
    for (int cc = 0; cc < 4; cc++)
        #pragma unroll
        for (int j = 0; j < 4; j++) a[cc][j] = make_float4(0.f, 0.f, 0.f, 0.f);
    for (int kz = 0; kz < SK; kz++) {
        const float* p = P + ((size_t)kz * 6144 + colg) * 32 + h * 16;
        #pragma unroll
        for (int cc = 0; cc < 4; cc++)
            #pragma unroll
            for (int j = 0; j < 4; j++) {
                float4 u = *(const float4*)(p + (size_t)cc * 32 + 4 * j);
                a[cc][j].x += u.x; a[cc][j].y += u.y; a[cc][j].z += u.z; a[cc][j].w += u.w;
            }
    }
    int d0 = colg & 127;
    if (colg < 5120) {
        int i0 = d0 >> 1;
        float c0 = fcos[i0], s0 = fsin[i0];
        float c1 = fcos[i0 + 1], s1 = fsin[i0 + 1];
        float* dst; int head, H;
        if (colg < 4096) { head = colg >> 7; dst = q; H = NHQ; }
        else { head = (colg - 4096) >> 7; dst = knew; H = NHKV; }
        #pragma unroll
        for (int j = 0; j < 4; j++) {
            #pragma unroll
            for (int e = 0; e < 4; e++) {
                int b = h * 16 + 4 * j + e;
                float x0 = (e == 0 ? a[0][j].x : e == 1 ? a[0][j].y : e == 2 ? a[0][j].z : a[0][j].w);
                float x1 = (e == 0 ? a[1][j].x : e == 1 ? a[1][j].y : e == 2 ? a[1][j].z : a[1][j].w);
                float x2 = (e == 0 ? a[2][j].x : e == 1 ? a[2][j].y : e == 2 ? a[2][j].z : a[2][j].w);
                float x3 = (e == 0 ? a[3][j].x : e == 1 ? a[3][j].y : e == 2 ? a[3][j].z : a[3][j].w);
                float* o = dst + ((size_t)b * H + head) * HEADD + d0;
                o[0] = x0 * c0 - x1 * s0;
                o[1] = x0 * s0 + x1 * c0;
                o[2] = x2 * c1 - x3 * s1;
                o[3] = x2 * s1 + x3 * c1;
            }
        }
    } else {
        int g = (colg - 5120) >> 7;
        #pragma unroll
        for (int j = 0; j < 4; j++) {
            #pragma unroll
            for (int e = 0; e < 4; e++) {
                int b = h * 16 + 4 * j + e;
                float x0 = (e == 0 ? a[0][j].x : e == 1 ? a[0][j].y : e == 2 ? a[0][j].z : a[0][j].w);
                float x1 = (e == 0 ? a[1][j].x : e == 1 ? a[1][j].y : e == 2 ? a[1][j].z : a[1][j].w);
                float x2 = (e == 0 ? a[2][j].x : e == 1 ? a[2][j].y : e == 2 ? a[2][j].z : a[2][j].w);
                float x3 = (e == 0 ? a[3][j].x : e == 1 ? a[3][j].y : e == 2 ? a[3][j].z : a[3][j].w);
                float* o = vnew + ((size_t)b * NHKV + g) * HEADD + d0;
                o[0] = x0; o[1] = x1; o[2] = x2; o[3] = x3;
            }
        }
    }
}

__global__ void __launch_bounds__(256) reduce_addres_kernel(
    const float* __restrict__ P, const float* __restrict__ res, float* __restrict__ out,
    int N, int SK)
{
    int c = threadIdx.x & 127, h = threadIdx.x >> 7;
    int n = blockIdx.x * 128 + c;
    float4 a[4];
    #pragma unroll
    for (int j = 0; j < 4; j++) a[j] = make_float4(0.f, 0.f, 0.f, 0.f);
    for (int kz = 0; kz < SK; kz++) {
        const float* p = P + ((size_t)kz * N + n) * 32 + h * 16;
        #pragma unroll
        for (int j = 0; j < 4; j++) {
            float4 u = *(const float4*)(p + 4 * j);
            a[j].x += u.x; a[j].y += u.y; a[j].z += u.z; a[j].w += u.w;
        }
    }
    #pragma unroll
    for (int j = 0; j < 4; j++) {
        int b = h * 16 + 4 * j;
        out[(size_t)(b + 0) * N + n] = a[j].x + res[(size_t)(b + 0) * N + n];
        out[(size_t)(b + 1) * N + n] = a[j].y + res[(size_t)(b + 1) * N + n];
        out[(size_t)(b + 2) * N + n] = a[j].z + res[(size_t)(b + 2) * N + n];
        out[(size_t)(b + 3) * N + n] = a[j].w + res[(size_t)(b + 3) * N + n];
    }
}

__global__ void __launch_bounds__(256) reduce_gate_kernel(
    const float* __restrict__ P1, const float* __restrict__ P2,
    __nv_bfloat16* __restrict__ gh, __nv_bfloat16* __restrict__ gl, int SK)
{
    int c = threadIdx.x & 127, h = threadIdx.x >> 7;
    int n = blockIdx.x * 128 + c;
    float4 a[4], g3[4];
    #pragma unroll
    for (int j = 0; j < 4; j++) { a[j] = make_float4(0.f, 0.f, 0.f, 0.f); g3[j] = a[j]; }
    for (int kz = 0; kz < SK; kz++) {
        const float* p1 = P1 + ((size_t)kz * HIDDEN + n) * 32 + h * 16;
        const float* p3 = P2 + ((size_t)kz * HIDDEN + n) * 32 + h * 16;
        #pragma unroll
        for (int j = 0; j < 4; j++) {
            float4 u = *(const float4*)(p1 + 4 * j);
            a[j].x += u.x; a[j].y += u.y; a[j].z += u.z; a[j].w += u.w;
            float4 w = *(const float4*)(p3 + 4 * j);
            g3[j].x += w.x; g3[j].y += w.y; g3[j].z += w.z; g3[j].w += w.w;
        }
    }
    #pragma unroll
    for (int j = 0; j < 4; j++) {
        float vs[4] = {a[j].x, a[j].y, a[j].z, a[j].w};
        float ws[4] = {g3[j].x, g3[j].y, g3[j].z, g3[j].w};
        #pragma unroll
        for (int e = 0; e < 4; e++) {
            int b = h * 16 + 4 * j + e;
            float v = (vs[e] / (1.f + expf(-vs[e]))) * ws[e];
            __nv_bfloat16 hh = __float2bfloat16(v);
            gh[(size_t)b * HIDDEN + n] = hh;
            gl[(size_t)b * HIDDEN + n] = __float2bfloat16(v - __bfloat162float(hh));
        }
    }
}

// ---------------- attention: split-L x8, merged-shfl scores, float4 V ----------------
__global__ void __launch_bounds__(256) attn_part_kernel(
    const float* __restrict__ cache_k, const float* __restrict__ cache_v,
    const float* __restrict__ q, const float* __restrict__ knew, const float* __restrict__ vnew,
    float* __restrict__ apart)
{
    int g = blockIdx.x, b = blockIdx.y, ch = blockIdx.z;
    int lbase = ch * CHL;
    int cs = (ch == NCH - 1) ? CHL + 1 : CHL;
    __shared__ __align__(16) float sc[4][136];
    __shared__ __align__(16) float qs[4][HEADD];
    __shared__ float red[8];
    __shared__ __align__(16) float vred[8][4][32][4];
    int tid = threadIdx.x, warp = tid >> 5, lane = tid & 31;
    float* ap = apart + (size_t)((g * 32 + b) * NCH + ch) * 520;

    for (int i = tid; i < 4 * HEADD; i += 256) {
        int r = i >> 7, d = i & 127;
        qs[r][d] = q[((size_t)b * NHQ + (g * 4 + r)) * HEADD + d];
    }
    __syncthreads();
    float ql[4][4];
    #pragma unroll
    for (int r = 0; r < 4; r++) {
        float4 t = *(const float4*)&qs[r][lane * 4];
        ql[r][0] = t.x; ql[r][1] = t.y; ql[r][2] = t.z; ql[r][3] = t.w;
    }
    const float scale = 0.08838834764831845f;
    bool odd1 = (lane & 1), odd2 = (lane & 2);

    #pragma unroll 2
    for (int i = 0; i < CHL / 8; i++) {
        int li = warp + i * 8;
        int l = lbase + li;
        const float* kp = cache_k + (((size_t)b * MAXSEQ + l) * NHKV + g) * HEADD;
        float4 kv = *(const float4*)(kp + lane * 4);
        float p0 = kv.x * ql[0][0] + kv.y * ql[0][1] + kv.z * ql[0][2] + kv.w * ql[0][3];
        float p1 = kv.x * ql[1][0] + kv.y * ql[1][1] + kv.z * ql[1][2] + kv.w * ql[1][3];
        float p2 = kv.x * ql[2][0] + kv.y * ql[2][1] + kv.z * ql[2][2] + kv.w * ql[2][3];
        float p3 = kv.x * ql[3][0] + kv.y * ql[3][1] + kv.z * ql[3][2] + kv.w * ql[3][3];
        float a01 = (odd1 ? p1 : p0) + __shfl_xor_sync(0xffffffffu, odd1 ? p0 : p1, 1);
        float a23 = (odd1 ? p3 : p2) + __shfl_xor_sync(0xffffffffu, odd1 ? p2 : p3, 1);
        float v4 = (odd2 ? a23 : a01) + __shfl_xor_sync(0xffffffffu, odd2 ? a01 : a23, 2);
        v4 += __shfl_xor_sync(0xffffffffu, v4, 4);
        v4 += __shfl_xor_sync(0xffffffffu, v4, 8);
        v4 += __shfl_xor_sync(0xffffffffu, v4, 16);
        if (lane < 4) sc[lane][li] = v4 * scale;
    }
    if (ch == NCH - 1 && warp == 0) {
        const float* kp = knew + ((size_t)b * NHKV + g) * HEADD;
        float4 kv = *(const float4*)(kp + lane * 4);
        float p0 = kv.x * ql[0][0] + kv.y * ql[0][1] + kv.z * ql[0][2] + kv.w * ql[0][3];
        float p1 = kv.x * ql[1][0] + kv.y * ql[1][1] + kv.z * ql[1][2] + kv.w * ql[1][3];
        float p2 = kv.x * ql[2][0] + kv.y * ql[2][1] + kv.z * ql[2][2] + kv.w * ql[2][3];
        float p3 = kv.x * ql[3][0] + kv.y * ql[3][1] + kv.z * ql[3][2] + kv.w * ql[3][3];
        float a01 = (odd1 ? p1 : p0) + __shfl_xor_sync(0xffffffffu, odd1 ? p0 : p1, 1);
        float a23 = (odd1 ? p3 : p2) + __shfl_xor_sync(0xffffffffu, odd1 ? p2 : p3, 1);
        float v4 = (odd2 ? a23 : a01) + __shfl_xor_sync(0xffffffffu, odd2 ? a01 : a23, 2);
        v4 += __shfl_xor_sync(0xffffffffu, v4, 4);
        v4 += __shfl_xor_sync(0xffffffffu, v4, 8);
        v4 += __shfl_xor_sync(0xffffffffu, v4, 16);
        if (lane < 4) sc[lane][CHL] = v4 * scale;
    }
    __syncthreads();

    {
        int r = tid >> 6, t = tid & 63;
        float m = -1e30f;
        for (int li = t; li < cs; li += 64) m = fmaxf(m, sc[r][li]);
        #pragma unroll
        for (int o = 16; o; o >>= 1) m = fmaxf(m, __shfl_xor_sync(0xffffffffu, m, o));
        if (lane == 0) red[warp] = m;
        __syncthreads();
        m = fmaxf(red[2 * r], red[2 * r + 1]);
        float s = 0.f;
        for (int li = t; li < cs; li += 64) {
            float e = expf(sc[r][li] - m);
            sc[r][li] = e; s += e;
        }
        #pragma unroll
        for (int o = 16; o; o >>= 1) s += __shfl_xor_sync(0xffffffffu, s, o);
        __syncthreads();
        if (lane == 0) red[warp] = s;
        __syncthreads();
        s = red[2 * r] + red[2 * r + 1];
        if (t == 0) { ap[r] = m; ap[4 + r] = s; }
    }
    __syncthreads();

    {
        int quad = tid & 31, sl = tid >> 5;
        float4 a0 = make_float4(0, 0, 0, 0), a1 = a0, a2 = a0, a3 = a0;
        #pragma unroll 4
        for (int li = sl; li < cs; li += 8) {
            int l = lbase + li;
            const float* vp = (l < STARTPOS)
                ? cache_v + (((size_t)b * MAXSEQ + l) * NHKV + g) * HEADD
                : vnew + ((size_t)b * NHKV + g) * HEADD;
            float4 v = *(const float4*)(vp + quad * 4);
            float s0 = sc[0][li], s1 = sc[1][li], s2 = sc[2][li], s3 = sc[3][li];
            a0.x += s0 * v.x; a0.y += s0 * v.y; a0.z += s0 * v.z; a0.w += s0 * v.w;
            a1.x += s1 * v.x; a1.y += s1 * v.y; a1.z += s1 * v.z; a1.w += s1 * v.w;
            a2.x += s2 * v.x; a2.y += s2 * v.y; a2.z += s2 * v.z; a2.w += s2 * v.w;
            a3.x += s3 * v.x; a3.y += s3 * v.y; a3.z += s3 * v.z; a3.w += s3 * v.w;
        }
        *(float4*)&vred[sl][0][quad][0] = a0;
        *(float4*)&vred[sl][1][quad][0] = a1;
        *(float4*)&vred[sl][2][quad][0] = a2;
        *(float4*)&vred[sl][3][quad][0] = a3;
    }
    __syncthreads();
    if (tid < 128) {
        int head = tid >> 5, quad = tid & 31;
        float4 s = make_float4(0, 0, 0, 0);
        #pragma unroll
        for (int sl = 0; sl < 8; sl++) {
            float4 u = *(const float4*)&vred[sl][head][quad][0];
            s.x += u.x; s.y += u.y; s.z += u.z; s.w += u.w;
        }
        *(float4*)(ap + 8 + head * 128 + quad * 4) = s;
    }
}

__global__ void __launch_bounds__(128) attn_combine_kernel(
    const float* __restrict__ apart,
    __nv_bfloat16* __restrict__ aoh, __nv_bfloat16* __restrict__ aol)
{
    int g = blockIdx.x, b = blockIdx.y, d = threadIdx.x;
    const float* base = apart + (size_t)((g * 32 + b) * NCH) * 520;
    #pragma unroll
    for (int r = 0; r < 4; r++) {
        float M = -1e30f;
        #pragma unroll
        for (int c = 0; c < NCH; c++) M = fmaxf(M, base[c * 520 + r]);
        float denom = 0.f, o = 0.f;
        #pragma unroll
        for (int c = 0; c < NCH; c++) {
            float w = expf(base[c * 520 + r] - M);
            denom += base[c * 520 + 4 + r] * w;
            o += base[c * 520 + 8 + r * 128 + d] * w;
        }
        float v = o / denom;
        __nv_bfloat16 hh = __float2bfloat16(v);
        size_t idx = (size_t)b * DIMM + (g * 4 + r) * 128 + d;
        aoh[idx] = hh;
        aol[idx] = __float2bfloat16(v - __bfloat162float(hh));
    }
}

// ---------------- launch ----------------
extern "C" void kernel_launch(void* const* d_in, const int* in_sizes, int n_in,
                              void* d_out, int out_size)
{
    const float* x     = (const float*)d_in[0];
    const float* fcos  = (const float*)d_in[2];
    const float* fsin  = (const float*)d_in[3];
    const float* cachek = (const float*)d_in[4];
    const float* cachev = (const float*)d_in[5];
    const float* wq = (const float*)d_in[6];
    const float* wk = (const float*)d_in[7];
    const float* wv = (const float*)d_in[8];
    const float* wo = (const float*)d_in[9];
    const float* w1 = (const float*)d_in[10];
    const float* w2 = (const float*)d_in[11];
    const float* w3 = (const float*)d_in[12];
    const float* anw = (const float*)d_in[13];
    const float* fnw = (const float*)d_in[14];
    float* out = (float*)d_out;

    __nv_bfloat16 *p_xh, *p_xl, *p_aoh, *p_aol, *p_h2h, *p_h2l, *p_gh, *p_gl;
    float *p_q, *p_knew, *p_vnew, *p_res2, *p_P1, *p_P2, *p_apart;
    cudaGetSymbolAddress((void**)&p_xh, g_xh);
    cudaGetSymbolAddress((void**)&p_xl, g_xl);
    cudaGetSymbolAddress((void**)&p_aoh, g_aoh);
    cudaGetSymbolAddress((void**)&p_aol, g_aol);
    cudaGetSymbolAddress((void**)&p_h2h, g_h2h);
    cudaGetSymbolAddress((void**)&p_h2l, g_h2l);
    cudaGetSymbolAddress((void**)&p_gh, g_gh);
    cudaGetSymbolAddress((void**)&p_gl, g_gl);
    cudaGetSymbolAddress((void**)&p_q, g_q);
    cudaGetSymbolAddress((void**)&p_knew, g_knew);
    cudaGetSymbolAddress((void**)&p_vnew, g_vnew);
    cudaGetSymbolAddress((void**)&p_res2, g_res2);
    cudaGetSymbolAddress((void**)&p_P1, g_P1);
    cudaGetSymbolAddress((void**)&p_P2, g_P2);
    cudaGetSymbolAddress((void**)&p_apart, g_apart);

    cudaFuncSetAttribute(gemm_qkv_kernel, cudaFuncAttributeMaxDynamicSharedMemorySize, GSMEM);
    cudaFuncSetAttribute(gemm_single_kernel, cudaFuncAttributeMaxDynamicSharedMemorySize, GSMEM);
    cudaFuncSetAttribute(gemm_gate_kernel, cudaFuncAttributeMaxDynamicSharedMemorySize, GSMEM);

    rmsnorm_split_kernel<<<32, 256>>>(x, anw, p_xh, p_xl);
    gemm_qkv_kernel<<<dim3(48, 6), 256, GSMEM>>>(p_xh, p_xl, wq, wk, wv, p_P1);
    reduce_qkv_rope_kernel<<<12, 256>>>(p_P1, fcos, fsin, p_q, p_knew, p_vnew, 6);
    attn_part_kernel<<<dim3(8, 32, NCH), 256>>>(cachek, cachev, p_q, p_knew, p_vnew, p_apart);
    attn_combine_kernel<<<dim3(8, 32), 128>>>(p_apart, p_aoh, p_aol);
    gemm_single_kernel<<<dim3(32, 9), 256, GSMEM>>>(p_aoh, p_aol, 4096, wo, 4096, p_P1, 4096, 9);
    reduce_addres_kernel<<<32, 256>>>(p_P1, x, p_res2, 4096, 9);
    rmsnorm_split_kernel<<<32, 256>>>(p_res2, fnw, p_h2h, p_h2l);
    gemm_gate_kernel<<<dim3(172, 4), 256, GSMEM>>>(p_h2h, p_h2l, w1, w3, p_P1, p_P2);
    reduce_gate_kernel<<<86, 256>>>(p_P1, p_P2, p_gh, p_gl, 4);
    gemm_single_kernel<<<dim3(32, 9), 256, GSMEM>>>(p_gh, p_gl, 11008, w2, 4096, p_P1, 4096, 9);
    reduce_addres_kernel<<<32, 256>>>(p_P1, p_res2, out, 4096, 9);
}

// round 8
// speedup vs baseline: 2.8640x; 1.0437x over previous
#include <cuda_runtime.h>
#include <cuda_fp16.h>
#include <math.h>
#include <stdint.h>

#define DIMM 4096
#define HEADD 128
#define NHQ 32
#define NHKV 8
#define HIDDEN 11008
#define BATCH 32
#define MAXSEQ 2048
#define STARTPOS 1024
#define SEQL (STARTPOS + 1)
#define EPS 1e-5f
#define NCH 8
#define CHL 128

// ---------------- PTX helpers (baseline PTX only) ----------------
__device__ __forceinline__ uint32_t s2u(const void* p) {
    uint32_t a;
    asm("{ .reg .u64 t; cvta.to.shared.u64 t, %1; cvt.u32.u64 %0, t; }" : "=r"(a) : "l"(p));
    return a;
}
__device__ __forceinline__ void ldm_x4(uint32_t* r, uint32_t a) {
    asm volatile("ldmatrix.sync.aligned.m8n8.x4.shared.b16 {%0,%1,%2,%3}, [%4];"
                 : "=r"(r[0]), "=r"(r[1]), "=r"(r[2]), "=r"(r[3]) : "r"(a));
}
__device__ __forceinline__ void ldm_x4t(uint32_t* r, uint32_t a) {
    asm volatile("ldmatrix.sync.aligned.m8n8.x4.trans.shared.b16 {%0,%1,%2,%3}, [%4];"
                 : "=r"(r[0]), "=r"(r[1]), "=r"(r[2]), "=r"(r[3]) : "r"(a));
}
__device__ __forceinline__ void mmah(float* c, const uint32_t* a, const uint32_t* b) {
    asm volatile(
        "mma.sync.aligned.m16n8k16.row.col.f32.f16.f16.f32 "
        "{%0,%1,%2,%3}, {%4,%5,%6,%7}, {%8,%9}, {%0,%1,%2,%3};"
        : "+f"(c[0]), "+f"(c[1]), "+f"(c[2]), "+f"(c[3])
        : "r"(a[0]), "r"(a[1]), "r"(a[2]), "r"(a[3]), "r"(b[0]), "r"(b[1]));
}
__device__ __forceinline__ uint32_t f16pack(float a, float b) {
    __half2 h = __floats2half2_rn(a, b);
    return *reinterpret_cast<uint32_t*>(&h);
}

// ---------------- scratch ----------------
__device__ __align__(16) __half g_xh[BATCH * DIMM];
__device__ __align__(16) __half g_xl[BATCH * DIMM];
__device__ __align__(16) __half g_aoh[BATCH * DIMM];
__device__ __align__(16) __half g_aol[BATCH * DIMM];
__device__ __align__(16) __half g_h2h[BATCH * DIMM];
__device__ __align__(16) __half g_h2l[BATCH * DIMM];
__device__ __align__(16) __half g_gh[BATCH * HIDDEN];
__device__ __align__(16) __half g_gl[BATCH * HIDDEN];
__device__ __align__(16) float g_q[BATCH * NHQ * HEADD];
__device__ __align__(16) float g_knew[BATCH * NHKV * HEADD];
__device__ __align__(16) float g_vnew[BATCH * NHKV * HEADD];
__device__ __align__(16) float g_res2[BATCH * DIMM];
__device__ __align__(16) float g_P1[2359296];   // 12 x 6144 x 32 / 18 x 4096 x 32
__device__ __align__(16) float g_P2[1056768];   // 3 x 11008 x 32
__device__ __align__(16) float g_apart[NHKV * BATCH * NCH * 520];

// ---------------- HMMA GEMM core: M=32 x N=256, K64 chunks, fp16 ----------------
// A = X fp16 hi/lo pairs (2 passes), B = W fp32 -> fp16 single pass.
// smem: A: buf*9216 (AH 32x144B, AL at +4608); B: 18432 + buf*33792 (64 rows x 528B)
#define BPITCH 528
#define GSMEM 86016

__device__ __forceinline__ void gemm_core(
    const __half* __restrict__ XH, const __half* __restrict__ XL,
    int Ktot, const float* __restrict__ W, int ldW,
    float* __restrict__ Pout, int s, int nsplit, char* smem, uint32_t sb)
{
    int tid = threadIdx.x, wid = tid >> 5, lane = tid & 31;
    int chunks = Ktot >> 6;
    int c0 = (chunks * s) / nsplit, c1 = (chunks * (s + 1)) / nsplit;
    int nch = c1 - c0;

    float acc[2][4][4];
    #pragma unroll
    for (int t = 0; t < 2; t++)
        #pragma unroll
        for (int u = 0; u < 4; u++)
            #pragma unroll
            for (int i = 0; i < 4; i++) acc[t][u][i] = 0.f;

    int arow = tid >> 3, aseg = tid & 7;        // A: 32 rows x 8 segs of 16B
    int bcol = (tid & 31) * 8, brow0 = tid >> 5; // B: row group per warp, 8 cols/thread

    uint4 AHr, ALr;
    float4 Br[8];   // half of B: 4 rows x 8 floats

    auto GLOADA = [&](int c) {
        int kg = (c0 + c) << 6;
        AHr = *(const uint4*)(XH + (size_t)arow * Ktot + kg + aseg * 8);
        ALr = *(const uint4*)(XL + (size_t)arow * Ktot + kg + aseg * 8);
    };
    auto GLOADB = [&](int c, int half) {
        int kg = (c0 + c) << 6;
        #pragma unroll
        for (int p = 0; p < 4; p++) {
            int row = brow0 + (half * 4 + p) * 8;
            const float* wp = W + (size_t)(kg + row) * ldW + bcol;
            Br[2 * p]     = *(const float4*)wp;
            Br[2 * p + 1] = *(const float4*)(wp + 4);
        }
    };
    auto GSTOREA = [&](int buf) {
        *(uint4*)(smem + buf * 9216 + arow * 144 + aseg * 16) = AHr;
        *(uint4*)(smem + buf * 9216 + 4608 + arow * 144 + aseg * 16) = ALr;
    };
    auto GSTOREB = [&](int buf, int half) {
        #pragma unroll
        for (int p = 0; p < 4; p++) {
            int row = brow0 + (half * 4 + p) * 8;
            uint4 q;
            q.x = f16pack(Br[2 * p].x, Br[2 * p].y);
            q.y = f16pack(Br[2 * p].z, Br[2 * p].w);
            q.z = f16pack(Br[2 * p + 1].x, Br[2 * p + 1].y);
            q.w = f16pack(Br[2 * p + 1].z, Br[2 * p + 1].w);
            *(uint4*)(smem + 18432 + buf * 33792 + row * BPITCH + bcol * 2) = q;
        }
    };

    // prologue: fill buf 0
    GLOADA(0); GLOADB(0, 0);
    GSTOREA(0); GSTOREB(0, 0);
    GLOADB(0, 1); GSTOREB(0, 1);
    __syncthreads();

    uint32_t a_row = ((lane >> 3) & 1) * 8 + (lane & 7);
    uint32_t a_kk8 = (lane >> 4) * 8;
    uint32_t b_kk  = ((lane >> 3) & 1) * 8 + (lane & 7);
    uint32_t b_nn  = (lane >> 4) * 8;

    for (int c = 0; c < nch; c++) {
        int buf = c & 1, nb = (c + 1) & 1;
        bool more = (c + 1 < nch);
        if (more) { GLOADA(c + 1); GLOADB(c + 1, 0); }

        uint32_t abase = sb + buf * 9216;
        uint32_t bbase = sb + 18432 + buf * 33792 + wid * 64;

        #pragma unroll
        for (int ks = 0; ks < 2; ks++) {
            uint32_t ah[2][4], al[2][4], bf[2][4];
            #pragma unroll
            for (int t = 0; t < 2; t++) {
                uint32_t ad = abase + (t * 16 + a_row) * 144 + (ks * 16 + a_kk8) * 2;
                ldm_x4(ah[t], ad);
                ldm_x4(al[t], ad + 4608);
            }
            uint32_t bd = bbase + (ks * 16 + b_kk) * BPITCH + b_nn * 2;
            ldm_x4t(bf[0], bd);
            ldm_x4t(bf[1], bd + 32);
            #pragma unroll
            for (int t = 0; t < 2; t++)
                #pragma unroll
                for (int u = 0; u < 4; u++) {
                    mmah(acc[t][u], ah[t], &bf[u >> 1][2 * (u & 1)]);
                    mmah(acc[t][u], al[t], &bf[u >> 1][2 * (u & 1)]);
                }
        }
        if (more) { GSTOREA(nb); GSTOREB(nb, 0); GLOADB(c + 1, 1); }
        #pragma unroll
        for (int ks = 2; ks < 4; ks++) {
            uint32_t ah[2][4], al[2][4], bf[2][4];
            #pragma unroll
            for (int t = 0; t < 2; t++) {
                uint32_t ad = abase + (t * 16 + a_row) * 144 + (ks * 16 + a_kk8) * 2;
                ldm_x4(ah[t], ad);
                ldm_x4(al[t], ad + 4608);
            }
            uint32_t bd = bbase + (ks * 16 + b_kk) * BPITCH + b_nn * 2;
            ldm_x4t(bf[0], bd);
            ldm_x4t(bf[1], bd + 32);
            #pragma unroll
            for (int t = 0; t < 2; t++)
                #pragma unroll
                for (int u = 0; u < 4; u++) {
                    mmah(acc[t][u], ah[t], &bf[u >> 1][2 * (u & 1)]);
                    mmah(acc[t][u], al[t], &bf[u >> 1][2 * (u & 1)]);
                }
        }
        if (more) GSTOREB(nb, 1);
        __syncthreads();
    }

    int g = lane >> 2, tg = lane & 3;
    #pragma unroll
    for (int t = 0; t < 2; t++)
        #pragma unroll
        for (int u = 0; u < 4; u++) {
            int n = wid * 32 + u * 8 + tg * 2;
            int r0 = t * 16 + g;
            Pout[(size_t)n * 32 + r0]           = acc[t][u][0];
            Pout[(size_t)(n + 1) * 32 + r0]     = acc[t][u][1];
            Pout[(size_t)n * 32 + r0 + 8]       = acc[t][u][2];
            Pout[(size_t)(n + 1) * 32 + r0 + 8] = acc[t][u][3];
        }
}

// fused qkv: tiles 0..15 wq, 16..19 wk, 20..23 wv (256 cols each)
__global__ void __launch_bounds__(256, 2) gemm_qkv_kernel(
    const __half* __restrict__ XH, const __half* __restrict__ XL,
    const float* __restrict__ wq, const float* __restrict__ wk, const float* __restrict__ wv,
    float* __restrict__ P)
{
    extern __shared__ char smem[];
    uint32_t sb = s2u(smem);
    int nbase = blockIdx.x * 256, s = blockIdx.y;
    const float* W; int ld, nloc;
    if (nbase < 4096)      { W = wq; ld = 4096; nloc = nbase; }
    else if (nbase < 5120) { W = wk; ld = 1024; nloc = nbase - 4096; }
    else                   { W = wv; ld = 1024; nloc = nbase - 5120; }
    gemm_core(XH, XL, 4096, W + nloc, ld,
              P + ((size_t)s * 6144 + nbase) * 32, s, 12, smem, sb);
}

__global__ void __launch_bounds__(256, 2) gemm_single_kernel(
    const __half* __restrict__ XH, const __half* __restrict__ XL,
    int Ktot, const float* __restrict__ W, int ldW,
    float* __restrict__ P, int PN, int nsplit)
{
    extern __shared__ char smem[];
    uint32_t sb = s2u(smem);
    int nbase = blockIdx.x * 256, s = blockIdx.y;
    gemm_core(XH, XL, Ktot, W + nbase, ldW,
              P + ((size_t)s * PN + nbase) * 32, s, nsplit, smem, sb);
}

// fused gate: tiles 0..42 -> w1/P1, 43..85 -> w3/P2
__global__ void __launch_bounds__(256, 2) gemm_gate_kernel(
    const __half* __restrict__ XH, const __half* __restrict__ XL,
    const float* __restrict__ w1, const float* __restrict__ w3,
    float* __restrict__ P1, float* __restrict__ P2)
{
    extern __shared__ char smem[];
    uint32_t sb = s2u(smem);
    int t = blockIdx.x, s = blockIdx.y;
    if (t < 43) {
        int nbase = t * 256;
        gemm_core(XH, XL, 4096, w1 + nbase, HIDDEN,
                  P1 + ((size_t)s * HIDDEN + nbase) * 32, s, 3, smem, sb);
    } else {
        int nbase = (t - 43) * 256;
        gemm_core(XH, XL, 4096, w3 + nbase, HIDDEN,
                  P2 + ((size_t)s * HIDDEN + nbase) * 32, s, 3, smem, sb);
    }
}

// ---------------- rmsnorm + fp16 hi/lo split (b-major out) ----------------
__global__ void __launch_bounds__(256) rmsnorm_split_kernel(
    const float* __restrict__ x, const float* __restrict__ w,
    __half* __restrict__ yh, __half* __restrict__ yl)
{
    int b = blockIdx.x;
    const float* xr = x + (size_t)b * DIMM;
    __shared__ float red[32];
    float ss = 0.f;
    for (int i = threadIdx.x; i < DIMM; i += 256) { float v = xr[i]; ss += v * v; }
    #pragma unroll
    for (int o = 16; o; o >>= 1) ss += __shfl_xor_sync(0xffffffffu, ss, o);
    if ((threadIdx.x & 31) == 0) red[threadIdx.x >> 5] = ss;
    __syncthreads();
    if (threadIdx.x < 32) {
        float v = (threadIdx.x < 8) ? red[threadIdx.x] : 0.f;
        #pragma unroll
        for (int o = 16; o; o >>= 1) v += __shfl_xor_sync(0xffffffffu, v, o);
        if (threadIdx.x == 0) red[0] = v;
    }
    __syncthreads();
    float inv = 1.0f / (sqrtf(red[0] * (1.0f / DIMM)) + EPS);
    for (int i = threadIdx.x; i < DIMM; i += 256) {
        float v = w[i] * xr[i] * inv;
        __half h = __float2half_rn(v);
        yh[(size_t)b * DIMM + i] = h;
        yl[(size_t)b * DIMM + i] = __float2half_rn(v - __half2float(h));
    }
}

// ---------------- reduces ----------------
__global__ void __launch_bounds__(256) reduce_qkv_rope_kernel(
    const float* __restrict__ P, const float* __restrict__ fcos, const float* __restrict__ fsin,
    float* __restrict__ q, float* __restrict__ knew, float* __restrict__ vnew, int SK)
{
    int c = threadIdx.x & 127, h = threadIdx.x >> 7;
    int colg = blockIdx.x * 512 + 4 * c;
    float4 a[4][4];
    #pragma unroll
    for (int cc = 0; cc < 4; cc++)
        #pragma unroll
        for (int j = 0; j < 4; j++) a[cc][j] = make_float4(0.f, 0.f, 0.f, 0.f);
    for (int kz = 0; kz < SK; kz++) {
        const float* p = P + ((size_t)kz * 6144 + colg) * 32 + h * 16;
        #pragma unroll
        for (int cc = 0; cc < 4; cc++)
            #pragma unroll
            for (int j = 0; j < 4; j++) {
                float4 u = *(const float4*)(p + (size_t)cc * 32 + 4 * j);
                a[cc][j].x += u.x; a[cc][j].y += u.y; a[cc][j].z += u.z; a[cc][j].w += u.w;
            }
    }
    int d0 = colg & 127;
    if (colg < 5120) {
        int i0 = d0 >> 1;
        float c0 = fcos[i0], s0 = fsin[i0];
        float c1 = fcos[i0 + 1], s1 = fsin[i0 + 1];
        float* dst; int head, H;
        if (colg < 4096) { head = colg >> 7; dst = q; H = NHQ; }
        else { head = (colg - 4096) >> 7; dst = knew; H = NHKV; }
        #pragma unroll
        for (int j = 0; j < 4; j++) {
            #pragma unroll
            for (int e = 0; e < 4; e++) {
                int b = h * 16 + 4 * j + e;
                float x0 = (e == 0 ? a[0][j].x : e == 1 ? a[0][j].y : e == 2 ? a[0][j].z : a[0][j].w);
                float x1 = (e == 0 ? a[1][j].x : e == 1 ? a[1][j].y : e == 2 ? a[1][j].z : a[1][j].w);
                float x2 = (e == 0 ? a[2][j].x : e == 1 ? a[2][j].y : e == 2 ? a[2][j].z : a[2][j].w);
                float x3 = (e == 0 ? a[3][j].x : e == 1 ? a[3][j].y : e == 2 ? a[3][j].z : a[3][j].w);
                float* o = dst + ((size_t)b * H + head) * HEADD + d0;
                o[0] = x0 * c0 - x1 * s0;
                o[1] = x0 * s0 + x1 * c0;
                o[2] = x2 * c1 - x3 * s1;
                o[3] = x2 * s1 + x3 * c1;
            }
        }
    } else {
        int g = (colg - 5120) >> 7;
        #pragma unroll
        for (int j = 0; j < 4; j++) {
            #pragma unroll
            for (int e = 0; e < 4; e++) {
                int b = h * 16 + 4 * j + e;
                float x0 = (e == 0 ? a[0][j].x : e == 1 ? a[0][j].y : e == 2 ? a[0][j].z : a[0][j].w);
                float x1 = (e == 0 ? a[1][j].x : e == 1 ? a[1][j].y : e == 2 ? a[1][j].z : a[1][j].w);
                float x2 = (e == 0 ? a[2][j].x : e == 1 ? a[2][j].y : e == 2 ? a[2][j].z : a[2][j].w);
                float x3 = (e == 0 ? a[3][j].x : e == 1 ? a[3][j].y : e == 2 ? a[3][j].z : a[3][j].w);
                float* o = vnew + ((size_t)b * NHKV + g) * HEADD + d0;
                o[0] = x0; o[1] = x1; o[2] = x2; o[3] = x3;
            }
        }
    }
}

__global__ void __launch_bounds__(256) reduce_addres_kernel(
    const float* __restrict__ P, const float* __restrict__ res, float* __restrict__ out,
    int N, int SK)
{
    int c = threadIdx.x & 127, h = threadIdx.x >> 7;
    int n = blockIdx.x * 128 + c;
    float4 a[4];
    #pragma unroll
    for (int j = 0; j < 4; j++) a[j] = make_float4(0.f, 0.f, 0.f, 0.f);
    for (int kz = 0; kz < SK; kz++) {
        const float* p = P + ((size_t)kz * N + n) * 32 + h * 16;
        #pragma unroll
        for (int j = 0; j < 4; j++) {
            float4 u = *(const float4*)(p + 4 * j);
            a[j].x += u.x; a[j].y += u.y; a[j].z += u.z; a[j].w += u.w;
        }
    }
    #pragma unroll
    for (int j = 0; j < 4; j++) {
        int b = h * 16 + 4 * j;
        out[(size_t)(b + 0) * N + n] = a[j].x + res[(size_t)(b + 0) * N + n];
        out[(size_t)(b + 1) * N + n] = a[j].y + res[(size_t)(b + 1) * N + n];
        out[(size_t)(b + 2) * N + n] = a[j].z + res[(size_t)(b + 2) * N + n];
        out[(size_t)(b + 3) * N + n] = a[j].w + res[(size_t)(b + 3) * N + n];
    }
}

__global__ void __launch_bounds__(256) reduce_gate_kernel(
    const float* __restrict__ P1, const float* __restrict__ P2,
    __half* __restrict__ gh, __half* __restrict__ gl, int SK)
{
    int c = threadIdx.x & 127, h = threadIdx.x >> 7;
    int n = blockIdx.x * 128 + c;
    float4 a[4], g3[4];
    #pragma unroll
    for (int j = 0; j < 4; j++) { a[j] = make_float4(0.f, 0.f, 0.f, 0.f); g3[j] = a[j]; }
    for (int kz = 0; kz < SK; kz++) {
        const float* p1 = P1 + ((size_t)kz * HIDDEN + n) * 32 + h * 16;
        const float* p3 = P2 + ((size_t)kz * HIDDEN + n) * 32 + h * 16;
        #pragma unroll
        for (int j = 0; j < 4; j++) {
            float4 u = *(const float4*)(p1 + 4 * j);
            a[j].x += u.x; a[j].y += u.y; a[j].z += u.z; a[j].w += u.w;
            float4 w = *(const float4*)(p3 + 4 * j);
            g3[j].x += w.x; g3[j].y += w.y; g3[j].z += w.z; g3[j].w += w.w;
        }
    }
    #pragma unroll
    for (int j = 0; j < 4; j++) {
        float vs[4] = {a[j].x, a[j].y, a[j].z, a[j].w};
        float ws[4] = {g3[j].x, g3[j].y, g3[j].z, g3[j].w};
        #pragma unroll
        for (int e = 0; e < 4; e++) {
            int b = h * 16 + 4 * j + e;
            float v = (vs[e] / (1.f + expf(-vs[e]))) * ws[e];
            __half hh = __float2half_rn(v);
            gh[(size_t)b * HIDDEN + n] = hh;
            gl[(size_t)b * HIDDEN + n] = __float2half_rn(v - __half2float(hh));
        }
    }
}

// ---------------- attention: split-L x8, merged-shfl scores, float4 V ----------------
__global__ void __launch_bounds__(256) attn_part_kernel(
    const float* __restrict__ cache_k, const float* __restrict__ cache_v,
    const float* __restrict__ q, const float* __restrict__ knew, const float* __restrict__ vnew,
    float* __restrict__ apart)
{
    int g = blockIdx.x, b = blockIdx.y, ch = blockIdx.z;
    int lbase = ch * CHL;
    int cs = (ch == NCH - 1) ? CHL + 1 : CHL;
    __shared__ __align__(16) float sc[4][136];
    __shared__ __align__(16) float qs[4][HEADD];
    __shared__ float red[8];
    __shared__ __align__(16) float vred[8][4][32][4];
    int tid = threadIdx.x, warp = tid >> 5, lane = tid & 31;
    float* ap = apart + (size_t)((g * 32 + b) * NCH + ch) * 520;

    for (int i = tid; i < 4 * HEADD; i += 256) {
        int r = i >> 7, d = i & 127;
        qs[r][d] = q[((size_t)b * NHQ + (g * 4 + r)) * HEADD + d];
    }
    __syncthreads();
    float ql[4][4];
    #pragma unroll
    for (int r = 0; r < 4; r++) {
        float4 t = *(const float4*)&qs[r][lane * 4];
        ql[r][0] = t.x; ql[r][1] = t.y; ql[r][2] = t.z; ql[r][3] = t.w;
    }
    const float scale = 0.08838834764831845f;
    bool odd1 = (lane & 1), odd2 = (lane & 2);

    #pragma unroll 2
    for (int i = 0; i < CHL / 8; i++) {
        int li = warp + i * 8;
        int l = lbase + li;
        const float* kp = cache_k + (((size_t)b * MAXSEQ + l) * NHKV + g) * HEADD;
        float4 kv = *(const float4*)(kp + lane * 4);
        float p0 = kv.x * ql[0][0] + kv.y * ql[0][1] + kv.z * ql[0][2] + kv.w * ql[0][3];
        float p1 = kv.x * ql[1][0] + kv.y * ql[1][1] + kv.z * ql[1][2] + kv.w * ql[1][3];
        float p2 = kv.x * ql[2][0] + kv.y * ql[2][1] + kv.z * ql[2][2] + kv.w * ql[2][3];
        float p3 = kv.x * ql[3][0] + kv.y * ql[3][1] + kv.z * ql[3][2] + kv.w * ql[3][3];
        float a01 = (odd1 ? p1 : p0) + __shfl_xor_sync(0xffffffffu, odd1 ? p0 : p1, 1);
        float a23 = (odd1 ? p3 : p2) + __shfl_xor_sync(0xffffffffu, odd1 ? p2 : p3, 1);
        float v4 = (odd2 ? a23 : a01) + __shfl_xor_sync(0xffffffffu, odd2 ? a01 : a23, 2);
        v4 += __shfl_xor_sync(0xffffffffu, v4, 4);
        v4 += __shfl_xor_sync(0xffffffffu, v4, 8);
        v4 += __shfl_xor_sync(0xffffffffu, v4, 16);
        if (lane < 4) sc[lane][li] = v4 * scale;
    }
    if (ch == NCH - 1 && warp == 0) {
        const float* kp = knew + ((size_t)b * NHKV + g) * HEADD;
        float4 kv = *(const float4*)(kp + lane * 4);
        float p0 = kv.x * ql[0][0] + kv.y * ql[0][1] + kv.z * ql[0][2] + kv.w * ql[0][3];
        float p1 = kv.x * ql[1][0] + kv.y * ql[1][1] + kv.z * ql[1][2] + kv.w * ql[1][3];
        float p2 = kv.x * ql[2][0] + kv.y * ql[2][1] + kv.z * ql[2][2] + kv.w * ql[2][3];
        float p3 = kv.x * ql[3][0] + kv.y * ql[3][1] + kv.z * ql[3][2] + kv.w * ql[3][3];
        float a01 = (odd1 ? p1 : p0) + __shfl_xor_sync(0xffffffffu, odd1 ? p0 : p1, 1);
        float a23 = (odd1 ? p3 : p2) + __shfl_xor_sync(0xffffffffu, odd1 ? p2 : p3, 1);
        float v4 = (odd2 ? a23 : a01) + __shfl_xor_sync(0xffffffffu, odd2 ? a01 : a23, 2);
        v4 += __shfl_xor_sync(0xffffffffu, v4, 4);
        v4 += __shfl_xor_sync(0xffffffffu, v4, 8);
        v4 += __shfl_xor_sync(0xffffffffu, v4, 16);
        if (lane < 4) sc[lane][CHL] = v4 * scale;
    }
    __syncthreads();

    {
        int r = tid >> 6, t = tid & 63;
        float m = -1e30f;
        for (int li = t; li < cs; li += 64) m = fmaxf(m, sc[r][li]);
        #pragma unroll
        for (int o = 16; o; o >>= 1) m = fmaxf(m, __shfl_xor_sync(0xffffffffu, m, o));
        if (lane == 0) red[warp] = m;
        __syncthreads();
        m = fmaxf(red[2 * r], red[2 * r + 1]);
        float s = 0.f;
        for (int li = t; li < cs; li += 64) {
            float e = expf(sc[r][li] - m);
            sc[r][li] = e; s += e;
        }
        #pragma unroll
        for (int o = 16; o; o >>= 1) s += __shfl_xor_sync(0xffffffffu, s, o);
        __syncthreads();
        if (lane == 0) red[warp] = s;
        __syncthreads();
        s = red[2 * r] + red[2 * r + 1];
        if (t == 0) { ap[r] = m; ap[4 + r] = s; }
    }
    __syncthreads();

    {
        int quad = tid & 31, sl = tid >> 5;
        float4 a0 = make_float4(0, 0, 0, 0), a1 = a0, a2 = a0, a3 = a0;
        #pragma unroll 4
        for (int li = sl; li < cs; li += 8) {
            int l = lbase + li;
            const float* vp = (l < STARTPOS)
                ? cache_v + (((size_t)b * MAXSEQ + l) * NHKV + g) * HEADD
                : vnew + ((size_t)b * NHKV + g) * HEADD;
            float4 v = *(const float4*)(vp + quad * 4);
            float s0 = sc[0][li], s1 = sc[1][li], s2 = sc[2][li], s3 = sc[3][li];
            a0.x += s0 * v.x; a0.y += s0 * v.y; a0.z += s0 * v.z; a0.w += s0 * v.w;
            a1.x += s1 * v.x; a1.y += s1 * v.y; a1.z += s1 * v.z; a1.w += s1 * v.w;
            a2.x += s2 * v.x; a2.y += s2 * v.y; a2.z += s2 * v.z; a2.w += s2 * v.w;
            a3.x += s3 * v.x; a3.y += s3 * v.y; a3.z += s3 * v.z; a3.w += s3 * v.w;
        }
        *(float4*)&vred[sl][0][quad][0] = a0;
        *(float4*)&vred[sl][1][quad][0] = a1;
        *(float4*)&vred[sl][2][quad][0] = a2;
        *(float4*)&vred[sl][3][quad][0] = a3;
    }
    __syncthreads();
    if (tid < 128) {
        int head = tid >> 5, quad = tid & 31;
        float4 s = make_float4(0, 0, 0, 0);
        #pragma unroll
        for (int sl = 0; sl < 8; sl++) {
            float4 u = *(const float4*)&vred[sl][head][quad][0];
            s.x += u.x; s.y += u.y; s.z += u.z; s.w += u.w;
        }
        *(float4*)(ap + 8 + head * 128 + quad * 4) = s;
    }
}

__global__ void __launch_bounds__(128) attn_combine_kernel(
    const float* __restrict__ apart,
    __half* __restrict__ aoh, __half* __restrict__ aol)
{
    int g = blockIdx.x, b = blockIdx.y, d = threadIdx.x;
    const float* base = apart + (size_t)((g * 32 + b) * NCH) * 520;
    #pragma unroll
    for (int r = 0; r < 4; r++) {
        float M = -1e30f;
        #pragma unroll
        for (int c = 0; c < NCH; c++) M = fmaxf(M, base[c * 520 + r]);
        float denom = 0.f, o = 0.f;
        #pragma unroll
        for (int c = 0; c < NCH; c++) {
            float w = expf(base[c * 520 + r] - M);
            denom += base[c * 520 + 4 + r] * w;
            o += base[c * 520 + 8 + r * 128 + d] * w;
        }
        float v = o / denom;
        __half hh = __float2half_rn(v);
        size_t idx = (size_t)b * DIMM + (g * 4 + r) * 128 + d;
        aoh[idx] = hh;
        aol[idx] = __float2half_rn(v - __half2float(hh));
    }
}

// ---------------- launch ----------------
extern "C" void kernel_launch(void* const* d_in, const int* in_sizes, int n_in,
                              void* d_out, int out_size)
{
    const float* x     = (const float*)d_in[0];
    const float* fcos  = (const float*)d_in[2];
    const float* fsin  = (const float*)d_in[3];
    const float* cachek = (const float*)d_in[4];
    const float* cachev = (const float*)d_in[5];
    const float* wq = (const float*)d_in[6];
    const float* wk = (const float*)d_in[7];
    const float* wv = (const float*)d_in[8];
    const float* wo = (const float*)d_in[9];
    const float* w1 = (const float*)d_in[10];
    const float* w2 = (const float*)d_in[11];
    const float* w3 = (const float*)d_in[12];
    const float* anw = (const float*)d_in[13];
    const float* fnw = (const float*)d_in[14];
    float* out = (float*)d_out;

    __half *p_xh, *p_xl, *p_aoh, *p_aol, *p_h2h, *p_h2l, *p_gh, *p_gl;
    float *p_q, *p_knew, *p_vnew, *p_res2, *p_P1, *p_P2, *p_apart;
    cudaGetSymbolAddress((void**)&p_xh, g_xh);
    cudaGetSymbolAddress((void**)&p_xl, g_xl);
    cudaGetSymbolAddress((void**)&p_aoh, g_aoh);
    cudaGetSymbolAddress((void**)&p_aol, g_aol);
    cudaGetSymbolAddress((void**)&p_h2h, g_h2h);
    cudaGetSymbolAddress((void**)&p_h2l, g_h2l);
    cudaGetSymbolAddress((void**)&p_gh, g_gh);
    cudaGetSymbolAddress((void**)&p_gl, g_gl);
    cudaGetSymbolAddress((void**)&p_q, g_q);
    cudaGetSymbolAddress((void**)&p_knew, g_knew);
    cudaGetSymbolAddress((void**)&p_vnew, g_vnew);
    cudaGetSymbolAddress((void**)&p_res2, g_res2);
    cudaGetSymbolAddress((void**)&p_P1, g_P1);
    cudaGetSymbolAddress((void**)&p_P2, g_P2);
    cudaGetSymbolAddress((void**)&p_apart, g_apart);

    cudaFuncSetAttribute(gemm_qkv_kernel, cudaFuncAttributeMaxDynamicSharedMemorySize, GSMEM);
    cudaFuncSetAttribute(gemm_single_kernel, cudaFuncAttributeMaxDynamicSharedMemorySize, GSMEM);
    cudaFuncSetAttribute(gemm_gate_kernel, cudaFuncAttributeMaxDynamicSharedMemorySize, GSMEM);

    rmsnorm_split_kernel<<<32, 256>>>(x, anw, p_xh, p_xl);
    gemm_qkv_kernel<<<dim3(24, 12), 256, GSMEM>>>(p_xh, p_xl, wq, wk, wv, p_P1);
    reduce_qkv_rope_kernel<<<12, 256>>>(p_P1, fcos, fsin, p_q, p_knew, p_vnew, 12);
    attn_part_kernel<<<dim3(8, 32, NCH), 256>>>(cachek, cachev, p_q, p_knew, p_vnew, p_apart);
    attn_combine_kernel<<<dim3(8, 32), 128>>>(p_apart, p_aoh, p_aol);
    gemm_single_kernel<<<dim3(16, 18), 256, GSMEM>>>(p_aoh, p_aol, 4096, wo, 4096, p_P1, 4096, 18);
    reduce_addres_kernel<<<32, 256>>>(p_P1, x, p_res2, 4096, 18);
    rmsnorm_split_kernel<<<32, 256>>>(p_res2, fnw, p_h2h, p_h2l);
    gemm_gate_kernel<<<dim3(86, 3), 256, GSMEM>>>(p_h2h, p_h2l, w1, w3, p_P1, p_P2);
    reduce_gate_kernel<<<86, 256>>>(p_P1, p_P2, p_gh, p_gl, 3);
    gemm_single_kernel<<<dim3(16, 18), 256, GSMEM>>>(p_gh, p_gl, 11008, w2, 4096, p_P1, 4096, 18);
    reduce_addres_kernel<<<32, 256>>>(p_P1, p_res2, out, 4096, 18);
}

// round 11
// speedup vs baseline: 2.8994x; 1.0124x over previous
#include <cuda_runtime.h>
#include <cuda_fp16.h>
#include <math.h>
#include <stdint.h>

#define DIMM 4096
#define HEADD 128
#define NHQ 32
#define NHKV 8
#define HIDDEN 11008
#define BATCH 32
#define MAXSEQ 2048
#define STARTPOS 1024
#define SEQL (STARTPOS + 1)
#define EPS 1e-5f
#define NCH 8
#define CHL 128

// ---------------- PTX helpers (baseline PTX only) ----------------
__device__ __forceinline__ uint32_t s2u(const void* p) {
    uint32_t a;
    asm("{ .reg .u64 t; cvta.to.shared.u64 t, %1; cvt.u32.u64 %0, t; }" : "=r"(a) : "l"(p));
    return a;
}
__device__ __forceinline__ void ldm_x4(uint32_t* r, uint32_t a) {
    asm volatile("ldmatrix.sync.aligned.m8n8.x4.shared.b16 {%0,%1,%2,%3}, [%4];"
                 : "=r"(r[0]), "=r"(r[1]), "=r"(r[2]), "=r"(r[3]) : "r"(a));
}
__device__ __forceinline__ void ldm_x4t(uint32_t* r, uint32_t a) {
    asm volatile("ldmatrix.sync.aligned.m8n8.x4.trans.shared.b16 {%0,%1,%2,%3}, [%4];"
                 : "=r"(r[0]), "=r"(r[1]), "=r"(r[2]), "=r"(r[3]) : "r"(a));
}
__device__ __forceinline__ void mmah(float* c, const uint32_t* a, const uint32_t* b) {
    asm volatile(
        "mma.sync.aligned.m16n8k16.row.col.f32.f16.f16.f32 "
        "{%0,%1,%2,%3}, {%4,%5,%6,%7}, {%8,%9}, {%0,%1,%2,%3};"
        : "+f"(c[0]), "+f"(c[1]), "+f"(c[2]), "+f"(c[3])
        : "r"(a[0]), "r"(a[1]), "r"(a[2]), "r"(a[3]), "r"(b[0]), "r"(b[1]));
}
__device__ __forceinline__ uint32_t f16pack(float a, float b) {
    __half2 h = __floats2half2_rn(a, b);
    return *reinterpret_cast<uint32_t*>(&h);
}

// ---------------- scratch ----------------
__device__ __align__(16) __half g_xh[BATCH * DIMM];
__device__ __align__(16) __half g_xl[BATCH * DIMM];
__device__ __align__(16) __half g_aoh[BATCH * DIMM];
__device__ __align__(16) __half g_aol[BATCH * DIMM];
__device__ __align__(16) __half g_h2h[BATCH * DIMM];
__device__ __align__(16) __half g_h2l[BATCH * DIMM];
__device__ __align__(16) __half g_gh[BATCH * HIDDEN];
__device__ __align__(16) __half g_gl[BATCH * HIDDEN];
__device__ __align__(16) float g_q[BATCH * NHQ * HEADD];
__device__ __align__(16) float g_knew[BATCH * NHKV * HEADD];
__device__ __align__(16) float g_vnew[BATCH * NHKV * HEADD];
__device__ __align__(16) float g_res2[BATCH * DIMM];
__device__ __align__(16) float g_P1[2359296];
__device__ __align__(16) float g_P2[1056768];
__device__ __align__(16) float g_apart[NHKV * BATCH * NCH * 520];

// ---------------- HMMA GEMM core: M=32 x N=256, K64 chunks, fp16 ----------------
#define BPITCH 528
#define GSMEM 86016

__device__ __forceinline__ void gemm_core(
    const __half* __restrict__ XH, const __half* __restrict__ XL,
    int Ktot, const float* __restrict__ W, int ldW,
    float* __restrict__ Pout, int s, int nsplit, char* smem, uint32_t sb)
{
    int tid = threadIdx.x, wid = tid >> 5, lane = tid & 31;
    int chunks = Ktot >> 6;
    int c0 = (chunks * s) / nsplit, c1 = (chunks * (s + 1)) / nsplit;
    int nch = c1 - c0;

    float acc[2][4][4];
    #pragma unroll
    for (int t = 0; t < 2; t++)
        #pragma unroll
        for (int u = 0; u < 4; u++)
            #pragma unroll
            for (int i = 0; i < 4; i++) acc[t][u][i] = 0.f;

    int arow = tid >> 3, aseg = tid & 7;
    int bcol = (tid & 31) * 8, brow0 = tid >> 5;

    uint4 AHr, ALr;
    float4 Br[8];

    auto GLOADA = [&](int c) {
        int kg = (c0 + c) << 6;
        AHr = *(const uint4*)(XH + (size_t)arow * Ktot + kg + aseg * 8);
        ALr = *(const uint4*)(XL + (size_t)arow * Ktot + kg + aseg * 8);
    };
    auto GLOADB = [&](int c, int half) {
        int kg = (c0 + c) << 6;
        #pragma unroll
        for (int p = 0; p < 4; p++) {
            int row = brow0 + (half * 4 + p) * 8;
            const float* wp = W + (size_t)(kg + row) * ldW + bcol;
            Br[2 * p]     = *(const float4*)wp;
            Br[2 * p + 1] = *(const float4*)(wp + 4);
        }
    };
    auto GSTOREA = [&](int buf) {
        *(uint4*)(smem + buf * 9216 + arow * 144 + aseg * 16) = AHr;
        *(uint4*)(smem + buf * 9216 + 4608 + arow * 144 + aseg * 16) = ALr;
    };
    auto GSTOREB = [&](int buf, int half) {
        #pragma unroll
        for (int p = 0; p < 4; p++) {
            int row = brow0 + (half * 4 + p) * 8;
            uint4 q;
            q.x = f16pack(Br[2 * p].x, Br[2 * p].y);
            q.y = f16pack(Br[2 * p].z, Br[2 * p].w);
            q.z = f16pack(Br[2 * p + 1].x, Br[2 * p + 1].y);
            q.w = f16pack(Br[2 * p + 1].z, Br[2 * p + 1].w);
            *(uint4*)(smem + 18432 + buf * 33792 + row * BPITCH + bcol * 2) = q;
        }
    };

    GLOADA(0); GLOADB(0, 0);
    GSTOREA(0); GSTOREB(0, 0);
    GLOADB(0, 1); GSTOREB(0, 1);
    __syncthreads();

    uint32_t a_row = ((lane >> 3) & 1) * 8 + (lane & 7);
    uint32_t a_kk8 = (lane >> 4) * 8;
    uint32_t b_kk  = ((lane >> 3) & 1) * 8 + (lane & 7);
    uint32_t b_nn  = (lane >> 4) * 8;

    for (int c = 0; c < nch; c++) {
        int buf = c & 1, nb = (c + 1) & 1;
        bool more = (c + 1 < nch);
        if (more) { GLOADA(c + 1); GLOADB(c + 1, 0); }

        uint32_t abase = sb + buf * 9216;
        uint32_t bbase = sb + 18432 + buf * 33792 + wid * 64;

        #pragma unroll
        for (int ks = 0; ks < 2; ks++) {
            uint32_t ah[2][4], al[2][4], bf[2][4];
            #pragma unroll
            for (int t = 0; t < 2; t++) {
                uint32_t ad = abase + (t * 16 + a_row) * 144 + (ks * 16 + a_kk8) * 2;
                ldm_x4(ah[t], ad);
                ldm_x4(al[t], ad + 4608);
            }
            uint32_t bd = bbase + (ks * 16 + b_kk) * BPITCH + b_nn * 2;
            ldm_x4t(bf[0], bd);
            ldm_x4t(bf[1], bd + 32);
            #pragma unroll
            for (int t = 0; t < 2; t++)
                #pragma unroll
                for (int u = 0; u < 4; u++) {
                    mmah(acc[t][u], ah[t], &bf[u >> 1][2 * (u & 1)]);
                    mmah(acc[t][u], al[t], &bf[u >> 1][2 * (u & 1)]);
                }
        }
        if (more) { GSTOREA(nb); GSTOREB(nb, 0); GLOADB(c + 1, 1); }
        #pragma unroll
        for (int ks = 2; ks < 4; ks++) {
            uint32_t ah[2][4], al[2][4], bf[2][4];
            #pragma unroll
            for (int t = 0; t < 2; t++) {
                uint32_t ad = abase + (t * 16 + a_row) * 144 + (ks * 16 + a_kk8) * 2;
                ldm_x4(ah[t], ad);
                ldm_x4(al[t], ad + 4608);
            }
            uint32_t bd = bbase + (ks * 16 + b_kk) * BPITCH + b_nn * 2;
            ldm_x4t(bf[0], bd);
            ldm_x4t(bf[1], bd + 32);
            #pragma unroll
            for (int t = 0; t < 2; t++)
                #pragma unroll
                for (int u = 0; u < 4; u++) {
                    mmah(acc[t][u], ah[t], &bf[u >> 1][2 * (u & 1)]);
                    mmah(acc[t][u], al[t], &bf[u >> 1][2 * (u & 1)]);
                }
        }
        if (more) GSTOREB(nb, 1);
        __syncthreads();
    }

    // epilogue: stage to smem (pitch 36, 16B-aligned, conflict-free), coalesced writes
    {
        float* st = (float*)smem;
        int g = lane >> 2, tg = lane & 3;
        #pragma unroll
        for (int t = 0; t < 2; t++)
            #pragma unroll
            for (int u = 0; u < 4; u++) {
                int n = wid * 32 + u * 8 + tg * 2;
                int r0 = t * 16 + g;
                st[n * 36 + r0]           = acc[t][u][0];
                st[(n + 1) * 36 + r0]     = acc[t][u][1];
                st[n * 36 + r0 + 8]       = acc[t][u][2];
                st[(n + 1) * 36 + r0 + 8] = acc[t][u][3];
            }
        __syncthreads();
        const float4* src = (const float4*)(st + tid * 36);
        float4* dst = (float4*)(Pout + (size_t)tid * 32);
        #pragma unroll
        for (int j = 0; j < 8; j++) dst[j] = src[j];
    }
}

// fused qkv
__global__ void __launch_bounds__(256, 2) gemm_qkv_kernel(
    const __half* __restrict__ XH, const __half* __restrict__ XL,
    const float* __restrict__ wq, const float* __restrict__ wk, const float* __restrict__ wv,
    float* __restrict__ P)
{
    extern __shared__ char smem[];
    uint32_t sb = s2u(smem);
    int nbase = blockIdx.x * 256, s = blockIdx.y;
    const float* W; int ld, nloc;
    if (nbase < 4096)      { W = wq; ld = 4096; nloc = nbase; }
    else if (nbase < 5120) { W = wk; ld = 1024; nloc = nbase - 4096; }
    else                   { W = wv; ld = 1024; nloc = nbase - 5120; }
    gemm_core(XH, XL, 4096, W + nloc, ld,
              P + ((size_t)s * 6144 + nbase) * 32, s, 12, smem, sb);
}

__global__ void __launch_bounds__(256, 2) gemm_single_kernel(
    const __half* __restrict__ XH, const __half* __restrict__ XL,
    int Ktot, const float* __restrict__ W, int ldW,
    float* __restrict__ P, int PN, int nsplit)
{
    extern __shared__ char smem[];
    uint32_t sb = s2u(smem);
    int nbase = blockIdx.x * 256, s = blockIdx.y;
    gemm_core(XH, XL, Ktot, W + nbase, ldW,
              P + ((size_t)s * PN + nbase) * 32, s, nsplit, smem, sb);
}

__global__ void __launch_bounds__(256, 2) gemm_gate_kernel(
    const __half* __restrict__ XH, const __half* __restrict__ XL,
    const float* __restrict__ w1, const float* __restrict__ w3,
    float* __restrict__ P1, float* __restrict__ P2)
{
    extern __shared__ char smem[];
    uint32_t sb = s2u(smem);
    int t = blockIdx.x, s = blockIdx.y;
    if (t < 43) {
        int nbase = t * 256;
        gemm_core(XH, XL, 4096, w1 + nbase, HIDDEN,
                  P1 + ((size_t)s * HIDDEN + nbase) * 32, s, 3, smem, sb);
    } else {
        int nbase = (t - 43) * 256;
        gemm_core(XH, XL, 4096, w3 + nbase, HIDDEN,
                  P2 + ((size_t)s * HIDDEN + nbase) * 32, s, 3, smem, sb);
    }
}

// ---------------- rmsnorm + fp16 hi/lo split ----------------
__global__ void __launch_bounds__(256) rmsnorm_split_kernel(
    const float* __restrict__ x, const float* __restrict__ w,
    __half* __restrict__ yh, __half* __restrict__ yl)
{
    int b = blockIdx.x;
    const float* xr = x + (size_t)b * DIMM;
    __shared__ float red[32];
    float ss = 0.f;
    for (int i = threadIdx.x; i < DIMM; i += 256) { float v = xr[i]; ss += v * v; }
    #pragma unroll
    for (int o = 16; o; o >>= 1) ss += __shfl_xor_sync(0xffffffffu, ss, o);
    if ((threadIdx.x & 31) == 0) red[threadIdx.x >> 5] = ss;
    __syncthreads();
    if (threadIdx.x < 32) {
        float v = (threadIdx.x < 8) ? red[threadIdx.x] : 0.f;
        #pragma unroll
        for (int o = 16; o; o >>= 1) v += __shfl_xor_sync(0xffffffffu, v, o);
        if (threadIdx.x == 0) red[0] = v;
    }
    __syncthreads();
    float inv = 1.0f / (sqrtf(red[0] * (1.0f / DIMM)) + EPS);
    for (int i = threadIdx.x; i < DIMM; i += 256) {
        float v = w[i] * xr[i] * inv;
        __half h = __float2half_rn(v);
        yh[(size_t)b * DIMM + i] = h;
        yl[(size_t)b * DIMM + i] = __float2half_rn(v - __half2float(h));
    }
}

// ---------------- reduces ----------------
__global__ void __launch_bounds__(256) reduce_qkv_rope_kernel(
    const float* __restrict__ P, const float* __restrict__ fcos, const float* __restrict__ fsin,
    float* __restrict__ q, float* __restrict__ knew, float* __restrict__ vnew, int SK)
{
    int c = threadIdx.x & 127, h = threadIdx.x >> 7;
    int colg = blockIdx.x * 512 + 4 * c;
    float4 a[4][4];
    #pragma unroll
    for (int cc = 0; cc < 4; cc++)
        #pragma unroll
        for (int j = 0; j < 4; j++) a[cc][j] = make_float4(0.f, 0.f, 0.f, 0.f);
    for (int kz = 0; kz < SK; kz++) {
        const float* p = P + ((size_t)kz * 6144 + colg) * 32 + h * 16;
        #pragma unroll
        for (int cc = 0; cc < 4; cc++)
            #pragma unroll
            for (int j = 0; j < 4; j++) {
                float4 u = *(const float4*)(p + (size_t)cc * 32 + 4 * j);
                a[cc][j].x += u.x; a[cc][j].y += u.y; a[cc][j].z += u.z; a[cc][j].w += u.w;
            }
    }
    int d0 = colg & 127;
    if (colg < 5120) {
        int i0 = d0 >> 1;
        float c0 = fcos[i0], s0 = fsin[i0];
        float c1 = fcos[i0 + 1], s1 = fsin[i0 + 1];
        float* dst; int head, H;
        if (colg < 4096) { head = colg >> 7; dst = q; H = NHQ; }
        else { head = (colg - 4096) >> 7; dst = knew; H = NHKV; }
        #pragma unroll
        for (int j = 0; j < 4; j++) {
            #pragma unroll
            for (int e = 0; e < 4; e++) {
                int b = h * 16 + 4 * j + e;
                float x0 = (e == 0 ? a[0][j].x : e == 1 ? a[0][j].y : e == 2 ? a[0][j].z : a[0][j].w);
                float x1 = (e == 0 ? a[1][j].x : e == 1 ? a[1][j].y : e == 2 ? a[1][j].z : a[1][j].w);
                float x2 = (e == 0 ? a[2][j].x : e == 1 ? a[2][j].y : e == 2 ? a[2][j].z : a[2][j].w);
                float x3 = (e == 0 ? a[3][j].x : e == 1 ? a[3][j].y : e == 2 ? a[3][j].z : a[3][j].w);
                float* o = dst + ((size_t)b * H + head) * HEADD + d0;
                *(float4*)o = make_float4(x0 * c0 - x1 * s0, x0 * s0 + x1 * c0,
                                          x2 * c1 - x3 * s1, x2 * s1 + x3 * c1);
            }
        }
    } else {
        int g = (colg - 5120) >> 7;
        #pragma unroll
        for (int j = 0; j < 4; j++) {
            #pragma unroll
            for (int e = 0; e < 4; e++) {
                int b = h * 16 + 4 * j + e;
                float x0 = (e == 0 ? a[0][j].x : e == 1 ? a[0][j].y : e == 2 ? a[0][j].z : a[0][j].w);
                float x1 = (e == 0 ? a[1][j].x : e == 1 ? a[1][j].y : e == 2 ? a[1][j].z : a[1][j].w);
                float x2 = (e == 0 ? a[2][j].x : e == 1 ? a[2][j].y : e == 2 ? a[2][j].z : a[2][j].w);
                float x3 = (e == 0 ? a[3][j].x : e == 1 ? a[3][j].y : e == 2 ? a[3][j].z : a[3][j].w);
                float* o = vnew + ((size_t)b * NHKV + g) * HEADD + d0;
                *(float4*)o = make_float4(x0, x1, x2, x3);
            }
        }
    }
}

__global__ void __launch_bounds__(256) reduce_addres_kernel(
    const float* __restrict__ P, const float* __restrict__ res, float* __restrict__ out,
    int N, int SK)
{
    int j = threadIdx.x & 7, nl = threadIdx.x >> 3;
    int n = blockIdx.x * 32 + nl;
    float4 a = make_float4(0.f, 0.f, 0.f, 0.f);
    for (int kz = 0; kz < SK; kz++) {
        float4 u = *(const float4*)(P + ((size_t)kz * N + n) * 32 + j * 4);
        a.x += u.x; a.y += u.y; a.z += u.z; a.w += u.w;
    }
    int b0 = 4 * j;
    out[(size_t)(b0 + 0) * N + n] = a.x + res[(size_t)(b0 + 0) * N + n];
    out[(size_t)(b0 + 1) * N + n] = a.y + res[(size_t)(b0 + 1) * N + n];
    out[(size_t)(b0 + 2) * N + n] = a.z + res[(size_t)(b0 + 2) * N + n];
    out[(size_t)(b0 + 3) * N + n] = a.w + res[(size_t)(b0 + 3) * N + n];
}

// gate reduce: coalesced reads -> smem transpose (pitch 36) -> 32B-run half writes
__global__ void __launch_bounds__(256) reduce_gate_kernel(
    const float* __restrict__ P1, const float* __restrict__ P2,
    __half* __restrict__ gh, __half* __restrict__ gl, int SK)
{
    __shared__ __align__(16) float s1[128 * 36];
    __shared__ __align__(16) float s2[128 * 36];
    int tid = threadIdx.x;
    int j = tid & 7, nl = tid >> 3;
    int nblk = blockIdx.x * 128;
    #pragma unroll
    for (int p = 0; p < 4; p++) {
        int n_local = p * 32 + nl;
        int n = nblk + n_local;
        float4 a = make_float4(0.f, 0.f, 0.f, 0.f), g3 = a;
        for (int kz = 0; kz < SK; kz++) {
            float4 u = *(const float4*)(P1 + ((size_t)kz * HIDDEN + n) * 32 + j * 4);
            a.x += u.x; a.y += u.y; a.z += u.z; a.w += u.w;
            float4 w = *(const float4*)(P2 + ((size_t)kz * HIDDEN + n) * 32 + j * 4);
            g3.x += w.x; g3.y += w.y; g3.z += w.z; g3.w += w.w;
        }
        *(float4*)(s1 + n_local * 36 + 4 * j) = a;   // pitch 36: 16B-aligned
        *(float4*)(s2 + n_local * 36 + 4 * j) = g3;
    }
    __syncthreads();
    int b = tid & 31, ng = tid >> 5;
    __half hb[16], lb[16];
    #pragma unroll
    for (int i = 0; i < 16; i++) {
        int n_local = ng * 16 + i;
        float v1 = s1[n_local * 36 + b];
        float v3 = s2[n_local * 36 + b];
        float v = (v1 / (1.f + expf(-v1))) * v3;
        __half hh = __float2half_rn(v);
        hb[i] = hh;
        lb[i] = __float2half_rn(v - __half2float(hh));
    }
    size_t off = (size_t)b * HIDDEN + nblk + ng * 16;
    *(uint4*)(gh + off) = *(uint4*)hb;
    *(uint4*)(gh + off + 8) = *(uint4*)(hb + 8);
    *(uint4*)(gl + off) = *(uint4*)lb;
    *(uint4*)(gl + off + 8) = *(uint4*)(lb + 8);
}

// ---------------- attention: split-L x8, merged-shfl scores, float4 V ----------------
__global__ void __launch_bounds__(256) attn_part_kernel(
    const float* __restrict__ cache_k, const float* __restrict__ cache_v,
    const float* __restrict__ q, const float* __restrict__ knew, const float* __restrict__ vnew,
    float* __restrict__ apart)
{
    int g = blockIdx.x, b = blockIdx.y, ch = blockIdx.z;
    int lbase = ch * CHL;
    int cs = (ch == NCH - 1) ? CHL + 1 : CHL;
    __shared__ __align__(16) float sc[4][136];
    __shared__ __align__(16) float qs[4][HEADD];
    __shared__ float red[8];
    __shared__ __align__(16) float vred[8][4][32][4];
    int tid = threadIdx.x, warp = tid >> 5, lane = tid & 31;
    float* ap = apart + (size_t)((g * 32 + b) * NCH + ch) * 520;

    for (int i = tid; i < 4 * HEADD; i += 256) {
        int r = i >> 7, d = i & 127;
        qs[r][d] = q[((size_t)b * NHQ + (g * 4 + r)) * HEADD + d];
    }
    __syncthreads();
    float ql[4][4];
    #pragma unroll
    for (int r = 0; r < 4; r++) {
        float4 t = *(const float4*)&qs[r][lane * 4];
        ql[r][0] = t.x; ql[r][1] = t.y; ql[r][2] = t.z; ql[r][3] = t.w;
    }
    const float scale = 0.08838834764831845f;
    bool odd1 = (lane & 1), odd2 = (lane & 2);

    #pragma unroll 2
    for (int i = 0; i < CHL / 8; i++) {
        int li = warp + i * 8;
        int l = lbase + li;
        const float* kp = cache_k + (((size_t)b * MAXSEQ + l) * NHKV + g) * HEADD;
        float4 kv = *(const float4*)(kp + lane * 4);
        float p0 = kv.x * ql[0][0] + kv.y * ql[0][1] + kv.z * ql[0][2] + kv.w * ql[0][3];
        float p1 = kv.x * ql[1][0] + kv.y * ql[1][1] + kv.z * ql[1][2] + kv.w * ql[1][3];
        float p2 = kv.x * ql[2][0] + kv.y * ql[2][1] + kv.z * ql[2][2] + kv.w * ql[2][3];
        float p3 = kv.x * ql[3][0] + kv.y * ql[3][1] + kv.z * ql[3][2] + kv.w * ql[3][3];
        float a01 = (odd1 ? p1 : p0) + __shfl_xor_sync(0xffffffffu, odd1 ? p0 : p1, 1);
        float a23 = (odd1 ? p3 : p2) + __shfl_xor_sync(0xffffffffu, odd1 ? p2 : p3, 1);
        float v4 = (odd2 ? a23 : a01) + __shfl_xor_sync(0xffffffffu, odd2 ? a01 : a23, 2);
        v4 += __shfl_xor_sync(0xffffffffu, v4, 4);
        v4 += __shfl_xor_sync(0xffffffffu, v4, 8);
        v4 += __shfl_xor_sync(0xffffffffu, v4, 16);
        if (lane < 4) sc[lane][li] = v4 * scale;
    }
    if (ch == NCH - 1 && warp == 0) {
        const float* kp = knew + ((size_t)b * NHKV + g) * HEADD;
        float4 kv = *(const float4*)(kp + lane * 4);
        float p0 = kv.x * ql[0][0] + kv.y * ql[0][1] + kv.z * ql[0][2] + kv.w * ql[0][3];
        float p1 = kv.x * ql[1][0] + kv.y * ql[1][1] + kv.z * ql[1][2] + kv.w * ql[1][3];
        float p2 = kv.x * ql[2][0] + kv.y * ql[2][1] + kv.z * ql[2][2] + kv.w * ql[2][3];
        float p3 = kv.x * ql[3][0] + kv.y * ql[3][1] + kv.z * ql[3][2] + kv.w * ql[3][3];
        float a01 = (odd1 ? p1 : p0) + __shfl_xor_sync(0xffffffffu, odd1 ? p0 : p1, 1);
        float a23 = (odd1 ? p3 : p2) + __shfl_xor_sync(0xffffffffu, odd1 ? p2 : p3, 1);
        float v4 = (odd2 ? a23 : a01) + __shfl_xor_sync(0xffffffffu, odd2 ? a01 : a23, 2);
        v4 += __shfl_xor_sync(0xffffffffu, v4, 4);
        v4 += __shfl_xor_sync(0xffffffffu, v4, 8);
        v4 += __shfl_xor_sync(0xffffffffu, v4, 16);
        if (lane < 4) sc[lane][CHL] = v4 * scale;
    }
    __syncthreads();

    {
        int r = tid >> 6, t = tid & 63;
        float m = -1e30f;
        for (int li = t; li < cs; li += 64) m = fmaxf(m, sc[r][li]);
        #pragma unroll
        for (int o = 16; o; o >>= 1) m = fmaxf(m, __shfl_xor_sync(0xffffffffu, m, o));
        if (lane == 0) red[warp] = m;
        __syncthreads();
        m = fmaxf(red[2 * r], red[2 * r + 1]);
        float s = 0.f;
        for (int li = t; li < cs; li += 64) {
            float e = expf(sc[r][li] - m);
            sc[r][li] = e; s += e;
        }
        #pragma unroll
        for (int o = 16; o; o >>= 1) s += __shfl_xor_sync(0xffffffffu, s, o);
        __syncthreads();
        if (lane == 0) red[warp] = s;
        __syncthreads();
        s = red[2 * r] + red[2 * r + 1];
        if (t == 0) { ap[r] = m; ap[4 + r] = s; }
    }
    __syncthreads();

    {
        int quad = tid & 31, sl = tid >> 5;
        float4 a0 = make_float4(0, 0, 0, 0), a1 = a0, a2 = a0, a3 = a0;
        #pragma unroll 4
        for (int li = sl; li < cs; li += 8) {
            int l = lbase + li;
            const float* vp = (l < STARTPOS)
                ? cache_v + (((size_t)b * MAXSEQ + l) * NHKV + g) * HEADD
                : vnew + ((size_t)b * NHKV + g) * HEADD;
            float4 v = *(const float4*)(vp + quad * 4);
            float s0 = sc[0][li], s1 = sc[1][li], s2 = sc[2][li], s3 = sc[3][li];
            a0.x += s0 * v.x; a0.y += s0 * v.y; a0.z += s0 * v.z; a0.w += s0 * v.w;
            a1.x += s1 * v.x; a1.y += s1 * v.y; a1.z += s1 * v.z; a1.w += s1 * v.w;
            a2.x += s2 * v.x; a2.y += s2 * v.y; a2.z += s2 * v.z; a2.w += s2 * v.w;
            a3.x += s3 * v.x; a3.y += s3 * v.y; a3.z += s3 * v.z; a3.w += s3 * v.w;
        }
        *(float4*)&vred[sl][0][quad][0] = a0;
        *(float4*)&vred[sl][1][quad][0] = a1;
        *(float4*)&vred[sl][2][quad][0] = a2;
        *(float4*)&vred[sl][3][quad][0] = a3;
    }
    __syncthreads();
    if (tid < 128) {
        int head = tid >> 5, quad = tid & 31;
        float4 s = make_float4(0, 0, 0, 0);
        #pragma unroll
        for (int sl = 0; sl < 8; sl++) {
            float4 u = *(const float4*)&vred[sl][head][quad][0];
            s.x += u.x; s.y += u.y; s.z += u.z; s.w += u.w;
        }
        *(float4*)(ap + 8 + head * 128 + quad * 4) = s;
    }
}

__global__ void __launch_bounds__(128) attn_combine_kernel(
    const float* __restrict__ apart,
    __half* __restrict__ aoh, __half* __restrict__ aol)
{
    int g = blockIdx.x, b = blockIdx.y, d = threadIdx.x;
    const float* base = apart + (size_t)((g * 32 + b) * NCH) * 520;
    #pragma unroll
    for (int r = 0; r < 4; r++) {
        float M = -1e30f;
        #pragma unroll
        for (int c = 0; c < NCH; c++) M = fmaxf(M, base[c * 520 + r]);
        float denom = 0.f, o = 0.f;
        #pragma unroll
        for (int c = 0; c < NCH; c++) {
            float w = expf(base[c * 520 + r] - M);
            denom += base[c * 520 + 4 + r] * w;
            o += base[c * 520 + 8 + r * 128 + d] * w;
        }
        float v = o / denom;
        __half hh = __float2half_rn(v);
        size_t idx = (size_t)b * DIMM + (g * 4 + r) * 128 + d;
        aoh[idx] = hh;
        aol[idx] = __float2half_rn(v - __half2float(hh));
    }
}

// ---------------- launch ----------------
extern "C" void kernel_launch(void* const* d_in, const int* in_sizes, int n_in,
                              void* d_out, int out_size)
{
    const float* x     = (const float*)d_in[0];
    const float* fcos  = (const float*)d_in[2];
    const float* fsin  = (const float*)d_in[3];
    const float* cachek = (const float*)d_in[4];
    const float* cachev = (const float*)d_in[5];
    const float* wq = (const float*)d_in[6];
    const float* wk = (const float*)d_in[7];
    const float* wv = (const float*)d_in[8];
    const float* wo = (const float*)d_in[9];
    const float* w1 = (const float*)d_in[10];
    const float* w2 = (const float*)d_in[11];
    const float* w3 = (const float*)d_in[12];
    const float* anw = (const float*)d_in[13];
    const float* fnw = (const float*)d_in[14];
    float* out = (float*)d_out;

    __half *p_xh, *p_xl, *p_aoh, *p_aol, *p_h2h, *p_h2l, *p_gh, *p_gl;
    float *p_q, *p_knew, *p_vnew, *p_res2, *p_P1, *p_P2, *p_apart;
    cudaGetSymbolAddress((void**)&p_xh, g_xh);
    cudaGetSymbolAddress((void**)&p_xl, g_xl);
    cudaGetSymbolAddress((void**)&p_aoh, g_aoh);
    cudaGetSymbolAddress((void**)&p_aol, g_aol);
    cudaGetSymbolAddress((void**)&p_h2h, g_h2h);
    cudaGetSymbolAddress((void**)&p_h2l, g_h2l);
    cudaGetSymbolAddress((void**)&p_gh, g_gh);
    cudaGetSymbolAddress((void**)&p_gl, g_gl);
    cudaGetSymbolAddress((void**)&p_q, g_q);
    cudaGetSymbolAddress((void**)&p_knew, g_knew);
    cudaGetSymbolAddress((void**)&p_vnew, g_vnew);
    cudaGetSymbolAddress((void**)&p_res2, g_res2);
    cudaGetSymbolAddress((void**)&p_P1, g_P1);
    cudaGetSymbolAddress((void**)&p_P2, g_P2);
    cudaGetSymbolAddress((void**)&p_apart, g_apart);

    cudaFuncSetAttribute(gemm_qkv_kernel, cudaFuncAttributeMaxDynamicSharedMemorySize, GSMEM);
    cudaFuncSetAttribute(gemm_single_kernel, cudaFuncAttributeMaxDynamicSharedMemorySize, GSMEM);
    cudaFuncSetAttribute(gemm_gate_kernel, cudaFuncAttributeMaxDynamicSharedMemorySize, GSMEM);

    rmsnorm_split_kernel<<<32, 256>>>(x, anw, p_xh, p_xl);
    gemm_qkv_kernel<<<dim3(24, 12), 256, GSMEM>>>(p_xh, p_xl, wq, wk, wv, p_P1);
    reduce_qkv_rope_kernel<<<12, 256>>>(p_P1, fcos, fsin, p_q, p_knew, p_vnew, 12);
    attn_part_kernel<<<dim3(8, 32, NCH), 256>>>(cachek, cachev, p_q, p_knew, p_vnew, p_apart);
    attn_combine_kernel<<<dim3(8, 32), 128>>>(p_apart, p_aoh, p_aol);
    gemm_single_kernel<<<dim3(16, 18), 256, GSMEM>>>(p_aoh, p_aol, 4096, wo, 4096, p_P1, 4096, 18);
    reduce_addres_kernel<<<128, 256>>>(p_P1, x, p_res2, 4096, 18);
    rmsnorm_split_kernel<<<32, 256>>>(p_res2, fnw, p_h2h, p_h2l);
    gemm_gate_kernel<<<dim3(86, 3), 256, GSMEM>>>(p_h2h, p_h2l, w1, w3, p_P1, p_P2);
    reduce_gate_kernel<<<86, 256>>>(p_P1, p_P2, p_gh, p_gl, 3);
    gemm_single_kernel<<<dim3(16, 18), 256, GSMEM>>>(p_gh, p_gl, 11008, w2, 4096, p_P1, 4096, 18);
    reduce_addres_kernel<<<128, 256>>>(p_P1, p_res2, out, 4096, 18);
}

// round 12
// speedup vs baseline: 3.2082x; 1.1065x over previous
#include <cuda_runtime.h>
#include <cuda_fp16.h>
#include <math.h>
#include <stdint.h>

#define DIMM 4096
#define HEADD 128
#define NHQ 32
#define NHKV 8
#define HIDDEN 11008
#define BATCH 32
#define MAXSEQ 2048
#define STARTPOS 1024
#define SEQL (STARTPOS + 1)
#define EPS 1e-5f
#define NCH 8
#define CHL 128

// ---------------- PTX helpers (baseline PTX only) ----------------
__device__ __forceinline__ uint32_t s2u(const void* p) {
    uint32_t a;
    asm("{ .reg .u64 t; cvta.to.shared.u64 t, %1; cvt.u32.u64 %0, t; }" : "=r"(a) : "l"(p));
    return a;
}
__device__ __forceinline__ void ldm_x4(uint32_t* r, uint32_t a) {
    asm volatile("ldmatrix.sync.aligned.m8n8.x4.shared.b16 {%0,%1,%2,%3}, [%4];"
                 : "=r"(r[0]), "=r"(r[1]), "=r"(r[2]), "=r"(r[3]) : "r"(a));
}
__device__ __forceinline__ void ldm_x4t(uint32_t* r, uint32_t a) {
    asm volatile("ldmatrix.sync.aligned.m8n8.x4.trans.shared.b16 {%0,%1,%2,%3}, [%4];"
                 : "=r"(r[0]), "=r"(r[1]), "=r"(r[2]), "=r"(r[3]) : "r"(a));
}
__device__ __forceinline__ void mmah(float* c, const uint32_t* a, const uint32_t* b) {
    asm volatile(
        "mma.sync.aligned.m16n8k16.row.col.f32.f16.f16.f32 "
        "{%0,%1,%2,%3}, {%4,%5,%6,%7}, {%8,%9}, {%0,%1,%2,%3};"
        : "+f"(c[0]), "+f"(c[1]), "+f"(c[2]), "+f"(c[3])
        : "r"(a[0]), "r"(a[1]), "r"(a[2]), "r"(a[3]), "r"(b[0]), "r"(b[1]));
}
__device__ __forceinline__ uint32_t f16pack(float a, float b) {
    __half2 h = __floats2half2_rn(a, b);
    return *reinterpret_cast<uint32_t*>(&h);
}

// ---------------- scratch ----------------
__device__ __align__(16) __half g_xh[BATCH * DIMM];
__device__ __align__(16) __half g_aoh[BATCH * DIMM];
__device__ __align__(16) __half g_h2h[BATCH * DIMM];
__device__ __align__(16) __half g_gh[BATCH * HIDDEN];
__device__ __align__(16) float g_q[BATCH * NHQ * HEADD];
__device__ __align__(16) float g_knew[BATCH * NHKV * HEADD];
__device__ __align__(16) float g_vnew[BATCH * NHKV * HEADD];
__device__ __align__(16) float g_res2[BATCH * DIMM];
__device__ __align__(16) float g_P1[2359296];
__device__ __align__(16) float g_P2[1056768];
__device__ __align__(16) float g_apart[NHKV * BATCH * NCH * 520];

// ---------------- HMMA GEMM core: M=32 x N=256, K64 chunks, fp16 single-pass ----------------
#define BPITCH 528
#define GSMEM 86016

__device__ __forceinline__ void gemm_core(
    const __half* __restrict__ XH,
    int Ktot, const float* __restrict__ W, int ldW,
    float* __restrict__ Pout, int s, int nsplit, char* smem, uint32_t sb)
{
    int tid = threadIdx.x, wid = tid >> 5, lane = tid & 31;
    int chunks = Ktot >> 6;
    int c0 = (chunks * s) / nsplit, c1 = (chunks * (s + 1)) / nsplit;
    int nch = c1 - c0;

    float acc[2][4][4];
    #pragma unroll
    for (int t = 0; t < 2; t++)
        #pragma unroll
        for (int u = 0; u < 4; u++)
            #pragma unroll
            for (int i = 0; i < 4; i++) acc[t][u][i] = 0.f;

    int arow = tid >> 3, aseg = tid & 7;
    int bcol = (tid & 31) * 8, brow0 = tid >> 5;

    uint4 AHr;
    float4 Br[8];

    auto GLOADA = [&](int c) {
        int kg = (c0 + c) << 6;
        AHr = *(const uint4*)(XH + (size_t)arow * Ktot + kg + aseg * 8);
    };
    auto GLOADB = [&](int c, int half) {
        int kg = (c0 + c) << 6;
        #pragma unroll
        for (int p = 0; p < 4; p++) {
            int row = brow0 + (half * 4 + p) * 8;
            const float* wp = W + (size_t)(kg + row) * ldW + bcol;
            Br[2 * p]     = *(const float4*)wp;
            Br[2 * p + 1] = *(const float4*)(wp + 4);
        }
    };
    auto GSTOREA = [&](int buf) {
        *(uint4*)(smem + buf * 9216 + arow * 144 + aseg * 16) = AHr;
    };
    auto GSTOREB = [&](int buf, int half) {
        #pragma unroll
        for (int p = 0; p < 4; p++) {
            int row = brow0 + (half * 4 + p) * 8;
            uint4 q;
            q.x = f16pack(Br[2 * p].x, Br[2 * p].y);
            q.y = f16pack(Br[2 * p].z, Br[2 * p].w);
            q.z = f16pack(Br[2 * p + 1].x, Br[2 * p + 1].y);
            q.w = f16pack(Br[2 * p + 1].z, Br[2 * p + 1].w);
            *(uint4*)(smem + 18432 + buf * 33792 + row * BPITCH + bcol * 2) = q;
        }
    };

    GLOADA(0); GLOADB(0, 0);
    GSTOREA(0); GSTOREB(0, 0);
    GLOADB(0, 1); GSTOREB(0, 1);
    __syncthreads();

    uint32_t a_row = ((lane >> 3) & 1) * 8 + (lane & 7);
    uint32_t a_kk8 = (lane >> 4) * 8;
    uint32_t b_kk  = ((lane >> 3) & 1) * 8 + (lane & 7);
    uint32_t b_nn  = (lane >> 4) * 8;

    for (int c = 0; c < nch; c++) {
        int buf = c & 1, nb = (c + 1) & 1;
        bool more = (c + 1 < nch);
        if (more) { GLOADA(c + 1); GLOADB(c + 1, 0); }

        uint32_t abase = sb + buf * 9216;
        uint32_t bbase = sb + 18432 + buf * 33792 + wid * 64;

        #pragma unroll
        for (int ks = 0; ks < 2; ks++) {
            uint32_t ah[2][4], bf[2][4];
            #pragma unroll
            for (int t = 0; t < 2; t++) {
                uint32_t ad = abase + (t * 16 + a_row) * 144 + (ks * 16 + a_kk8) * 2;
                ldm_x4(ah[t], ad);
            }
            uint32_t bd = bbase + (ks * 16 + b_kk) * BPITCH + b_nn * 2;
            ldm_x4t(bf[0], bd);
            ldm_x4t(bf[1], bd + 32);
            #pragma unroll
            for (int t = 0; t < 2; t++)
                #pragma unroll
                for (int u = 0; u < 4; u++)
                    mmah(acc[t][u], ah[t], &bf[u >> 1][2 * (u & 1)]);
        }
        if (more) { GSTOREA(nb); GSTOREB(nb, 0); GLOADB(c + 1, 1); }
        #pragma unroll
        for (int ks = 2; ks < 4; ks++) {
            uint32_t ah[2][4], bf[2][4];
            #pragma unroll
            for (int t = 0; t < 2; t++) {
                uint32_t ad = abase + (t * 16 + a_row) * 144 + (ks * 16 + a_kk8) * 2;
                ldm_x4(ah[t], ad);
            }
            uint32_t bd = bbase + (ks * 16 + b_kk) * BPITCH + b_nn * 2;
            ldm_x4t(bf[0], bd);
            ldm_x4t(bf[1], bd + 32);
            #pragma unroll
            for (int t = 0; t < 2; t++)
                #pragma unroll
                for (int u = 0; u < 4; u++)
                    mmah(acc[t][u], ah[t], &bf[u >> 1][2 * (u & 1)]);
        }
        if (more) GSTOREB(nb, 1);
        __syncthreads();
    }

    // epilogue: stage to smem (pitch 36, 16B-aligned), coalesced writes
    {
        float* st = (float*)smem;
        int g = lane >> 2, tg = lane & 3;
        #pragma unroll
        for (int t = 0; t < 2; t++)
            #pragma unroll
            for (int u = 0; u < 4; u++) {
                int n = wid * 32 + u * 8 + tg * 2;
                int r0 = t * 16 + g;
                st[n * 36 + r0]           = acc[t][u][0];
                st[(n + 1) * 36 + r0]     = acc[t][u][1];
                st[n * 36 + r0 + 8]       = acc[t][u][2];
                st[(n + 1) * 36 + r0 + 8] = acc[t][u][3];
            }
        __syncthreads();
        const float4* src = (const float4*)(st + tid * 36);
        float4* dst = (float4*)(Pout + (size_t)tid * 32);
        #pragma unroll
        for (int j = 0; j < 8; j++) dst[j] = src[j];
    }
}

// fused qkv
__global__ void __launch_bounds__(256, 2) gemm_qkv_kernel(
    const __half* __restrict__ XH,
    const float* __restrict__ wq, const float* __restrict__ wk, const float* __restrict__ wv,
    float* __restrict__ P)
{
    extern __shared__ char smem[];
    uint32_t sb = s2u(smem);
    int nbase = blockIdx.x * 256, s = blockIdx.y;
    const float* W; int ld, nloc;
    if (nbase < 4096)      { W = wq; ld = 4096; nloc = nbase; }
    else if (nbase < 5120) { W = wk; ld = 1024; nloc = nbase - 4096; }
    else                   { W = wv; ld = 1024; nloc = nbase - 5120; }
    gemm_core(XH, 4096, W + nloc, ld,
              P + ((size_t)s * 6144 + nbase) * 32, s, 12, smem, sb);
}

__global__ void __launch_bounds__(256, 2) gemm_single_kernel(
    const __half* __restrict__ XH,
    int Ktot, const float* __restrict__ W, int ldW,
    float* __restrict__ P, int PN, int nsplit)
{
    extern __shared__ char smem[];
    uint32_t sb = s2u(smem);
    int nbase = blockIdx.x * 256, s = blockIdx.y;
    gemm_core(XH, Ktot, W + nbase, ldW,
              P + ((size_t)s * PN + nbase) * 32, s, nsplit, smem, sb);
}

__global__ void __launch_bounds__(256, 2) gemm_gate_kernel(
    const __half* __restrict__ XH,
    const float* __restrict__ w1, const float* __restrict__ w3,
    float* __restrict__ P1, float* __restrict__ P2)
{
    extern __shared__ char smem[];
    uint32_t sb = s2u(smem);
    int t = blockIdx.x, s = blockIdx.y;
    if (t < 43) {
        int nbase = t * 256;
        gemm_core(XH, 4096, w1 + nbase, HIDDEN,
                  P1 + ((size_t)s * HIDDEN + nbase) * 32, s, 3, smem, sb);
    } else {
        int nbase = (t - 43) * 256;
        gemm_core(XH, 4096, w3 + nbase, HIDDEN,
                  P2 + ((size_t)s * HIDDEN + nbase) * 32, s, 3, smem, sb);
    }
}

// ---------------- rmsnorm -> fp16 (b-major) ----------------
__global__ void __launch_bounds__(256) rmsnorm_half_kernel(
    const float* __restrict__ x, const float* __restrict__ w,
    __half* __restrict__ yh)
{
    int b = blockIdx.x;
    const float* xr = x + (size_t)b * DIMM;
    __shared__ float red[32];
    float ss = 0.f;
    for (int i = threadIdx.x; i < DIMM; i += 256) { float v = xr[i]; ss += v * v; }
    #pragma unroll
    for (int o = 16; o; o >>= 1) ss += __shfl_xor_sync(0xffffffffu, ss, o);
    if ((threadIdx.x & 31) == 0) red[threadIdx.x >> 5] = ss;
    __syncthreads();
    if (threadIdx.x < 32) {
        float v = (threadIdx.x < 8) ? red[threadIdx.x] : 0.f;
        #pragma unroll
        for (int o = 16; o; o >>= 1) v += __shfl_xor_sync(0xffffffffu, v, o);
        if (threadIdx.x == 0) red[0] = v;
    }
    __syncthreads();
    float inv = 1.0f / (sqrtf(red[0] * (1.0f / DIMM)) + EPS);
    for (int i = threadIdx.x; i < DIMM; i += 256)
        yh[(size_t)b * DIMM + i] = __float2half_rn(w[i] * xr[i] * inv);
}

// ---------------- reduces ----------------
// 48 blocks: thread = 4 cols x 4 batches
__global__ void __launch_bounds__(256) reduce_qkv_rope_kernel(
    const float* __restrict__ P, const float* __restrict__ fcos, const float* __restrict__ fsin,
    float* __restrict__ q, float* __restrict__ knew, float* __restrict__ vnew, int SK)
{
    int c = threadIdx.x & 31, h = threadIdx.x >> 5;     // c: col-quad, h: batch-quad 0..7
    int colg = blockIdx.x * 128 + 4 * c;
    float4 a[4];
    #pragma unroll
    for (int cc = 0; cc < 4; cc++) a[cc] = make_float4(0.f, 0.f, 0.f, 0.f);
    for (int kz = 0; kz < SK; kz++) {
        const float* p = P + ((size_t)kz * 6144 + colg) * 32 + h * 4;
        #pragma unroll
        for (int cc = 0; cc < 4; cc++) {
            float4 u = *(const float4*)(p + (size_t)cc * 32);
            a[cc].x += u.x; a[cc].y += u.y; a[cc].z += u.z; a[cc].w += u.w;
        }
    }
    int d0 = colg & 127;
    if (colg < 5120) {
        int i0 = d0 >> 1;
        float c0 = fcos[i0], s0 = fsin[i0];
        float c1 = fcos[i0 + 1], s1 = fsin[i0 + 1];
        float* dst; int head, H;
        if (colg < 4096) { head = colg >> 7; dst = q; H = NHQ; }
        else { head = (colg - 4096) >> 7; dst = knew; H = NHKV; }
        #pragma unroll
        for (int e = 0; e < 4; e++) {
            int b = h * 4 + e;
            float x0 = (e == 0 ? a[0].x : e == 1 ? a[0].y : e == 2 ? a[0].z : a[0].w);
            float x1 = (e == 0 ? a[1].x : e == 1 ? a[1].y : e == 2 ? a[1].z : a[1].w);
            float x2 = (e == 0 ? a[2].x : e == 1 ? a[2].y : e == 2 ? a[2].z : a[2].w);
            float x3 = (e == 0 ? a[3].x : e == 1 ? a[3].y : e == 2 ? a[3].z : a[3].w);
            float* o = dst + ((size_t)b * H + head) * HEADD + d0;
            *(float4*)o = make_float4(x0 * c0 - x1 * s0, x0 * s0 + x1 * c0,
                                      x2 * c1 - x3 * s1, x2 * s1 + x3 * c1);
        }
    } else {
        int g = (colg - 5120) >> 7;
        #pragma unroll
        for (int e = 0; e < 4; e++) {
            int b = h * 4 + e;
            float x0 = (e == 0 ? a[0].x : e == 1 ? a[0].y : e == 2 ? a[0].z : a[0].w);
            float x1 = (e == 0 ? a[1].x : e == 1 ? a[1].y : e == 2 ? a[1].z : a[1].w);
            float x2 = (e == 0 ? a[2].x : e == 1 ? a[2].y : e == 2 ? a[2].z : a[2].w);
            float x3 = (e == 0 ? a[3].x : e == 1 ? a[3].y : e == 2 ? a[3].z : a[3].w);
            float* o = vnew + ((size_t)b * NHKV + g) * HEADD + d0;
            *(float4*)o = make_float4(x0, x1, x2, x3);
        }
    }
}

__global__ void __launch_bounds__(256) reduce_addres_kernel(
    const float* __restrict__ P, const float* __restrict__ res, float* __restrict__ out,
    int N, int SK)
{
    int j = threadIdx.x & 7, nl = threadIdx.x >> 3;
    int n = blockIdx.x * 32 + nl;
    float4 a = make_float4(0.f, 0.f, 0.f, 0.f);
    for (int kz = 0; kz < SK; kz++) {
        float4 u = *(const float4*)(P + ((size_t)kz * N + n) * 32 + j * 4);
        a.x += u.x; a.y += u.y; a.z += u.z; a.w += u.w;
    }
    int b0 = 4 * j;
    out[(size_t)(b0 + 0) * N + n] = a.x + res[(size_t)(b0 + 0) * N + n];
    out[(size_t)(b0 + 1) * N + n] = a.y + res[(size_t)(b0 + 1) * N + n];
    out[(size_t)(b0 + 2) * N + n] = a.z + res[(size_t)(b0 + 2) * N + n];
    out[(size_t)(b0 + 3) * N + n] = a.w + res[(size_t)(b0 + 3) * N + n];
}

// gate reduce: coalesced reads -> smem transpose (pitch 36) -> 32B-run half writes
__global__ void __launch_bounds__(256) reduce_gate_kernel(
    const float* __restrict__ P1, const float* __restrict__ P2,
    __half* __restrict__ gh, int SK)
{
    __shared__ __align__(16) float s1[128 * 36];
    __shared__ __align__(16) float s2[128 * 36];
    int tid = threadIdx.x;
    int j = tid & 7, nl = tid >> 3;
    int nblk = blockIdx.x * 128;
    #pragma unroll
    for (int p = 0; p < 4; p++) {
        int n_local = p * 32 + nl;
        int n = nblk + n_local;
        float4 a = make_float4(0.f, 0.f, 0.f, 0.f), g3 = a;
        for (int kz = 0; kz < SK; kz++) {
            float4 u = *(const float4*)(P1 + ((size_t)kz * HIDDEN + n) * 32 + j * 4);
            a.x += u.x; a.y += u.y; a.z += u.z; a.w += u.w;
            float4 w = *(const float4*)(P2 + ((size_t)kz * HIDDEN + n) * 32 + j * 4);
            g3.x += w.x; g3.y += w.y; g3.z += w.z; g3.w += w.w;
        }
        *(float4*)(s1 + n_local * 36 + 4 * j) = a;
        *(float4*)(s2 + n_local * 36 + 4 * j) = g3;
    }
    __syncthreads();
    int b = tid & 31, ng = tid >> 5;
    __half hb[16];
    #pragma unroll
    for (int i = 0; i < 16; i++) {
        int n_local = ng * 16 + i;
        float v1 = s1[n_local * 36 + b];
        float v3 = s2[n_local * 36 + b];
        float v = (v1 / (1.f + expf(-v1))) * v3;
        hb[i] = __float2half_rn(v);
    }
    size_t off = (size_t)b * HIDDEN + nblk + ng * 16;
    *(uint4*)(gh + off) = *(uint4*)hb;
    *(uint4*)(gh + off + 8) = *(uint4*)(hb + 8);
}

// ---------------- attention: split-L x8, merged-shfl scores, float4 V ----------------
__global__ void __launch_bounds__(256) attn_part_kernel(
    const float* __restrict__ cache_k, const float* __restrict__ cache_v,
    const float* __restrict__ q, const float* __restrict__ knew, const float* __restrict__ vnew,
    float* __restrict__ apart)
{
    int g = blockIdx.x, b = blockIdx.y, ch = blockIdx.z;
    int lbase = ch * CHL;
    int cs = (ch == NCH - 1) ? CHL + 1 : CHL;
    __shared__ __align__(16) float sc[4][136];
    __shared__ __align__(16) float qs[4][HEADD];
    __shared__ float red[8];
    __shared__ __align__(16) float vred[8][4][32][4];
    int tid = threadIdx.x, warp = tid >> 5, lane = tid & 31;
    float* ap = apart + (size_t)((g * 32 + b) * NCH + ch) * 520;

    for (int i = tid; i < 4 * HEADD; i += 256) {
        int r = i >> 7, d = i & 127;
        qs[r][d] = q[((size_t)b * NHQ + (g * 4 + r)) * HEADD + d];
    }
    __syncthreads();
    float ql[4][4];
    #pragma unroll
    for (int r = 0; r < 4; r++) {
        float4 t = *(const float4*)&qs[r][lane * 4];
        ql[r][0] = t.x; ql[r][1] = t.y; ql[r][2] = t.z; ql[r][3] = t.w;
    }
    const float scale = 0.08838834764831845f;
    bool odd1 = (lane & 1), odd2 = (lane & 2);

    #pragma unroll 2
    for (int i = 0; i < CHL / 8; i++) {
        int li = warp + i * 8;
        int l = lbase + li;
        const float* kp = cache_k + (((size_t)b * MAXSEQ + l) * NHKV + g) * HEADD;
        float4 kv = *(const float4*)(kp + lane * 4);
        float p0 = kv.x * ql[0][0] + kv.y * ql[0][1] + kv.z * ql[0][2] + kv.w * ql[0][3];
        float p1 = kv.x * ql[1][0] + kv.y * ql[1][1] + kv.z * ql[1][2] + kv.w * ql[1][3];
        float p2 = kv.x * ql[2][0] + kv.y * ql[2][1] + kv.z * ql[2][2] + kv.w * ql[2][3];
        float p3 = kv.x * ql[3][0] + kv.y * ql[3][1] + kv.z * ql[3][2] + kv.w * ql[3][3];
        float a01 = (odd1 ? p1 : p0) + __shfl_xor_sync(0xffffffffu, odd1 ? p0 : p1, 1);
        float a23 = (odd1 ? p3 : p2) + __shfl_xor_sync(0xffffffffu, odd1 ? p2 : p3, 1);
        float v4 = (odd2 ? a23 : a01) + __shfl_xor_sync(0xffffffffu, odd2 ? a01 : a23, 2);
        v4 += __shfl_xor_sync(0xffffffffu, v4, 4);
        v4 += __shfl_xor_sync(0xffffffffu, v4, 8);
        v4 += __shfl_xor_sync(0xffffffffu, v4, 16);
        if (lane < 4) sc[lane][li] = v4 * scale;
    }
    if (ch == NCH - 1 && warp == 0) {
        const float* kp = knew + ((size_t)b * NHKV + g) * HEADD;
        float4 kv = *(const float4*)(kp + lane * 4);
        float p0 = kv.x * ql[0][0] + kv.y * ql[0][1] + kv.z * ql[0][2] + kv.w * ql[0][3];
        float p1 = kv.x * ql[1][0] + kv.y * ql[1][1] + kv.z * ql[1][2] + kv.w * ql[1][3];
        float p2 = kv.x * ql[2][0] + kv.y * ql[2][1] + kv.z * ql[2][2] + kv.w * ql[2][3];
        float p3 = kv.x * ql[3][0] + kv.y * ql[3][1] + kv.z * ql[3][2] + kv.w * ql[3][3];
        float a01 = (odd1 ? p1 : p0) + __shfl_xor_sync(0xffffffffu, odd1 ? p0 : p1, 1);
        float a23 = (odd1 ? p3 : p2) + __shfl_xor_sync(0xffffffffu, odd1 ? p2 : p3, 1);
        float v4 = (odd2 ? a23 : a01) + __shfl_xor_sync(0xffffffffu, odd2 ? a01 : a23, 2);
        v4 += __shfl_xor_sync(0xffffffffu, v4, 4);
        v4 += __shfl_xor_sync(0xffffffffu, v4, 8);
        v4 += __shfl_xor_sync(0xffffffffu, v4, 16);
        if (lane < 4) sc[lane][CHL] = v4 * scale;
    }
    __syncthreads();

    {
        int r = tid >> 6, t = tid & 63;
        float m = -1e30f;
        for (int li = t; li < cs; li += 64) m = fmaxf(m, sc[r][li]);
        #pragma unroll
        for (int o = 16; o; o >>= 1) m = fmaxf(m, __shfl_xor_sync(0xffffffffu, m, o));
        if (lane == 0) red[warp] = m;
        __syncthreads();
        m = fmaxf(red[2 * r], red[2 * r + 1]);
        float s = 0.f;
        for (int li = t; li < cs; li += 64) {
            float e = expf(sc[r][li] - m);
            sc[r][li] = e; s += e;
        }
        #pragma unroll
        for (int o = 16; o; o >>= 1) s += __shfl_xor_sync(0xffffffffu, s, o);
        __syncthreads();
        if (lane == 0) red[warp] = s;
        __syncthreads();
        s = red[2 * r] + red[2 * r + 1];
        if (t == 0) { ap[r] = m; ap[4 + r] = s; }
    }
    __syncthreads();

    {
        int quad = tid & 31, sl = tid >> 5;
        float4 a0 = make_float4(0, 0, 0, 0), a1 = a0, a2 = a0, a3 = a0;
        #pragma unroll 4
        for (int li = sl; li < cs; li += 8) {
            int l = lbase + li;
            const float* vp = (l < STARTPOS)
                ? cache_v + (((size_t)b * MAXSEQ + l) * NHKV + g) * HEADD
                : vnew + ((size_t)b * NHKV + g) * HEADD;
            float4 v = *(const float4*)(vp + quad * 4);
            float s0 = sc[0][li], s1 = sc[1][li], s2 = sc[2][li], s3 = sc[3][li];
            a0.x += s0 * v.x; a0.y += s0 * v.y; a0.z += s0 * v.z; a0.w += s0 * v.w;
            a1.x += s1 * v.x; a1.y += s1 * v.y; a1.z += s1 * v.z; a1.w += s1 * v.w;
            a2.x += s2 * v.x; a2.y += s2 * v.y; a2.z += s2 * v.z; a2.w += s2 * v.w;
            a3.x += s3 * v.x; a3.y += s3 * v.y; a3.z += s3 * v.z; a3.w += s3 * v.w;
        }
        *(float4*)&vred[sl][0][quad][0] = a0;
        *(float4*)&vred[sl][1][quad][0] = a1;
        *(float4*)&vred[sl][2][quad][0] = a2;
        *(float4*)&vred[sl][3][quad][0] = a3;
    }
    __syncthreads();
    if (tid < 128) {
        int head = tid >> 5, quad = tid & 31;
        float4 s = make_float4(0, 0, 0, 0);
        #pragma unroll
        for (int sl = 0; sl < 8; sl++) {
            float4 u = *(const float4*)&vred[sl][head][quad][0];
            s.x += u.x; s.y += u.y; s.z += u.z; s.w += u.w;
        }
        *(float4*)(ap + 8 + head * 128 + quad * 4) = s;
    }
}

__global__ void __launch_bounds__(128) attn_combine_kernel(
    const float* __restrict__ apart, __half* __restrict__ aoh)
{
    int g = blockIdx.x, b = blockIdx.y, d = threadIdx.x;
    const float* base = apart + (size_t)((g * 32 + b) * NCH) * 520;
    #pragma unroll
    for (int r = 0; r < 4; r++) {
        float M = -1e30f;
        #pragma unroll
        for (int c = 0; c < NCH; c++) M = fmaxf(M, base[c * 520 + r]);
        float denom = 0.f, o = 0.f;
        #pragma unroll
        for (int c = 0; c < NCH; c++) {
            float w = expf(base[c * 520 + r] - M);
            denom += base[c * 520 + 4 + r] * w;
            o += base[c * 520 + 8 + r * 128 + d] * w;
        }
        aoh[(size_t)b * DIMM + (g * 4 + r) * 128 + d] = __float2half_rn(o / denom);
    }
}

// ---------------- launch ----------------
extern "C" void kernel_launch(void* const* d_in, const int* in_sizes, int n_in,
                              void* d_out, int out_size)
{
    const float* x     = (const float*)d_in[0];
    const float* fcos  = (const float*)d_in[2];
    const float* fsin  = (const float*)d_in[3];
    const float* cachek = (const float*)d_in[4];
    const float* cachev = (const float*)d_in[5];
    const float* wq = (const float*)d_in[6];
    const float* wk = (const float*)d_in[7];
    const float* wv = (const float*)d_in[8];
    const float* wo = (const float*)d_in[9];
    const float* w1 = (const float*)d_in[10];
    const float* w2 = (const float*)d_in[11];
    const float* w3 = (const float*)d_in[12];
    const float* anw = (const float*)d_in[13];
    const float* fnw = (const float*)d_in[14];
    float* out = (float*)d_out;

    __half *p_xh, *p_aoh, *p_h2h, *p_gh;
    float *p_q, *p_knew, *p_vnew, *p_res2, *p_P1, *p_P2, *p_apart;
    cudaGetSymbolAddress((void**)&p_xh, g_xh);
    cudaGetSymbolAddress((void**)&p_aoh, g_aoh);
    cudaGetSymbolAddress((void**)&p_h2h, g_h2h);
    cudaGetSymbolAddress((void**)&p_gh, g_gh);
    cudaGetSymbolAddress((void**)&p_q, g_q);
    cudaGetSymbolAddress((void**)&p_knew, g_knew);
    cudaGetSymbolAddress((void**)&p_vnew, g_vnew);
    cudaGetSymbolAddress((void**)&p_res2, g_res2);
    cudaGetSymbolAddress((void**)&p_P1, g_P1);
    cudaGetSymbolAddress((void**)&p_P2, g_P2);
    cudaGetSymbolAddress((void**)&p_apart, g_apart);

    cudaFuncSetAttribute(gemm_qkv_kernel, cudaFuncAttributeMaxDynamicSharedMemorySize, GSMEM);
    cudaFuncSetAttribute(gemm_single_kernel, cudaFuncAttributeMaxDynamicSharedMemorySize, GSMEM);
    cudaFuncSetAttribute(gemm_gate_kernel, cudaFuncAttributeMaxDynamicSharedMemorySize, GSMEM);

    rmsnorm_half_kernel<<<32, 256>>>(x, anw, p_xh);
    gemm_qkv_kernel<<<dim3(24, 12), 256, GSMEM>>>(p_xh, wq, wk, wv, p_P1);
    reduce_qkv_rope_kernel<<<48, 256>>>(p_P1, fcos, fsin, p_q, p_knew, p_vnew, 12);
    attn_part_kernel<<<dim3(8, 32, NCH), 256>>>(cachek, cachev, p_q, p_knew, p_vnew, p_apart);
    attn_combine_kernel<<<dim3(8, 32), 128>>>(p_apart, p_aoh);
    gemm_single_kernel<<<dim3(16, 18), 256, GSMEM>>>(p_aoh, 4096, wo, 4096, p_P1, 4096, 18);
    reduce_addres_kernel<<<128, 256>>>(p_P1, x, p_res2, 4096, 18);
    rmsnorm_half_kernel<<<32, 256>>>(p_res2, fnw, p_h2h);
    gemm_gate_kernel<<<dim3(86, 3), 256, GSMEM>>>(p_h2h, w1, w3, p_P1, p_P2);
    reduce_gate_kernel<<<86, 256>>>(p_P1, p_P2, p_gh, 3);
    gemm_single_kernel<<<dim3(16, 18), 256, GSMEM>>>(p_gh, 11008, w2, 4096, p_P1, 4096, 18);
    reduce_addres_kernel<<<128, 256>>>(p_P1, p_res2, out, 4096, 18);
}